// round 1
// baseline (speedup 1.0000x reference)
#include <cuda_runtime.h>
#include <math.h>

#define CC   128
#define NV   4096     // 16*16*16 voxels
#define NB   2
#define EPSF 1e-5f

#define VSTR 132      // padded row stride for transposed V tile
#define PSTR 65       // padded row stride for probability tile

// ---------------- scratch (no allocation allowed) ----------------
__device__ float g_a[CC];         // gamma * rsqrt(var+eps)
__device__ float g_dd[CC];        // beta - mean * a
__device__ float g_Wq[CC*CC];
__device__ float g_Wk[CC*CC];
__device__ float g_Wv[CC*CC];
__device__ float g_bq[CC];
__device__ float g_bk[CC];
__device__ float g_bv[CC];
__device__ float g_q[NB*CC*NV];
__device__ float g_k[NB*CC*NV];
__device__ float g_v[NB*CC*NV];
__device__ float g_h[NB*CC*NV];

// ---------------- 1) per-channel batch stats --------------------
__global__ void stats_kernel(const float* __restrict__ inp,
                             const float* __restrict__ gamma,
                             const float* __restrict__ beta)
{
    int c = blockIdx.x;
    int tid = threadIdx.x;
    const float* p0 = inp + c * NV;
    const float* p1 = inp + (CC + c) * NV;
    float s = 0.f, ss = 0.f;
    for (int n = tid * 4; n < NV; n += 256 * 4) {
        float4 a = *(const float4*)(p0 + n);
        float4 b = *(const float4*)(p1 + n);
        s  += a.x + a.y + a.z + a.w + b.x + b.y + b.z + b.w;
        ss += a.x*a.x + a.y*a.y + a.z*a.z + a.w*a.w
            + b.x*b.x + b.y*b.y + b.z*b.z + b.w*b.w;
    }
    #pragma unroll
    for (int off = 16; off; off >>= 1) {
        s  += __shfl_xor_sync(0xffffffffu, s, off);
        ss += __shfl_xor_sync(0xffffffffu, ss, off);
    }
    __shared__ float sb[8], ssb[8];
    int w = tid >> 5;
    if ((tid & 31) == 0) { sb[w] = s; ssb[w] = ss; }
    __syncthreads();
    if (tid == 0) {
        float ts = 0.f, tss = 0.f;
        #pragma unroll
        for (int i = 0; i < 8; i++) { ts += sb[i]; tss += ssb[i]; }
        const float inv = 1.f / (float)(NB * NV);
        float mean = ts * inv;
        float var  = tss * inv - mean * mean;
        float a = gamma[c] * rsqrtf(var + EPSF);
        g_a[c]  = a;
        g_dd[c] = beta[c] - mean * a;
    }
}

// ---------------- 2) fold BN (+ q scale) into weights -----------
__global__ void fold_kernel(const float* __restrict__ Wq, const float* __restrict__ bq,
                            const float* __restrict__ Wk, const float* __restrict__ bk,
                            const float* __restrict__ Wv, const float* __restrict__ bv)
{
    int m = blockIdx.x >> 7;      // 0=q 1=k 2=v
    int o = blockIdx.x & 127;
    int c = threadIdx.x;          // 128 threads
    // q side gets scale 1/sqrt(C) AND log2(e) folded in (softmax uses exp2)
    const float QSC = 1.44269504088896341f * 0.0883883476483184406f;
    const float* W; const float* bs; float* Wd; float* bd; float sc;
    if (m == 0)      { W = Wq; bs = bq; Wd = g_Wq; bd = g_bq; sc = QSC; }
    else if (m == 1) { W = Wk; bs = bk; Wd = g_Wk; bd = g_bk; sc = 1.f; }
    else             { W = Wv; bs = bv; Wd = g_Wv; bd = g_bv; sc = 1.f; }
    float w = W[o*CC + c];
    Wd[o*CC + c] = w * g_a[c] * sc;
    float part = w * g_dd[c];
    #pragma unroll
    for (int off = 16; off; off >>= 1)
        part += __shfl_xor_sync(0xffffffffu, part, off);
    __shared__ float pb[4];
    if ((c & 31) == 0) pb[c >> 5] = part;
    __syncthreads();
    if (c == 0) bd[o] = (bs[o] + pb[0] + pb[1] + pb[2] + pb[3]) * sc;
}

// ---------------- 3) QKV GEMM: (128x128) @ (128xN) + b ----------
__global__ void qkv_kernel(const float* __restrict__ inp)
{
    extern __shared__ float sm[];
    float* Ws = sm;               // transposed weight [c][o], 128x128
    float* xs = sm + CC*CC;       // input tile [c][j], 128x64
    int m = blockIdx.y, b = blockIdx.z;
    int n0 = blockIdx.x * 64;
    const float* W  = (m == 0) ? g_Wq : (m == 1) ? g_Wk : g_Wv;
    const float* bb = (m == 0) ? g_bq : (m == 1) ? g_bk : g_bv;
    float* outp = ((m == 0) ? g_q : (m == 1) ? g_k : g_v) + b*CC*NV;
    int tid = threadIdx.x;

    for (int i = tid; i < CC*CC/4; i += 256) {
        int o  = i >> 5;
        int c4 = (i & 31) << 2;
        float4 w = *(const float4*)(W + o*CC + c4);
        Ws[(c4+0)*CC + o] = w.x;
        Ws[(c4+1)*CC + o] = w.y;
        Ws[(c4+2)*CC + o] = w.z;
        Ws[(c4+3)*CC + o] = w.w;
    }
    for (int i = tid; i < CC*16; i += 256) {
        int c  = i >> 4;
        int j4 = (i & 15) << 2;
        *(float4*)(xs + c*64 + j4) =
            *(const float4*)(inp + (b*CC + c)*NV + n0 + j4);
    }
    __syncthreads();

    int oy = tid >> 4;   // output-row group (8 rows)
    int nx = tid & 15;   // column group (4 cols)
    float acc[8][4];
    #pragma unroll
    for (int u = 0; u < 8; u++)
        #pragma unroll
        for (int v = 0; v < 4; v++) acc[u][v] = 0.f;

    #pragma unroll 4
    for (int c = 0; c < CC; c++) {
        float4 w0 = *(float4*)(Ws + c*CC + oy*8);
        float4 w1 = *(float4*)(Ws + c*CC + oy*8 + 4);
        float4 x4 = *(float4*)(xs + c*64 + nx*4);
        float wv[8] = {w0.x, w0.y, w0.z, w0.w, w1.x, w1.y, w1.z, w1.w};
        float xv[4] = {x4.x, x4.y, x4.z, x4.w};
        #pragma unroll
        for (int u = 0; u < 8; u++)
            #pragma unroll
            for (int v = 0; v < 4; v++) acc[u][v] += wv[u] * xv[v];
    }

    #pragma unroll
    for (int u = 0; u < 8; u++) {
        int o = oy*8 + u;
        float bias = bb[o];
        float4 r = make_float4(acc[u][0] + bias, acc[u][1] + bias,
                               acc[u][2] + bias, acc[u][3] + bias);
        *(float4*)(outp + o*NV + n0 + nx*4) = r;
    }
}

// ---------------- 4) flash attention ----------------------------
// grid (NV/64, NB), 256 threads. Query tile 64, key tile 64.
// thread (ty,tx): scores s[4][4] for queries ty*4..+3 x keys tx*4..+3
//                 output acc[8][4] for channels tx*8..+7 x queries ty*4..+3
__global__ void attn_kernel()
{
    extern __shared__ float sm[];
    float* qs   = sm;                    // [c*64 + i]
    float* ks   = qs + CC*64;            // [c*64 + j]
    float* vs   = ks + CC*64;            // [j*VSTR + c] (transposed)
    float* ps   = vs + 64*VSTR;          // [i*PSTR + j]
    float* rowm = ps + 64*PSTR;
    float* rowl = rowm + 64;

    int b  = blockIdx.y;
    int i0 = blockIdx.x * 64;
    int tid = threadIdx.x;
    int ty = tid >> 4;
    int tx = tid & 15;
    const float* qg = g_q + b*CC*NV;
    const float* kg = g_k + b*CC*NV;
    const float* vg = g_v + b*CC*NV;

    for (int i = tid; i < CC*16; i += 256) {
        int c = i >> 4, j4 = (i & 15) << 2;
        *(float4*)(qs + c*64 + j4) = *(const float4*)(qg + c*NV + i0 + j4);
    }
    if (tid < 64) { rowm[tid] = -1e30f; rowl[tid] = 0.f; }

    float acc[8][4];
    #pragma unroll
    for (int u = 0; u < 8; u++)
        #pragma unroll
        for (int v = 0; v < 4; v++) acc[u][v] = 0.f;

    __syncthreads();

    for (int j0 = 0; j0 < NV; j0 += 64) {
        // load K tile (direct) and V tile (transposed, padded stride)
        for (int i = tid; i < CC*16; i += 256) {
            int c = i >> 4, j4 = (i & 15) << 2;
            *(float4*)(ks + c*64 + j4) =
                *(const float4*)(kg + c*NV + j0 + j4);
            float4 vv = *(const float4*)(vg + c*NV + j0 + j4);
            vs[(j4+0)*VSTR + c] = vv.x;
            vs[(j4+1)*VSTR + c] = vv.y;
            vs[(j4+2)*VSTR + c] = vv.z;
            vs[(j4+3)*VSTR + c] = vv.w;
        }
        __syncthreads();

        // scores (scale & log2e already folded into q)
        float s[4][4];
        #pragma unroll
        for (int v = 0; v < 4; v++)
            #pragma unroll
            for (int u = 0; u < 4; u++) s[v][u] = 0.f;
        #pragma unroll 8
        for (int c = 0; c < CC; c++) {
            float4 q4 = *(float4*)(qs + c*64 + ty*4);
            float4 k4 = *(float4*)(ks + c*64 + tx*4);
            float qv[4] = {q4.x, q4.y, q4.z, q4.w};
            float kv[4] = {k4.x, k4.y, k4.z, k4.w};
            #pragma unroll
            for (int v = 0; v < 4; v++)
                #pragma unroll
                for (int u = 0; u < 4; u++) s[v][u] += qv[v] * kv[u];
        }

        // online softmax: row max over 16 lanes sharing ty
        float mloc[4], mo[4], mn[4], al[4], rs[4];
        #pragma unroll
        for (int v = 0; v < 4; v++)
            mloc[v] = fmaxf(fmaxf(s[v][0], s[v][1]), fmaxf(s[v][2], s[v][3]));
        #pragma unroll
        for (int off = 1; off < 16; off <<= 1)
            #pragma unroll
            for (int v = 0; v < 4; v++)
                mloc[v] = fmaxf(mloc[v], __shfl_xor_sync(0xffffffffu, mloc[v], off));
        #pragma unroll
        for (int v = 0; v < 4; v++) {
            mo[v] = rowm[ty*4 + v];
            mn[v] = fmaxf(mo[v], mloc[v]);
            al[v] = exp2f(mo[v] - mn[v]);
        }
        #pragma unroll
        for (int v = 0; v < 4; v++) {
            rs[v] = 0.f;
            #pragma unroll
            for (int u = 0; u < 4; u++) {
                s[v][u] = exp2f(s[v][u] - mn[v]);
                rs[v] += s[v][u];
            }
        }
        #pragma unroll
        for (int off = 1; off < 16; off <<= 1)
            #pragma unroll
            for (int v = 0; v < 4; v++)
                rs[v] += __shfl_xor_sync(0xffffffffu, rs[v], off);
        __syncwarp();
        if (tx == 0) {
            #pragma unroll
            for (int v = 0; v < 4; v++) {
                rowm[ty*4 + v] = mn[v];
                rowl[ty*4 + v] = rowl[ty*4 + v] * al[v] + rs[v];
            }
        }
        // store probabilities, rescale accumulator
        #pragma unroll
        for (int v = 0; v < 4; v++)
            #pragma unroll
            for (int u = 0; u < 4; u++)
                ps[(ty*4 + v)*PSTR + tx*4 + u] = s[v][u];
        #pragma unroll
        for (int u = 0; u < 8; u++)
            #pragma unroll
            for (int v = 0; v < 4; v++) acc[u][v] *= al[v];
        __syncthreads();

        // O += V @ P^T
        int cb = tx * 8;
        #pragma unroll 4
        for (int j = 0; j < 64; j++) {
            float4 v0 = *(float4*)(vs + j*VSTR + cb);
            float4 v1 = *(float4*)(vs + j*VSTR + cb + 4);
            float vv[8] = {v0.x, v0.y, v0.z, v0.w, v1.x, v1.y, v1.z, v1.w};
            float pv[4];
            #pragma unroll
            for (int v = 0; v < 4; v++) pv[v] = ps[(ty*4 + v)*PSTR + j];
            #pragma unroll
            for (int u = 0; u < 8; u++)
                #pragma unroll
                for (int v = 0; v < 4; v++) acc[u][v] += vv[u] * pv[v];
        }
        __syncthreads();
    }

    float linv[4];
    #pragma unroll
    for (int v = 0; v < 4; v++) linv[v] = 1.f / rowl[ty*4 + v];
    float* hg = g_h + b*CC*NV;
    #pragma unroll
    for (int u = 0; u < 8; u++) {
        int c = tx*8 + u;
        #pragma unroll
        for (int v = 0; v < 4; v++)
            hg[c*NV + i0 + ty*4 + v] = acc[u][v] * linv[v];
    }
}

// ---------------- 5) output projection + residual ---------------
__global__ void proj_kernel(const float* __restrict__ inp,
                            const float* __restrict__ Wo,
                            const float* __restrict__ bo,
                            float* __restrict__ outp)
{
    extern __shared__ float sm[];
    float* Ws = sm;
    float* xs = sm + CC*CC;
    int b = blockIdx.y;
    int n0 = blockIdx.x * 64;
    int tid = threadIdx.x;

    for (int i = tid; i < CC*CC/4; i += 256) {
        int o  = i >> 5;
        int c4 = (i & 31) << 2;
        float4 w = *(const float4*)(Wo + o*CC + c4);
        Ws[(c4+0)*CC + o] = w.x;
        Ws[(c4+1)*CC + o] = w.y;
        Ws[(c4+2)*CC + o] = w.z;
        Ws[(c4+3)*CC + o] = w.w;
    }
    const float* hsrc = g_h + b*CC*NV;
    for (int i = tid; i < CC*16; i += 256) {
        int c  = i >> 4;
        int j4 = (i & 15) << 2;
        *(float4*)(xs + c*64 + j4) = *(const float4*)(hsrc + c*NV + n0 + j4);
    }
    __syncthreads();

    int oy = tid >> 4;
    int nx = tid & 15;
    float acc[8][4];
    #pragma unroll
    for (int u = 0; u < 8; u++)
        #pragma unroll
        for (int v = 0; v < 4; v++) acc[u][v] = 0.f;

    #pragma unroll 4
    for (int c = 0; c < CC; c++) {
        float4 w0 = *(float4*)(Ws + c*CC + oy*8);
        float4 w1 = *(float4*)(Ws + c*CC + oy*8 + 4);
        float4 x4 = *(float4*)(xs + c*64 + nx*4);
        float wv[8] = {w0.x, w0.y, w0.z, w0.w, w1.x, w1.y, w1.z, w1.w};
        float xv[4] = {x4.x, x4.y, x4.z, x4.w};
        #pragma unroll
        for (int u = 0; u < 8; u++)
            #pragma unroll
            for (int v = 0; v < 4; v++) acc[u][v] += wv[u] * xv[v];
    }

    #pragma unroll
    for (int u = 0; u < 8; u++) {
        int o = oy*8 + u;
        float bias = bo[o];
        float4 r0 = *(const float4*)(inp + (b*CC + o)*NV + n0 + nx*4);
        float4 r = make_float4(acc[u][0] + bias + r0.x,
                               acc[u][1] + bias + r0.y,
                               acc[u][2] + bias + r0.z,
                               acc[u][3] + bias + r0.w);
        *(float4*)(outp + (b*CC + o)*NV + n0 + nx*4) = r;
    }
}

// ---------------- launch ----------------------------------------
extern "C" void kernel_launch(void* const* d_in, const int* in_sizes, int n_in,
                              void* d_out, int out_size)
{
    const float* inp   = (const float*)d_in[0];
    const float* gamma = (const float*)d_in[1];
    const float* beta  = (const float*)d_in[2];
    const float* Wq    = (const float*)d_in[3];
    const float* bq    = (const float*)d_in[4];
    const float* Wk    = (const float*)d_in[5];
    const float* bk    = (const float*)d_in[6];
    const float* Wv    = (const float*)d_in[7];
    const float* bv    = (const float*)d_in[8];
    const float* Wo    = (const float*)d_in[9];
    const float* bo    = (const float*)d_in[10];
    float* outp = (float*)d_out;

    int gemm_smem = (CC*CC + CC*64) * (int)sizeof(float);                       // 96 KB
    int attn_smem = (CC*64*2 + 64*VSTR + 64*PSTR + 128) * (int)sizeof(float);   // ~114 KB
    cudaFuncSetAttribute(qkv_kernel, cudaFuncAttributeMaxDynamicSharedMemorySize, gemm_smem);
    cudaFuncSetAttribute(attn_kernel, cudaFuncAttributeMaxDynamicSharedMemorySize, attn_smem);
    cudaFuncSetAttribute(proj_kernel, cudaFuncAttributeMaxDynamicSharedMemorySize, gemm_smem);

    stats_kernel<<<CC, 256>>>(inp, gamma, beta);
    fold_kernel<<<3*CC, CC>>>(Wq, bq, Wk, bk, Wv, bv);
    qkv_kernel<<<dim3(NV/64, 3, NB), 256, gemm_smem>>>(inp);
    attn_kernel<<<dim3(NV/64, NB), 256, attn_smem>>>();
    proj_kernel<<<dim3(NV/64, NB), 256, gemm_smem>>>(inp, Wo, bo, outp);
}

// round 6
// speedup vs baseline: 3.6866x; 3.6866x over previous
#include <cuda_runtime.h>
#include <cuda_bf16.h>
#include <math.h>
#include <stdint.h>

#define CC   128
#define NV   4096
#define NB   2
#define EPSF 1e-5f
#define NVNV ((size_t)NV*(size_t)NV)

// ---------------- scratch (no allocation allowed) ----------------
__device__ float g_a[CC];
__device__ float g_dd[CC];
__device__ float g_Wq[CC*CC];
__device__ float g_Wk[CC*CC];
__device__ float g_Wv[CC*CC];
__device__ float g_bq[CC];
__device__ float g_bk[CC];
__device__ float g_bv[CC];
__device__ float g_q[NB*CC*NV];
__device__ float g_k[NB*CC*NV];
__device__ float g_v[NB*CC*NV];
__device__ float g_hT[NB*NV*CC];          // attention out, [b][i][c]
__device__ __nv_bfloat16 g_qTh[NB*NV*CC]; // q^T split hi/lo, [b][i][c]
__device__ __nv_bfloat16 g_qTl[NB*NV*CC];
__device__ __nv_bfloat16 g_kTh[NB*NV*CC];
__device__ __nv_bfloat16 g_kTl[NB*NV*CC];
__device__ __nv_bfloat16 g_vh[NB*CC*NV];  // v split, natural [b][c][n]
__device__ __nv_bfloat16 g_vl[NB*CC*NV];
__device__ float g_S[NB*NV*NV];           // scores (log2-domain)
__device__ __nv_bfloat16 g_Ph[NB*NV*NV];  // normalized probs split
__device__ __nv_bfloat16 g_Pl[NB*NV*NV];

// ---------------- PTX helpers (compute_80-era only!) -------------
__device__ __forceinline__ uint32_t smem_u32(const void* p) {
    uint32_t a;
    asm("{ .reg .u64 t; cvta.to.shared.u64 t, %1; cvt.u32.u64 %0, t; }"
        : "=r"(a) : "l"(p));
    return a;
}
#define LDMX4(r0,r1,r2,r3,addr) \
    asm volatile("ldmatrix.sync.aligned.m8n8.x4.shared.b16 {%0,%1,%2,%3}, [%4];" \
                 : "=r"(r0),"=r"(r1),"=r"(r2),"=r"(r3) : "r"(addr))
#define MMA_BF16(c,a,b) \
    asm volatile("mma.sync.aligned.m16n8k16.row.col.f32.bf16.bf16.f32 " \
                 "{%0,%1,%2,%3}, {%4,%5,%6,%7}, {%8,%9}, {%0,%1,%2,%3};" \
                 : "+f"((c)[0]),"+f"((c)[1]),"+f"((c)[2]),"+f"((c)[3]) \
                 : "r"((a)[0]),"r"((a)[1]),"r"((a)[2]),"r"((a)[3]), \
                   "r"((b)[0]),"r"((b)[1]))
#define CP_ASYNC16(s,g) \
    asm volatile("cp.async.cg.shared.global [%0], [%1], 16;" :: "r"(s), "l"(g) : "memory")
#define CP_COMMIT()  asm volatile("cp.async.commit_group;" ::: "memory")
#define CP_WAIT1()   asm volatile("cp.async.wait_group 1;" ::: "memory")
#define CP_WAIT0()   asm volatile("cp.async.wait_group 0;" ::: "memory")

__device__ __forceinline__ uint32_t pack_bf2(float a, float b) {
    __nv_bfloat162 t = __floats2bfloat162_rn(a, b);
    return *reinterpret_cast<uint32_t*>(&t);
}

// ---------------- 1) per-channel batch stats --------------------
__global__ void stats_kernel(const float* __restrict__ inp,
                             const float* __restrict__ gamma,
                             const float* __restrict__ beta)
{
    int c = blockIdx.x;
    int tid = threadIdx.x;
    const float* p0 = inp + c * NV;
    const float* p1 = inp + (CC + c) * NV;
    float s = 0.f, ss = 0.f;
    for (int n = tid * 4; n < NV; n += 256 * 4) {
        float4 a = *(const float4*)(p0 + n);
        float4 b = *(const float4*)(p1 + n);
        s  += a.x + a.y + a.z + a.w + b.x + b.y + b.z + b.w;
        ss += a.x*a.x + a.y*a.y + a.z*a.z + a.w*a.w
            + b.x*b.x + b.y*b.y + b.z*b.z + b.w*b.w;
    }
    #pragma unroll
    for (int off = 16; off; off >>= 1) {
        s  += __shfl_xor_sync(0xffffffffu, s, off);
        ss += __shfl_xor_sync(0xffffffffu, ss, off);
    }
    __shared__ float sb[8], ssb[8];
    int w = tid >> 5;
    if ((tid & 31) == 0) { sb[w] = s; ssb[w] = ss; }
    __syncthreads();
    if (tid == 0) {
        float ts = 0.f, tss = 0.f;
        #pragma unroll
        for (int i = 0; i < 8; i++) { ts += sb[i]; tss += ssb[i]; }
        const float inv = 1.f / (float)(NB * NV);
        float mean = ts * inv;
        float var  = tss * inv - mean * mean;
        float a = gamma[c] * rsqrtf(var + EPSF);
        g_a[c]  = a;
        g_dd[c] = beta[c] - mean * a;
    }
}

// ---------------- 2) fold BN (+ q scale + log2e) into weights ---
__global__ void fold_kernel(const float* __restrict__ Wq, const float* __restrict__ bq,
                            const float* __restrict__ Wk, const float* __restrict__ bk,
                            const float* __restrict__ Wv, const float* __restrict__ bv)
{
    int m = blockIdx.x >> 7;
    int o = blockIdx.x & 127;
    int c = threadIdx.x;
    const float QSC = 1.44269504088896341f * 0.0883883476483184406f;
    const float* W; const float* bs; float* Wd; float* bd; float sc;
    if (m == 0)      { W = Wq; bs = bq; Wd = g_Wq; bd = g_bq; sc = QSC; }
    else if (m == 1) { W = Wk; bs = bk; Wd = g_Wk; bd = g_bk; sc = 1.f; }
    else             { W = Wv; bs = bv; Wd = g_Wv; bd = g_bv; sc = 1.f; }
    float w = W[o*CC + c];
    Wd[o*CC + c] = w * g_a[c] * sc;
    float part = w * g_dd[c];
    #pragma unroll
    for (int off = 16; off; off >>= 1)
        part += __shfl_xor_sync(0xffffffffu, part, off);
    __shared__ float pb[4];
    if ((c & 31) == 0) pb[c >> 5] = part;
    __syncthreads();
    if (c == 0) bd[o] = (bs[o] + pb[0] + pb[1] + pb[2] + pb[3]) * sc;
}

// ---------------- 3) QKV GEMM -----------------------------------
__global__ void qkv_kernel(const float* __restrict__ inp)
{
    extern __shared__ float sm[];
    float* Ws = sm;
    float* xs = sm + CC*CC;
    int m = blockIdx.y, b = blockIdx.z;
    int n0 = blockIdx.x * 64;
    const float* W  = (m == 0) ? g_Wq : (m == 1) ? g_Wk : g_Wv;
    const float* bb = (m == 0) ? g_bq : (m == 1) ? g_bk : g_bv;
    float* outp = ((m == 0) ? g_q : (m == 1) ? g_k : g_v) + (size_t)b*CC*NV;
    int tid = threadIdx.x;

    for (int i = tid; i < CC*CC/4; i += 256) {
        int o  = i >> 5;
        int c4 = (i & 31) << 2;
        float4 w = *(const float4*)(W + o*CC + c4);
        Ws[(c4+0)*CC + o] = w.x;
        Ws[(c4+1)*CC + o] = w.y;
        Ws[(c4+2)*CC + o] = w.z;
        Ws[(c4+3)*CC + o] = w.w;
    }
    for (int i = tid; i < CC*16; i += 256) {
        int c  = i >> 4;
        int j4 = (i & 15) << 2;
        *(float4*)(xs + c*64 + j4) =
            *(const float4*)(inp + ((size_t)b*CC + c)*NV + n0 + j4);
    }
    __syncthreads();

    int oy = tid >> 4;
    int nx = tid & 15;
    float acc[8][4];
    #pragma unroll
    for (int u = 0; u < 8; u++)
        #pragma unroll
        for (int v = 0; v < 4; v++) acc[u][v] = 0.f;

    #pragma unroll 4
    for (int c = 0; c < CC; c++) {
        float4 w0 = *(float4*)(Ws + c*CC + oy*8);
        float4 w1 = *(float4*)(Ws + c*CC + oy*8 + 4);
        float4 x4 = *(float4*)(xs + c*64 + nx*4);
        float wv[8] = {w0.x, w0.y, w0.z, w0.w, w1.x, w1.y, w1.z, w1.w};
        float xv[4] = {x4.x, x4.y, x4.z, x4.w};
        #pragma unroll
        for (int u = 0; u < 8; u++)
            #pragma unroll
            for (int v = 0; v < 4; v++) acc[u][v] += wv[u] * xv[v];
    }

    #pragma unroll
    for (int u = 0; u < 8; u++) {
        int o = oy*8 + u;
        float bias = bb[o];
        float4 r = make_float4(acc[u][0] + bias, acc[u][1] + bias,
                               acc[u][2] + bias, acc[u][3] + bias);
        *(float4*)(outp + (size_t)o*NV + n0 + nx*4) = r;
    }
}

// ---------------- 4) transpose + bf16 split of q,k --------------
__global__ void transsplit_kernel()
{
    __shared__ float ts[32][33];
    int m = blockIdx.z & 1, b = blockIdx.z >> 1;
    int i0 = blockIdx.x * 32, c0 = blockIdx.y * 32;
    const float* src = (m ? g_k : g_q) + (size_t)b*CC*NV;
    __nv_bfloat16* dh = (m ? g_kTh : g_qTh) + (size_t)b*NV*CC;
    __nv_bfloat16* dl = (m ? g_kTl : g_qTl) + (size_t)b*NV*CC;
    int tx = threadIdx.x, ty = threadIdx.y;
    #pragma unroll
    for (int r = 0; r < 4; r++)
        ts[ty + 8*r][tx] = src[(size_t)(c0 + ty + 8*r)*NV + i0 + tx];
    __syncthreads();
    #pragma unroll
    for (int r = 0; r < 4; r++) {
        float v = ts[tx][ty + 8*r];
        __nv_bfloat16 h = __float2bfloat16(v);
        size_t o = (size_t)(i0 + ty + 8*r)*CC + c0 + tx;
        dh[o] = h;
        dl[o] = __float2bfloat16(v - __bfloat162float(h));
    }
}

// ---------------- 5) bf16 split of v ----------------------------
__global__ void vsplit_kernel()
{
    size_t i = ((size_t)blockIdx.x * 256 + threadIdx.x) * 4;
    float4 v = *(const float4*)(g_v + i);
    __nv_bfloat16 h0 = __float2bfloat16(v.x);
    __nv_bfloat16 h1 = __float2bfloat16(v.y);
    __nv_bfloat16 h2 = __float2bfloat16(v.z);
    __nv_bfloat16 h3 = __float2bfloat16(v.w);
    uint2 hi, lo;
    { __nv_bfloat162 a; a.x = h0; a.y = h1; hi.x = *reinterpret_cast<uint32_t*>(&a); }
    { __nv_bfloat162 a; a.x = h2; a.y = h3; hi.y = *reinterpret_cast<uint32_t*>(&a); }
    lo.x = pack_bf2(v.x - __bfloat162float(h0), v.y - __bfloat162float(h1));
    lo.y = pack_bf2(v.z - __bfloat162float(h2), v.w - __bfloat162float(h3));
    *(uint2*)(g_vh + i) = hi;
    *(uint2*)(g_vl + i) = lo;
}

// ---------------- 6) S = Q^T K via HMMA (split x3) --------------
// grid (32 j, 32 i, NB), 256 thr. smem: 4 tiles of [128][272B].
#define QK_STRIDE 272
__global__ void __launch_bounds__(256, 1) qk_kernel()
{
    extern __shared__ char smem[];
    uint32_t sb = smem_u32(smem);
    int tid = threadIdx.x, wid = tid >> 5, lane = tid & 31;
    int b = blockIdx.z, i0 = blockIdx.y * 128, j0 = blockIdx.x * 128;

    const int QH = 0, QL = 34816, KH = 69632, KL = 104448;
    const __nv_bfloat16* srcs[4] = {
        g_qTh + (size_t)b*NV*CC + (size_t)i0*CC,
        g_qTl + (size_t)b*NV*CC + (size_t)i0*CC,
        g_kTh + (size_t)b*NV*CC + (size_t)j0*CC,
        g_kTl + (size_t)b*NV*CC + (size_t)j0*CC };
    const int dsts[4] = {QH, QL, KH, KL};
    #pragma unroll
    for (int s = 0; s < 4; s++) {
        const __nv_bfloat16* src = srcs[s];
        char* dst = smem + dsts[s];
        for (int idx = tid; idx < 2048; idx += 256) {
            int row = idx >> 4, c = idx & 15;
            *(uint4*)(dst + row*QK_STRIDE + c*16) = *(const uint4*)(src + row*CC + c*8);
        }
    }
    __syncthreads();

    int wi = wid >> 1, wj = wid & 1;
    int ib = wi * 32, jb = wj * 64;
    float acc[2][8][4];
    #pragma unroll
    for (int mt = 0; mt < 2; mt++)
        #pragma unroll
        for (int nt = 0; nt < 8; nt++)
            #pragma unroll
            for (int e = 0; e < 4; e++) acc[mt][nt][e] = 0.f;

    int arow = (lane & 15);
    int acol = (lane >> 4) << 3;
    int bm   = lane >> 3;
    int brow = ((bm >> 1) << 3) + (lane & 7);
    int bcol = (bm & 1) << 3;

    #pragma unroll
    for (int pass = 0; pass < 3; pass++) {
        uint32_t Ab = sb + (pass == 2 ? QL : QH);
        uint32_t Bb = sb + (pass == 1 ? KL : KH);
        #pragma unroll
        for (int k = 0; k < 8; k++) {
            int kc = k * 16;
            uint32_t a[2][4];
            #pragma unroll
            for (int mt = 0; mt < 2; mt++) {
                uint32_t addr = Ab + (ib + mt*16 + arow)*QK_STRIDE + (kc + acol)*2;
                LDMX4(a[mt][0], a[mt][1], a[mt][2], a[mt][3], addr);
            }
            uint32_t bf[8][2];
            #pragma unroll
            for (int ntp = 0; ntp < 4; ntp++) {
                uint32_t addr = Bb + (jb + ntp*16 + brow)*QK_STRIDE + (kc + bcol)*2;
                uint32_t r0, r1, r2, r3;
                LDMX4(r0, r1, r2, r3, addr);
                bf[2*ntp][0] = r0;   bf[2*ntp][1] = r1;
                bf[2*ntp+1][0] = r2; bf[2*ntp+1][1] = r3;
            }
            #pragma unroll
            for (int mt = 0; mt < 2; mt++)
                #pragma unroll
                for (int nt = 0; nt < 8; nt++)
                    MMA_BF16(acc[mt][nt], a[mt], bf[nt]);
        }
    }

    float* Sb = g_S + (size_t)b*NVNV;
    int ir = lane >> 2, jc = (lane & 3) * 2;
    #pragma unroll
    for (int mt = 0; mt < 2; mt++)
        #pragma unroll
        for (int nt = 0; nt < 8; nt++) {
            int i = i0 + ib + mt*16 + ir;
            int j = j0 + jb + nt*8 + jc;
            *(float2*)(Sb + (size_t)i*NV + j)     = make_float2(acc[mt][nt][0], acc[mt][nt][1]);
            *(float2*)(Sb + (size_t)(i+8)*NV + j) = make_float2(acc[mt][nt][2], acc[mt][nt][3]);
        }
}

// ---------------- 7) softmax rows -> normalized P (bf16 split) --
__global__ void softmax_kernel()
{
    int b = blockIdx.y, i = blockIdx.x;
    int tid = threadIdx.x, wid = tid >> 5, lid = tid & 31;
    const float* row = g_S + (size_t)b*NVNV + (size_t)i*NV;
    __shared__ float red1[8], red2[8];

    float4 x[4];
    float m = -1e30f;
    #pragma unroll
    for (int r = 0; r < 4; r++) {
        x[r] = *(const float4*)(row + (size_t)(tid + 256*r)*4);
        m = fmaxf(m, fmaxf(fmaxf(x[r].x, x[r].y), fmaxf(x[r].z, x[r].w)));
    }
    #pragma unroll
    for (int off = 16; off; off >>= 1)
        m = fmaxf(m, __shfl_xor_sync(0xffffffffu, m, off));
    if (lid == 0) red1[wid] = m;
    __syncthreads();
    m = red1[0];
    #pragma unroll
    for (int w = 1; w < 8; w++) m = fmaxf(m, red1[w]);

    float sum = 0.f;
    #pragma unroll
    for (int r = 0; r < 4; r++) {
        x[r].x = exp2f(x[r].x - m);
        x[r].y = exp2f(x[r].y - m);
        x[r].z = exp2f(x[r].z - m);
        x[r].w = exp2f(x[r].w - m);
        sum += x[r].x + x[r].y + x[r].z + x[r].w;
    }
    #pragma unroll
    for (int off = 16; off; off >>= 1)
        sum += __shfl_xor_sync(0xffffffffu, sum, off);
    if (lid == 0) red2[wid] = sum;
    __syncthreads();
    sum = 0.f;
    #pragma unroll
    for (int w = 0; w < 8; w++) sum += red2[w];
    float inv = 1.f / sum;

    size_t base = (size_t)b*NVNV + (size_t)i*NV;
    #pragma unroll
    for (int r = 0; r < 4; r++) {
        float p0 = x[r].x * inv, p1 = x[r].y * inv, p2 = x[r].z * inv, p3 = x[r].w * inv;
        __nv_bfloat16 h0 = __float2bfloat16(p0);
        __nv_bfloat16 h1 = __float2bfloat16(p1);
        __nv_bfloat16 h2 = __float2bfloat16(p2);
        __nv_bfloat16 h3 = __float2bfloat16(p3);
        uint2 hi, lo;
        { __nv_bfloat162 a; a.x = h0; a.y = h1; hi.x = *reinterpret_cast<uint32_t*>(&a); }
        { __nv_bfloat162 a; a.x = h2; a.y = h3; hi.y = *reinterpret_cast<uint32_t*>(&a); }
        lo.x = pack_bf2(p0 - __bfloat162float(h0), p1 - __bfloat162float(h1));
        lo.y = pack_bf2(p2 - __bfloat162float(h2), p3 - __bfloat162float(h3));
        size_t e = base + (size_t)(tid + 256*r)*4;
        *(uint2*)(g_Ph + e) = hi;
        *(uint2*)(g_Pl + e) = lo;
    }
}

// ---------------- 8) H^T = P V^T via HMMA (split x3) ------------
// grid (64 iblk, NB), 256 thr. CTA: 64 i-rows x 128 channels, K=4096
// in 64 chunks of 64, cp.async double-buffered.
#define PV_STRIDE 144
__global__ void __launch_bounds__(256, 1) pv_kernel()
{
    extern __shared__ char smem[];
    uint32_t sb = smem_u32(smem);
    int tid = threadIdx.x, wid = tid >> 5, lane = tid & 31;
    int b = blockIdx.y, i0 = blockIdx.x * 64;

    const int BUFSZ = 55296, PH = 0, PL = 9216, VH = 18432, VL = 36864;
    const __nv_bfloat16* Pha = g_Ph + (size_t)b*NVNV + (size_t)i0*NV;
    const __nv_bfloat16* Pla = g_Pl + (size_t)b*NVNV + (size_t)i0*NV;
    const __nv_bfloat16* Vha = g_vh + (size_t)b*CC*NV;
    const __nv_bfloat16* Vla = g_vl + (size_t)b*CC*NV;

    // ---- prefetch chunk 0 into buffer 0
    {
        int j0 = 0;
        uint32_t base = sb;
        for (int idx = tid; idx < 512; idx += 256) {
            int row = idx >> 3, c = idx & 7;
            uint32_t so = base + PH + row*PV_STRIDE + c*16;
            size_t go = (size_t)row*NV + j0 + c*8;
            CP_ASYNC16(so, Pha + go);
            CP_ASYNC16(so + (PL - PH), Pla + go);
        }
        for (int idx = tid; idx < 1024; idx += 256) {
            int row = idx >> 3, c = idx & 7;
            uint32_t so = base + VH + row*PV_STRIDE + c*16;
            size_t go = (size_t)row*NV + j0 + c*8;
            CP_ASYNC16(so, Vha + go);
            CP_ASYNC16(so + (VL - VH), Vla + go);
        }
        CP_COMMIT();
    }

    int wi = wid >> 2, wc = wid & 3;
    int ib = wi * 32, cb = wc * 32;
    float acc[2][4][4];
    #pragma unroll
    for (int mt = 0; mt < 2; mt++)
        #pragma unroll
        for (int nt = 0; nt < 4; nt++)
            #pragma unroll
            for (int e = 0; e < 4; e++) acc[mt][nt][e] = 0.f;

    int arow = (lane & 15);
    int acol = (lane >> 4) << 3;
    int bm   = lane >> 3;
    int brow = ((bm >> 1) << 3) + (lane & 7);
    int bcol = (bm & 1) << 3;

    for (int t = 0; t < 64; t++) {
        int buf = t & 1;
        if (t + 1 < 64) {
            int j0 = (t + 1) * 64;
            uint32_t base = sb + (buf ^ 1) * BUFSZ;
            for (int idx = tid; idx < 512; idx += 256) {
                int row = idx >> 3, c = idx & 7;
                uint32_t so = base + PH + row*PV_STRIDE + c*16;
                size_t go = (size_t)row*NV + j0 + c*8;
                CP_ASYNC16(so, Pha + go);
                CP_ASYNC16(so + (PL - PH), Pla + go);
            }
            for (int idx = tid; idx < 1024; idx += 256) {
                int row = idx >> 3, c = idx & 7;
                uint32_t so = base + VH + row*PV_STRIDE + c*16;
                size_t go = (size_t)row*NV + j0 + c*8;
                CP_ASYNC16(so, Vha + go);
                CP_ASYNC16(so + (VL - VH), Vla + go);
            }
            CP_COMMIT();
            CP_WAIT1();
        } else {
            CP_WAIT0();
        }
        __syncthreads();

        uint32_t base = sb + buf * BUFSZ;
        #pragma unroll
        for (int pass = 0; pass < 3; pass++) {
            uint32_t Ab = base + (pass == 2 ? PL : PH);
            uint32_t Bb = base + (pass == 1 ? VL : VH);
            #pragma unroll
            for (int k = 0; k < 4; k++) {
                int kc = k * 16;
                uint32_t a[2][4];
                #pragma unroll
                for (int mt = 0; mt < 2; mt++) {
                    uint32_t addr = Ab + (ib + mt*16 + arow)*PV_STRIDE + (kc + acol)*2;
                    LDMX4(a[mt][0], a[mt][1], a[mt][2], a[mt][3], addr);
                }
                uint32_t bf[4][2];
                #pragma unroll
                for (int ntp = 0; ntp < 2; ntp++) {
                    uint32_t addr = Bb + (cb + ntp*16 + brow)*PV_STRIDE + (kc + bcol)*2;
                    uint32_t r0, r1, r2, r3;
                    LDMX4(r0, r1, r2, r3, addr);
                    bf[2*ntp][0] = r0;   bf[2*ntp][1] = r1;
                    bf[2*ntp+1][0] = r2; bf[2*ntp+1][1] = r3;
                }
                #pragma unroll
                for (int mt = 0; mt < 2; mt++)
                    #pragma unroll
                    for (int nt = 0; nt < 4; nt++)
                        MMA_BF16(acc[mt][nt], a[mt], bf[nt]);
            }
        }
        __syncthreads();
    }

    float* H = g_hT + (size_t)b*NV*CC;
    int ir = lane >> 2, jc = (lane & 3) * 2;
    #pragma unroll
    for (int mt = 0; mt < 2; mt++)
        #pragma unroll
        for (int nt = 0; nt < 4; nt++) {
            int i = i0 + ib + mt*16 + ir;
            int c = cb + nt*8 + jc;
            *(float2*)(H + (size_t)i*CC + c)     = make_float2(acc[mt][nt][0], acc[mt][nt][1]);
            *(float2*)(H + (size_t)(i+8)*CC + c) = make_float2(acc[mt][nt][2], acc[mt][nt][3]);
        }
}

// ---------------- 9) output projection + residual ---------------
__global__ void proj_kernel(const float* __restrict__ inp,
                            const float* __restrict__ Wo,
                            const float* __restrict__ bo,
                            float* __restrict__ outp)
{
    extern __shared__ float sm[];
    float* Ws = sm;
    float* xs = sm + CC*CC;
    int b = blockIdx.y;
    int n0 = blockIdx.x * 64;
    int tid = threadIdx.x;

    for (int i = tid; i < CC*CC/4; i += 256) {
        int o  = i >> 5;
        int c4 = (i & 31) << 2;
        float4 w = *(const float4*)(Wo + o*CC + c4);
        Ws[(c4+0)*CC + o] = w.x;
        Ws[(c4+1)*CC + o] = w.y;
        Ws[(c4+2)*CC + o] = w.z;
        Ws[(c4+3)*CC + o] = w.w;
    }
    const float* hsrc = g_hT + (size_t)b*NV*CC;
    for (int i = tid; i < 64*32; i += 256) {
        int j  = i >> 5;
        int c4 = (i & 31) << 2;
        float4 h4 = *(const float4*)(hsrc + (size_t)(n0 + j)*CC + c4);
        xs[(c4+0)*64 + j] = h4.x;
        xs[(c4+1)*64 + j] = h4.y;
        xs[(c4+2)*64 + j] = h4.z;
        xs[(c4+3)*64 + j] = h4.w;
    }
    __syncthreads();

    int oy = tid >> 4;
    int nx = tid & 15;
    float acc[8][4];
    #pragma unroll
    for (int u = 0; u < 8; u++)
        #pragma unroll
        for (int v = 0; v < 4; v++) acc[u][v] = 0.f;

    #pragma unroll 4
    for (int c = 0; c < CC; c++) {
        float4 w0 = *(float4*)(Ws + c*CC + oy*8);
        float4 w1 = *(float4*)(Ws + c*CC + oy*8 + 4);
        float4 x4 = *(float4*)(xs + c*64 + nx*4);
        float wv[8] = {w0.x, w0.y, w0.z, w0.w, w1.x, w1.y, w1.z, w1.w};
        float xv[4] = {x4.x, x4.y, x4.z, x4.w};
        #pragma unroll
        for (int u = 0; u < 8; u++)
            #pragma unroll
            for (int v = 0; v < 4; v++) acc[u][v] += wv[u] * xv[v];
    }

    #pragma unroll
    for (int u = 0; u < 8; u++) {
        int o = oy*8 + u;
        float bias = bo[o];
        float4 r0 = *(const float4*)(inp + ((size_t)b*CC + o)*NV + n0 + nx*4);
        float4 r = make_float4(acc[u][0] + bias + r0.x,
                               acc[u][1] + bias + r0.y,
                               acc[u][2] + bias + r0.z,
                               acc[u][3] + bias + r0.w);
        *(float4*)(outp + ((size_t)b*CC + o)*NV + n0 + nx*4) = r;
    }
}

// ---------------- launch ----------------------------------------
extern "C" void kernel_launch(void* const* d_in, const int* in_sizes, int n_in,
                              void* d_out, int out_size)
{
    const float* inp   = (const float*)d_in[0];
    const float* gamma = (const float*)d_in[1];
    const float* beta  = (const float*)d_in[2];
    const float* Wq    = (const float*)d_in[3];
    const float* bq    = (const float*)d_in[4];
    const float* Wk    = (const float*)d_in[5];
    const float* bk    = (const float*)d_in[6];
    const float* Wv    = (const float*)d_in[7];
    const float* bv    = (const float*)d_in[8];
    const float* Wo    = (const float*)d_in[9];
    const float* bo    = (const float*)d_in[10];
    float* outp = (float*)d_out;

    int gemm_smem = (CC*CC + CC*64) * (int)sizeof(float);   // 96 KB
    int qk_smem   = 4 * 128 * QK_STRIDE;                    // 139264
    int pv_smem   = 2 * 55296;                              // 110592
    cudaFuncSetAttribute(qkv_kernel,  cudaFuncAttributeMaxDynamicSharedMemorySize, gemm_smem);
    cudaFuncSetAttribute(proj_kernel, cudaFuncAttributeMaxDynamicSharedMemorySize, gemm_smem);
    cudaFuncSetAttribute(qk_kernel,   cudaFuncAttributeMaxDynamicSharedMemorySize, qk_smem);
    cudaFuncSetAttribute(pv_kernel,   cudaFuncAttributeMaxDynamicSharedMemorySize, pv_smem);

    stats_kernel<<<CC, 256>>>(inp, gamma, beta);
    fold_kernel<<<3*CC, CC>>>(Wq, bq, Wk, bk, Wv, bv);
    qkv_kernel<<<dim3(NV/64, 3, NB), 256, gemm_smem>>>(inp);
    transsplit_kernel<<<dim3(NV/32, CC/32, 2*NB), dim3(32, 8)>>>();
    vsplit_kernel<<<(NB*CC*NV)/1024, 256>>>();
    qk_kernel<<<dim3(NV/128, NV/128, NB), 256, qk_smem>>>();
    softmax_kernel<<<dim3(NV, NB), 256>>>();
    pv_kernel<<<dim3(NV/64, NB), 256, pv_smem>>>();
    proj_kernel<<<dim3(NV/64, NB), 256, gemm_smem>>>(inp, Wo, bo, outp);
}

// round 7
// speedup vs baseline: 4.5548x; 1.2355x over previous
#include <cuda_runtime.h>
#include <cuda_bf16.h>
#include <math.h>
#include <stdint.h>

#define CC   128
#define NV   4096
#define NB   2
#define EPSF 1e-5f

// ---------------- scratch (no allocation allowed) ----------------
__device__ float g_a[CC];
__device__ float g_dd[CC];
__device__ float g_Wq[CC*CC];
__device__ float g_Wk[CC*CC];
__device__ float g_Wv[CC*CC];
__device__ float g_bq[CC];
__device__ float g_bk[CC];
__device__ float g_bv[CC];
__device__ float g_q[NB*CC*NV];
__device__ float g_k[NB*CC*NV];
__device__ float g_v[NB*CC*NV];
__device__ float g_hT[NB*NV*CC];          // attention out, [b][i][c]
__device__ __nv_bfloat16 g_qTh[NB*NV*CC]; // q^T split hi/lo, [b][i][c]
__device__ __nv_bfloat16 g_qTl[NB*NV*CC];
__device__ __nv_bfloat16 g_kTh[NB*NV*CC];
__device__ __nv_bfloat16 g_kTl[NB*NV*CC];
__device__ __nv_bfloat16 g_vh[NB*CC*NV];  // v split, natural [b][c][n]
__device__ __nv_bfloat16 g_vl[NB*CC*NV];

// ---------------- PTX helpers (compute_80-era only!) -------------
__device__ __forceinline__ uint32_t smem_u32(const void* p) {
    uint32_t a;
    asm("{ .reg .u64 t; cvta.to.shared.u64 t, %1; cvt.u32.u64 %0, t; }"
        : "=r"(a) : "l"(p));
    return a;
}
#define LDMX4(r0,r1,r2,r3,addr) \
    asm volatile("ldmatrix.sync.aligned.m8n8.x4.shared.b16 {%0,%1,%2,%3}, [%4];" \
                 : "=r"(r0),"=r"(r1),"=r"(r2),"=r"(r3) : "r"(addr))
#define MMA_BF16(c,a,b) \
    asm volatile("mma.sync.aligned.m16n8k16.row.col.f32.bf16.bf16.f32 " \
                 "{%0,%1,%2,%3}, {%4,%5,%6,%7}, {%8,%9}, {%0,%1,%2,%3};" \
                 : "+f"((c)[0]),"+f"((c)[1]),"+f"((c)[2]),"+f"((c)[3]) \
                 : "r"((a)[0]),"r"((a)[1]),"r"((a)[2]),"r"((a)[3]), \
                   "r"((b)[0]),"r"((b)[1]))
#define CP_ASYNC16(s,g) \
    asm volatile("cp.async.cg.shared.global [%0], [%1], 16;" :: "r"(s), "l"(g) : "memory")
#define CP_COMMIT()  asm volatile("cp.async.commit_group;" ::: "memory")
#define CP_WAIT1()   asm volatile("cp.async.wait_group 1;" ::: "memory")
#define CP_WAIT0()   asm volatile("cp.async.wait_group 0;" ::: "memory")

__device__ __forceinline__ uint32_t pack_bf2(float a, float b) {
    __nv_bfloat162 t = __floats2bfloat162_rn(a, b);
    return *reinterpret_cast<uint32_t*>(&t);
}
__device__ __forceinline__ void split_pack(float a, float b, uint32_t& hi, uint32_t& lo) {
    __nv_bfloat16 ha = __float2bfloat16(a), hb = __float2bfloat16(b);
    __nv_bfloat162 H; H.x = ha; H.y = hb;
    hi = *reinterpret_cast<uint32_t*>(&H);
    lo = pack_bf2(a - __bfloat162float(ha), b - __bfloat162float(hb));
}

// ---------------- 1) per-channel batch stats --------------------
__global__ void stats_kernel(const float* __restrict__ inp,
                             const float* __restrict__ gamma,
                             const float* __restrict__ beta)
{
    int c = blockIdx.x;
    int tid = threadIdx.x;
    const float* p0 = inp + c * NV;
    const float* p1 = inp + (CC + c) * NV;
    float s = 0.f, ss = 0.f;
    for (int n = tid * 4; n < NV; n += 256 * 4) {
        float4 a = *(const float4*)(p0 + n);
        float4 b = *(const float4*)(p1 + n);
        s  += a.x + a.y + a.z + a.w + b.x + b.y + b.z + b.w;
        ss += a.x*a.x + a.y*a.y + a.z*a.z + a.w*a.w
            + b.x*b.x + b.y*b.y + b.z*b.z + b.w*b.w;
    }
    #pragma unroll
    for (int off = 16; off; off >>= 1) {
        s  += __shfl_xor_sync(0xffffffffu, s, off);
        ss += __shfl_xor_sync(0xffffffffu, ss, off);
    }
    __shared__ float sb[8], ssb[8];
    int w = tid >> 5;
    if ((tid & 31) == 0) { sb[w] = s; ssb[w] = ss; }
    __syncthreads();
    if (tid == 0) {
        float ts = 0.f, tss = 0.f;
        #pragma unroll
        for (int i = 0; i < 8; i++) { ts += sb[i]; tss += ssb[i]; }
        const float inv = 1.f / (float)(NB * NV);
        float mean = ts * inv;
        float var  = tss * inv - mean * mean;
        float a = gamma[c] * rsqrtf(var + EPSF);
        g_a[c]  = a;
        g_dd[c] = beta[c] - mean * a;
    }
}

// ---------------- 2) fold BN (+ q scale + log2e) into weights ---
__global__ void fold_kernel(const float* __restrict__ Wq, const float* __restrict__ bq,
                            const float* __restrict__ Wk, const float* __restrict__ bk,
                            const float* __restrict__ Wv, const float* __restrict__ bv)
{
    int m = blockIdx.x >> 7;
    int o = blockIdx.x & 127;
    int c = threadIdx.x;
    const float QSC = 1.44269504088896341f * 0.0883883476483184406f;
    const float* W; const float* bs; float* Wd; float* bd; float sc;
    if (m == 0)      { W = Wq; bs = bq; Wd = g_Wq; bd = g_bq; sc = QSC; }
    else if (m == 1) { W = Wk; bs = bk; Wd = g_Wk; bd = g_bk; sc = 1.f; }
    else             { W = Wv; bs = bv; Wd = g_Wv; bd = g_bv; sc = 1.f; }
    float w = W[o*CC + c];
    Wd[o*CC + c] = w * g_a[c] * sc;
    float part = w * g_dd[c];
    #pragma unroll
    for (int off = 16; off; off >>= 1)
        part += __shfl_xor_sync(0xffffffffu, part, off);
    __shared__ float pb[4];
    if ((c & 31) == 0) pb[c >> 5] = part;
    __syncthreads();
    if (c == 0) bd[o] = (bs[o] + pb[0] + pb[1] + pb[2] + pb[3]) * sc;
}

// ---------------- 3) QKV GEMM -----------------------------------
__global__ void qkv_kernel(const float* __restrict__ inp)
{
    extern __shared__ float sm[];
    float* Ws = sm;
    float* xs = sm + CC*CC;
    int m = blockIdx.y, b = blockIdx.z;
    int n0 = blockIdx.x * 64;
    const float* W  = (m == 0) ? g_Wq : (m == 1) ? g_Wk : g_Wv;
    const float* bb = (m == 0) ? g_bq : (m == 1) ? g_bk : g_bv;
    float* outp = ((m == 0) ? g_q : (m == 1) ? g_k : g_v) + (size_t)b*CC*NV;
    int tid = threadIdx.x;

    for (int i = tid; i < CC*CC/4; i += 256) {
        int o  = i >> 5;
        int c4 = (i & 31) << 2;
        float4 w = *(const float4*)(W + o*CC + c4);
        Ws[(c4+0)*CC + o] = w.x;
        Ws[(c4+1)*CC + o] = w.y;
        Ws[(c4+2)*CC + o] = w.z;
        Ws[(c4+3)*CC + o] = w.w;
    }
    for (int i = tid; i < CC*16; i += 256) {
        int c  = i >> 4;
        int j4 = (i & 15) << 2;
        *(float4*)(xs + c*64 + j4) =
            *(const float4*)(inp + ((size_t)b*CC + c)*NV + n0 + j4);
    }
    __syncthreads();

    int oy = tid >> 4;
    int nx = tid & 15;
    float acc[8][4];
    #pragma unroll
    for (int u = 0; u < 8; u++)
        #pragma unroll
        for (int v = 0; v < 4; v++) acc[u][v] = 0.f;

    #pragma unroll 4
    for (int c = 0; c < CC; c++) {
        float4 w0 = *(float4*)(Ws + c*CC + oy*8);
        float4 w1 = *(float4*)(Ws + c*CC + oy*8 + 4);
        float4 x4 = *(float4*)(xs + c*64 + nx*4);
        float wv[8] = {w0.x, w0.y, w0.z, w0.w, w1.x, w1.y, w1.z, w1.w};
        float xv[4] = {x4.x, x4.y, x4.z, x4.w};
        #pragma unroll
        for (int u = 0; u < 8; u++)
            #pragma unroll
            for (int v = 0; v < 4; v++) acc[u][v] += wv[u] * xv[v];
    }

    #pragma unroll
    for (int u = 0; u < 8; u++) {
        int o = oy*8 + u;
        float bias = bb[o];
        float4 r = make_float4(acc[u][0] + bias, acc[u][1] + bias,
                               acc[u][2] + bias, acc[u][3] + bias);
        *(float4*)(outp + (size_t)o*NV + n0 + nx*4) = r;
    }
}

// ---------------- 4) transpose + bf16 split of q,k --------------
__global__ void transsplit_kernel()
{
    __shared__ float ts[32][33];
    int m = blockIdx.z & 1, b = blockIdx.z >> 1;
    int i0 = blockIdx.x * 32, c0 = blockIdx.y * 32;
    const float* src = (m ? g_k : g_q) + (size_t)b*CC*NV;
    __nv_bfloat16* dh = (m ? g_kTh : g_qTh) + (size_t)b*NV*CC;
    __nv_bfloat16* dl = (m ? g_kTl : g_qTl) + (size_t)b*NV*CC;
    int tx = threadIdx.x, ty = threadIdx.y;
    #pragma unroll
    for (int r = 0; r < 4; r++)
        ts[ty + 8*r][tx] = src[(size_t)(c0 + ty + 8*r)*NV + i0 + tx];
    __syncthreads();
    #pragma unroll
    for (int r = 0; r < 4; r++) {
        float v = ts[tx][ty + 8*r];
        __nv_bfloat16 h = __float2bfloat16(v);
        size_t o = (size_t)(i0 + ty + 8*r)*CC + c0 + tx;
        dh[o] = h;
        dl[o] = __float2bfloat16(v - __bfloat162float(h));
    }
}

// ---------------- 5) bf16 split of v ----------------------------
__global__ void vsplit_kernel()
{
    size_t i = ((size_t)blockIdx.x * 256 + threadIdx.x) * 4;
    float4 v = *(const float4*)(g_v + i);
    uint32_t h0, l0, h1, l1;
    split_pack(v.x, v.y, h0, l0);
    split_pack(v.z, v.w, h1, l1);
    uint2 hi = make_uint2(h0, h1), lo = make_uint2(l0, l1);
    *(uint2*)(g_vh + i) = hi;
    *(uint2*)(g_vl + i) = lo;
}

// ---------------- 6) fused flash attention (HMMA, split x3) -----
// grid (NV/64, NB), 256 thr = 8 warps.
// warp w: i-rows [(w&3)*16, +16), j-half (w>>2)*32 of each 64-j chunk.
// K/V hi/lo chunk tiles double-buffered via cp.async.
#define FA_QSTR 272
#define FA_VSTR 144
#define FA_QL   17408
#define FA_BUF0 34816
#define FA_KL   17408
#define FA_VH   34816
#define FA_VL   53248
#define FA_BUFSZ 71680
#define FA_HM   178176
#define FA_LS   178688
#define FA_SMEM 179200

__global__ void __launch_bounds__(256, 1) fattn_kernel()
{
    extern __shared__ char smem[];
    uint32_t sb = smem_u32(smem);
    int tid = threadIdx.x, wid = tid >> 5, lane = tid & 31;
    int b = blockIdx.y, i0 = blockIdx.x * 64;

    const __nv_bfloat16* Qh = g_qTh + (size_t)b*NV*CC + (size_t)i0*CC;
    const __nv_bfloat16* Ql = g_qTl + (size_t)b*NV*CC + (size_t)i0*CC;
    const __nv_bfloat16* Kh = g_kTh + (size_t)b*NV*CC;
    const __nv_bfloat16* Kl = g_kTl + (size_t)b*NV*CC;
    const __nv_bfloat16* Vh = g_vh  + (size_t)b*CC*NV;
    const __nv_bfloat16* Vl = g_vl  + (size_t)b*CC*NV;

    // ---- prologue: Q tiles + chunk 0 into buffer 0
    for (int idx = tid; idx < 1024; idx += 256) {
        int row = idx >> 4, c = idx & 15;
        uint32_t so = sb + row*FA_QSTR + c*16;
        size_t go = (size_t)row*CC + c*8;
        CP_ASYNC16(so, Qh + go);
        CP_ASYNC16(so + FA_QL, Ql + go);
    }
    {
        uint32_t base = sb + FA_BUF0;
        for (int idx = tid; idx < 1024; idx += 256) {
            int row = idx >> 4, c = idx & 15;
            uint32_t so = base + row*FA_QSTR + c*16;
            size_t go = (size_t)row*CC + c*8;
            CP_ASYNC16(so, Kh + go);
            CP_ASYNC16(so + FA_KL, Kl + go);
        }
        for (int idx = tid; idx < 1024; idx += 256) {
            int row = idx >> 3, c = idx & 7;
            uint32_t so = base + FA_VH + row*FA_VSTR + c*16;
            size_t go = (size_t)row*NV + c*8;
            CP_ASYNC16(so, Vh + go);
            CP_ASYNC16(so + (FA_VL - FA_VH), Vl + go);
        }
        CP_COMMIT();
    }

    int ig = (wid & 3) * 16;
    int jh = (wid >> 2) * 32;
    int half = jh >> 5;
    int arow = lane & 15, acol = (lane >> 4) << 3;
    int bm = lane >> 3;
    int brow = ((bm >> 1) << 3) + (lane & 7);
    int bcol = (bm & 1) << 3;
    int qgrp = lane & 3;
    int lr = ig + (lane >> 2);

    float acc[16][4];
    #pragma unroll
    for (int nt = 0; nt < 16; nt++)
        #pragma unroll
        for (int e = 0; e < 4; e++) acc[nt][e] = 0.f;
    float l0 = 0.f, l1 = 0.f, m0 = -1e30f, m1 = -1e30f;

    float* hm = (float*)(smem + FA_HM);
    float* ls = (float*)(smem + FA_LS);

    for (int t = 0; t < 64; t++) {
        uint32_t base = sb + FA_BUF0 + (uint32_t)(t & 1)*FA_BUFSZ;
        if (t + 1 < 64) {
            uint32_t nb = sb + FA_BUF0 + (uint32_t)((t + 1) & 1)*FA_BUFSZ;
            int j0 = (t + 1) * 64;
            for (int idx = tid; idx < 1024; idx += 256) {
                int row = idx >> 4, c = idx & 15;
                uint32_t so = nb + row*FA_QSTR + c*16;
                size_t go = (size_t)(j0 + row)*CC + c*8;
                CP_ASYNC16(so, Kh + go);
                CP_ASYNC16(so + FA_KL, Kl + go);
            }
            for (int idx = tid; idx < 1024; idx += 256) {
                int row = idx >> 3, c = idx & 7;
                uint32_t so = nb + FA_VH + row*FA_VSTR + c*16;
                size_t go = (size_t)row*NV + j0 + c*8;
                CP_ASYNC16(so, Vh + go);
                CP_ASYNC16(so + (FA_VL - FA_VH), Vl + go);
            }
            CP_COMMIT();
            CP_WAIT1();
        } else {
            CP_WAIT0();
        }
        __syncthreads();

        // ---- QK: S (16 x 32) for this warp, 3-pass split
        float s[4][4];
        #pragma unroll
        for (int nt = 0; nt < 4; nt++)
            #pragma unroll
            for (int e = 0; e < 4; e++) s[nt][e] = 0.f;
        #pragma unroll
        for (int pass = 0; pass < 3; pass++) {
            uint32_t Ab = sb + (pass == 2 ? FA_QL : 0);
            uint32_t Bb = base + (pass == 1 ? FA_KL : 0);
            #pragma unroll
            for (int k = 0; k < 8; k++) {
                uint32_t a[4];
                LDMX4(a[0], a[1], a[2], a[3],
                      Ab + (ig + arow)*FA_QSTR + (k*16 + acol)*2);
                uint32_t bf[4][2];
                #pragma unroll
                for (int ntp = 0; ntp < 2; ntp++) {
                    uint32_t q0, q1, q2, q3;
                    LDMX4(q0, q1, q2, q3,
                          Bb + (jh + ntp*16 + brow)*FA_QSTR + (k*16 + bcol)*2);
                    bf[2*ntp][0] = q0;   bf[2*ntp][1] = q1;
                    bf[2*ntp+1][0] = q2; bf[2*ntp+1][1] = q3;
                }
                #pragma unroll
                for (int nt = 0; nt < 4; nt++)
                    MMA_BF16(s[nt], a, bf[nt]);
            }
        }

        // ---- online softmax (pair-shared max via smem)
        float mx0 = -1e30f, mx1 = -1e30f;
        #pragma unroll
        for (int nt = 0; nt < 4; nt++) {
            mx0 = fmaxf(mx0, fmaxf(s[nt][0], s[nt][1]));
            mx1 = fmaxf(mx1, fmaxf(s[nt][2], s[nt][3]));
        }
        mx0 = fmaxf(mx0, __shfl_xor_sync(0xffffffffu, mx0, 1));
        mx0 = fmaxf(mx0, __shfl_xor_sync(0xffffffffu, mx0, 2));
        mx1 = fmaxf(mx1, __shfl_xor_sync(0xffffffffu, mx1, 1));
        mx1 = fmaxf(mx1, __shfl_xor_sync(0xffffffffu, mx1, 2));
        if (qgrp == 0) {
            hm[lr*2 + half]     = mx0;
            hm[(lr+8)*2 + half] = mx1;
        }
        __syncthreads();
        float mn0 = fmaxf(m0, fmaxf(hm[lr*2],     hm[lr*2 + 1]));
        float mn1 = fmaxf(m1, fmaxf(hm[(lr+8)*2], hm[(lr+8)*2 + 1]));
        float al0 = exp2f(m0 - mn0), al1 = exp2f(m1 - mn1);
        m0 = mn0; m1 = mn1;
        float rs0 = 0.f, rs1 = 0.f;
        #pragma unroll
        for (int nt = 0; nt < 4; nt++) {
            s[nt][0] = exp2f(s[nt][0] - m0);
            s[nt][1] = exp2f(s[nt][1] - m0);
            s[nt][2] = exp2f(s[nt][2] - m1);
            s[nt][3] = exp2f(s[nt][3] - m1);
            rs0 += s[nt][0] + s[nt][1];
            rs1 += s[nt][2] + s[nt][3];
        }
        rs0 += __shfl_xor_sync(0xffffffffu, rs0, 1);
        rs0 += __shfl_xor_sync(0xffffffffu, rs0, 2);
        rs1 += __shfl_xor_sync(0xffffffffu, rs1, 1);
        rs1 += __shfl_xor_sync(0xffffffffu, rs1, 2);
        l0 = l0*al0 + rs0;
        l1 = l1*al1 + rs1;
        #pragma unroll
        for (int nt = 0; nt < 16; nt++) {
            acc[nt][0] *= al0; acc[nt][1] *= al0;
            acc[nt][2] *= al1; acc[nt][3] *= al1;
        }

        // ---- P -> bf16 hi/lo A-fragments in registers
        uint32_t ah[2][4], av[2][4];
        #pragma unroll
        for (int kb = 0; kb < 2; kb++) {
            int tA = 2*kb, tB = 2*kb + 1;
            split_pack(s[tA][0], s[tA][1], ah[kb][0], av[kb][0]);
            split_pack(s[tA][2], s[tA][3], ah[kb][1], av[kb][1]);
            split_pack(s[tB][0], s[tB][1], ah[kb][2], av[kb][2]);
            split_pack(s[tB][2], s[tB][3], ah[kb][3], av[kb][3]);
        }

        // ---- PV: acc += P @ V^T (3-pass split), k = this warp's j-half
        #pragma unroll
        for (int pass = 0; pass < 3; pass++) {
            uint32_t Bb = base + ((pass == 1) ? FA_VL : FA_VH);
            #pragma unroll
            for (int kb = 0; kb < 2; kb++) {
                const uint32_t* A = (pass == 2) ? av[kb] : ah[kb];
                int kc = jh + kb*16;
                uint32_t bf2[16][2];
                #pragma unroll
                for (int ntp = 0; ntp < 8; ntp++) {
                    uint32_t q0, q1, q2, q3;
                    LDMX4(q0, q1, q2, q3,
                          Bb + (ntp*16 + brow)*FA_VSTR + (kc + bcol)*2);
                    bf2[2*ntp][0] = q0;   bf2[2*ntp][1] = q1;
                    bf2[2*ntp+1][0] = q2; bf2[2*ntp+1][1] = q3;
                }
                #pragma unroll
                for (int nt = 0; nt < 16; nt++)
                    MMA_BF16(acc[nt], A, bf2[nt]);
            }
        }
        __syncthreads();
    }

    // ---- epilogue: merge j-half partials, normalize, store
    if (qgrp == 0) {
        ls[lr*2 + half]     = l0;
        ls[(lr+8)*2 + half] = l1;
    }
    float* Hred = (float*)(smem + FA_BUF0);
    if (half) {
        #pragma unroll
        for (int nt = 0; nt < 16; nt++) {
            Hred[lr*128 + nt*8 + qgrp*2]         = acc[nt][0];
            Hred[lr*128 + nt*8 + qgrp*2 + 1]     = acc[nt][1];
            Hred[(lr+8)*128 + nt*8 + qgrp*2]     = acc[nt][2];
            Hred[(lr+8)*128 + nt*8 + qgrp*2 + 1] = acc[nt][3];
        }
    }
    __syncthreads();
    if (!half) {
        float inv0 = 1.f / (ls[lr*2]     + ls[lr*2 + 1]);
        float inv1 = 1.f / (ls[(lr+8)*2] + ls[(lr+8)*2 + 1]);
        float* H = g_hT + (size_t)b*NV*CC;
        #pragma unroll
        for (int nt = 0; nt < 16; nt++) {
            float h0 = (acc[nt][0] + Hred[lr*128 + nt*8 + qgrp*2])         * inv0;
            float h1 = (acc[nt][1] + Hred[lr*128 + nt*8 + qgrp*2 + 1])     * inv0;
            float h2 = (acc[nt][2] + Hred[(lr+8)*128 + nt*8 + qgrp*2])     * inv1;
            float h3 = (acc[nt][3] + Hred[(lr+8)*128 + nt*8 + qgrp*2 + 1]) * inv1;
            *(float2*)(H + (size_t)(i0 + lr)*CC + nt*8 + qgrp*2)     = make_float2(h0, h1);
            *(float2*)(H + (size_t)(i0 + lr + 8)*CC + nt*8 + qgrp*2) = make_float2(h2, h3);
        }
    }
}

// ---------------- 7) output projection + residual ---------------
__global__ void proj_kernel(const float* __restrict__ inp,
                            const float* __restrict__ Wo,
                            const float* __restrict__ bo,
                            float* __restrict__ outp)
{
    extern __shared__ float sm[];
    float* Ws = sm;
    float* xs = sm + CC*CC;
    int b = blockIdx.y;
    int n0 = blockIdx.x * 64;
    int tid = threadIdx.x;

    for (int i = tid; i < CC*CC/4; i += 256) {
        int o  = i >> 5;
        int c4 = (i & 31) << 2;
        float4 w = *(const float4*)(Wo + o*CC + c4);
        Ws[(c4+0)*CC + o] = w.x;
        Ws[(c4+1)*CC + o] = w.y;
        Ws[(c4+2)*CC + o] = w.z;
        Ws[(c4+3)*CC + o] = w.w;
    }
    const float* hsrc = g_hT + (size_t)b*NV*CC;
    for (int i = tid; i < 64*32; i += 256) {
        int j  = i >> 5;
        int c4 = (i & 31) << 2;
        float4 h4 = *(const float4*)(hsrc + (size_t)(n0 + j)*CC + c4);
        xs[(c4+0)*64 + j] = h4.x;
        xs[(c4+1)*64 + j] = h4.y;
        xs[(c4+2)*64 + j] = h4.z;
        xs[(c4+3)*64 + j] = h4.w;
    }
    __syncthreads();

    int oy = tid >> 4;
    int nx = tid & 15;
    float acc[8][4];
    #pragma unroll
    for (int u = 0; u < 8; u++)
        #pragma unroll
        for (int v = 0; v < 4; v++) acc[u][v] = 0.f;

    #pragma unroll 4
    for (int c = 0; c < CC; c++) {
        float4 w0 = *(float4*)(Ws + c*CC + oy*8);
        float4 w1 = *(float4*)(Ws + c*CC + oy*8 + 4);
        float4 x4 = *(float4*)(xs + c*64 + nx*4);
        float wv[8] = {w0.x, w0.y, w0.z, w0.w, w1.x, w1.y, w1.z, w1.w};
        float xv[4] = {x4.x, x4.y, x4.z, x4.w};
        #pragma unroll
        for (int u = 0; u < 8; u++)
            #pragma unroll
            for (int v = 0; v < 4; v++) acc[u][v] += wv[u] * xv[v];
    }

    #pragma unroll
    for (int u = 0; u < 8; u++) {
        int o = oy*8 + u;
        float bias = bo[o];
        float4 r0 = *(const float4*)(inp + ((size_t)b*CC + o)*NV + n0 + nx*4);
        float4 r = make_float4(acc[u][0] + bias + r0.x,
                               acc[u][1] + bias + r0.y,
                               acc[u][2] + bias + r0.z,
                               acc[u][3] + bias + r0.w);
        *(float4*)(outp + ((size_t)b*CC + o)*NV + n0 + nx*4) = r;
    }
}

// ---------------- launch ----------------------------------------
extern "C" void kernel_launch(void* const* d_in, const int* in_sizes, int n_in,
                              void* d_out, int out_size)
{
    const float* inp   = (const float*)d_in[0];
    const float* gamma = (const float*)d_in[1];
    const float* beta  = (const float*)d_in[2];
    const float* Wq    = (const float*)d_in[3];
    const float* bq    = (const float*)d_in[4];
    const float* Wk    = (const float*)d_in[5];
    const float* bk    = (const float*)d_in[6];
    const float* Wv    = (const float*)d_in[7];
    const float* bv    = (const float*)d_in[8];
    const float* Wo    = (const float*)d_in[9];
    const float* bo    = (const float*)d_in[10];
    float* outp = (float*)d_out;

    int gemm_smem = (CC*CC + CC*64) * (int)sizeof(float);   // 96 KB
    cudaFuncSetAttribute(qkv_kernel,   cudaFuncAttributeMaxDynamicSharedMemorySize, gemm_smem);
    cudaFuncSetAttribute(proj_kernel,  cudaFuncAttributeMaxDynamicSharedMemorySize, gemm_smem);
    cudaFuncSetAttribute(fattn_kernel, cudaFuncAttributeMaxDynamicSharedMemorySize, FA_SMEM);

    stats_kernel<<<CC, 256>>>(inp, gamma, beta);
    fold_kernel<<<3*CC, CC>>>(Wq, bq, Wk, bk, Wv, bv);
    qkv_kernel<<<dim3(NV/64, 3, NB), 256, gemm_smem>>>(inp);
    transsplit_kernel<<<dim3(NV/32, CC/32, 2*NB), dim3(32, 8)>>>();
    vsplit_kernel<<<(NB*CC*NV)/1024, 256>>>();
    fattn_kernel<<<dim3(NV/64, NB), 256, FA_SMEM>>>();
    proj_kernel<<<dim3(NV/64, NB), 256, gemm_smem>>>(inp, Wo, bo, outp);
}

// round 10
// speedup vs baseline: 5.0438x; 1.1074x over previous
#include <cuda_runtime.h>
#include <cuda_bf16.h>
#include <math.h>
#include <stdint.h>

#define CC   128
#define NV   4096
#define NB   2
#define EPSF 1e-5f

// ---------------- scratch (no allocation allowed) ----------------
__device__ float g_a[CC];
__device__ float g_dd[CC];
__device__ float g_Wq[CC*CC];
__device__ float g_Wk[CC*CC];
__device__ float g_Wv[CC*CC];
__device__ float g_bq[CC];
__device__ float g_bk[CC];
__device__ float g_bv[CC];
__device__ float g_hT[NB*NV*CC];          // attention out, [b][i][c]
__device__ __nv_bfloat16 g_qTh[NB*NV*CC]; // q^T split hi/lo, [b][i][c]
__device__ __nv_bfloat16 g_qTl[NB*NV*CC];
__device__ __nv_bfloat16 g_kTh[NB*NV*CC];
__device__ __nv_bfloat16 g_kTl[NB*NV*CC];
__device__ __nv_bfloat16 g_vh[NB*CC*NV];  // v split, natural [b][c][n]
__device__ __nv_bfloat16 g_vl[NB*CC*NV];

// ---------------- PTX helpers (compute_80-era only!) -------------
__device__ __forceinline__ uint32_t smem_u32(const void* p) {
    uint32_t a;
    asm("{ .reg .u64 t; cvta.to.shared.u64 t, %1; cvt.u32.u64 %0, t; }"
        : "=r"(a) : "l"(p));
    return a;
}
#define LDMX4(r0,r1,r2,r3,addr) \
    asm volatile("ldmatrix.sync.aligned.m8n8.x4.shared.b16 {%0,%1,%2,%3}, [%4];" \
                 : "=r"(r0),"=r"(r1),"=r"(r2),"=r"(r3) : "r"(addr))
#define MMA_BF16(c,a,b) \
    asm volatile("mma.sync.aligned.m16n8k16.row.col.f32.bf16.bf16.f32 " \
                 "{%0,%1,%2,%3}, {%4,%5,%6,%7}, {%8,%9}, {%0,%1,%2,%3};" \
                 : "+f"((c)[0]),"+f"((c)[1]),"+f"((c)[2]),"+f"((c)[3]) \
                 : "r"((a)[0]),"r"((a)[1]),"r"((a)[2]),"r"((a)[3]), \
                   "r"((b)[0]),"r"((b)[1]))
#define CP_ASYNC16(s,g) \
    asm volatile("cp.async.cg.shared.global [%0], [%1], 16;" :: "r"(s), "l"(g) : "memory")
#define CP_COMMIT()  asm volatile("cp.async.commit_group;" ::: "memory")
#define CP_WAIT1()   asm volatile("cp.async.wait_group 1;" ::: "memory")
#define CP_WAIT0()   asm volatile("cp.async.wait_group 0;" ::: "memory")

__device__ __forceinline__ uint32_t pack_bf2(float a, float b) {
    __nv_bfloat162 t = __floats2bfloat162_rn(a, b);
    return *reinterpret_cast<uint32_t*>(&t);
}
__device__ __forceinline__ void split_pack(float a, float b, uint32_t& hi, uint32_t& lo) {
    __nv_bfloat16 ha = __float2bfloat16(a), hb = __float2bfloat16(b);
    __nv_bfloat162 H; H.x = ha; H.y = hb;
    hi = *reinterpret_cast<uint32_t*>(&H);
    lo = pack_bf2(a - __bfloat162float(ha), b - __bfloat162float(hb));
}

// ---------------- 1) per-channel batch stats --------------------
__global__ void stats_kernel(const float* __restrict__ inp,
                             const float* __restrict__ gamma,
                             const float* __restrict__ beta)
{
    int c = blockIdx.x;
    int tid = threadIdx.x;
    const float* p0 = inp + c * NV;
    const float* p1 = inp + (CC + c) * NV;
    float s = 0.f, ss = 0.f;
    for (int n = tid * 4; n < NV; n += 256 * 4) {
        float4 a = *(const float4*)(p0 + n);
        float4 b = *(const float4*)(p1 + n);
        s  += a.x + a.y + a.z + a.w + b.x + b.y + b.z + b.w;
        ss += a.x*a.x + a.y*a.y + a.z*a.z + a.w*a.w
            + b.x*b.x + b.y*b.y + b.z*b.z + b.w*b.w;
    }
    #pragma unroll
    for (int off = 16; off; off >>= 1) {
        s  += __shfl_xor_sync(0xffffffffu, s, off);
        ss += __shfl_xor_sync(0xffffffffu, ss, off);
    }
    __shared__ float sb[8], ssb[8];
    int w = tid >> 5;
    if ((tid & 31) == 0) { sb[w] = s; ssb[w] = ss; }
    __syncthreads();
    if (tid == 0) {
        float ts = 0.f, tss = 0.f;
        #pragma unroll
        for (int i = 0; i < 8; i++) { ts += sb[i]; tss += ssb[i]; }
        const float inv = 1.f / (float)(NB * NV);
        float mean = ts * inv;
        float var  = tss * inv - mean * mean;
        float a = gamma[c] * rsqrtf(var + EPSF);
        g_a[c]  = a;
        g_dd[c] = beta[c] - mean * a;
    }
}

// ---------------- 2) fold BN (+ q scale + log2e) into weights ---
__global__ void fold_kernel(const float* __restrict__ Wq, const float* __restrict__ bq,
                            const float* __restrict__ Wk, const float* __restrict__ bk,
                            const float* __restrict__ Wv, const float* __restrict__ bv)
{
    int m = blockIdx.x >> 7;
    int o = blockIdx.x & 127;
    int c = threadIdx.x;
    const float QSC = 1.44269504088896341f * 0.0883883476483184406f;
    const float* W; const float* bs; float* Wd; float* bd; float sc;
    if (m == 0)      { W = Wq; bs = bq; Wd = g_Wq; bd = g_bq; sc = QSC; }
    else if (m == 1) { W = Wk; bs = bk; Wd = g_Wk; bd = g_bk; sc = 1.f; }
    else             { W = Wv; bs = bv; Wd = g_Wv; bd = g_bv; sc = 1.f; }
    float w = W[o*CC + c];
    Wd[o*CC + c] = w * g_a[c] * sc;
    float part = w * g_dd[c];
    #pragma unroll
    for (int off = 16; off; off >>= 1)
        part += __shfl_xor_sync(0xffffffffu, part, off);
    __shared__ float pb[4];
    if ((c & 31) == 0) pb[c >> 5] = part;
    __syncthreads();
    if (c == 0) bd[o] = (bs[o] + pb[0] + pb[1] + pb[2] + pb[3]) * sc;
}

// ---------------- 3) QKV GEMM + split (+transpose for q,k) -----
__global__ void qkv_kernel(const float* __restrict__ inp)
{
    extern __shared__ float sm[];
    float* Ws = sm;
    float* xs = sm + CC*CC;
    int m = blockIdx.y, b = blockIdx.z;
    int n0 = blockIdx.x * 64;
    const float* W  = (m == 0) ? g_Wq : (m == 1) ? g_Wk : g_Wv;
    const float* bb = (m == 0) ? g_bq : (m == 1) ? g_bk : g_bv;
    int tid = threadIdx.x;

    for (int i = tid; i < CC*CC/4; i += 256) {
        int o  = i >> 5;
        int c4 = (i & 31) << 2;
        float4 w = *(const float4*)(W + o*CC + c4);
        Ws[(c4+0)*CC + o] = w.x;
        Ws[(c4+1)*CC + o] = w.y;
        Ws[(c4+2)*CC + o] = w.z;
        Ws[(c4+3)*CC + o] = w.w;
    }
    for (int i = tid; i < CC*16; i += 256) {
        int c  = i >> 4;
        int j4 = (i & 15) << 2;
        *(float4*)(xs + c*64 + j4) =
            *(const float4*)(inp + ((size_t)b*CC + c)*NV + n0 + j4);
    }
    __syncthreads();

    int oy = tid >> 4;
    int nx = tid & 15;
    float acc[8][4];
    #pragma unroll
    for (int u = 0; u < 8; u++)
        #pragma unroll
        for (int v = 0; v < 4; v++) acc[u][v] = 0.f;

    #pragma unroll 4
    for (int c = 0; c < CC; c++) {
        float4 w0 = *(float4*)(Ws + c*CC + oy*8);
        float4 w1 = *(float4*)(Ws + c*CC + oy*8 + 4);
        float4 x4 = *(float4*)(xs + c*64 + nx*4);
        float wv[8] = {w0.x, w0.y, w0.z, w0.w, w1.x, w1.y, w1.z, w1.w};
        float xv[4] = {x4.x, x4.y, x4.z, x4.w};
        #pragma unroll
        for (int u = 0; u < 8; u++)
            #pragma unroll
            for (int v = 0; v < 4; v++) acc[u][v] += wv[u] * xv[v];
    }

    #pragma unroll
    for (int u = 0; u < 8; u++) {
        float bias = bb[oy*8 + u];
        #pragma unroll
        for (int v = 0; v < 4; v++) acc[u][v] += bias;
    }

    if (m < 2) {
        // transposed + split: [b][i][c] hi/lo, 16B stores of 8 channels
        __nv_bfloat16* dh = (m == 0 ? g_qTh : g_kTh) + (size_t)b*NV*CC;
        __nv_bfloat16* dl = (m == 0 ? g_qTl : g_kTl) + (size_t)b*NV*CC;
        #pragma unroll
        for (int v = 0; v < 4; v++) {
            int i = n0 + nx*4 + v;
            uint32_t hi[4], lo[4];
            #pragma unroll
            for (int p = 0; p < 4; p++)
                split_pack(acc[2*p][v], acc[2*p+1][v], hi[p], lo[p]);
            *(uint4*)(dh + (size_t)i*CC + oy*8) = make_uint4(hi[0], hi[1], hi[2], hi[3]);
            *(uint4*)(dl + (size_t)i*CC + oy*8) = make_uint4(lo[0], lo[1], lo[2], lo[3]);
        }
    } else {
        // natural + split: [b][c][n] hi/lo, 8B stores of 4 n
        __nv_bfloat16* dh = g_vh + (size_t)b*CC*NV;
        __nv_bfloat16* dl = g_vl + (size_t)b*CC*NV;
        #pragma unroll
        for (int u = 0; u < 8; u++) {
            int c = oy*8 + u;
            uint32_t h0, l0, h1, l1;
            split_pack(acc[u][0], acc[u][1], h0, l0);
            split_pack(acc[u][2], acc[u][3], h1, l1);
            *(uint2*)(dh + (size_t)c*NV + n0 + nx*4) = make_uint2(h0, h1);
            *(uint2*)(dl + (size_t)c*NV + n0 + nx*4) = make_uint2(l0, l1);
        }
    }
}

// ---------------- 4) fused flash attention (HMMA, split x3) -----
// grid (NV/64, NB), 256 thr = 8 warps.
// warp w: i-rows [(w&3)*16, +16), j-half (w>>2)*32 of each 64-j chunk.
// Q hi/lo fragments hoisted to registers; B_hi fragments shared
// between the hi*hi and lo*hi passes. K/V chunk tiles double-buffered.
#define FA_QSTR 272
#define FA_VSTR 144
#define FA_QL   17408
#define FA_BUF0 34816
#define FA_KL   17408
#define FA_VH   34816
#define FA_VL   53248
#define FA_BUFSZ 71680
#define FA_HM   178176
#define FA_LS   178688
#define FA_SMEM 179200

__global__ void __launch_bounds__(256, 1) fattn_kernel()
{
    extern __shared__ char smem[];
    uint32_t sb = smem_u32(smem);
    int tid = threadIdx.x, wid = tid >> 5, lane = tid & 31;
    int b = blockIdx.y, i0 = blockIdx.x * 64;

    const __nv_bfloat16* Qh = g_qTh + (size_t)b*NV*CC + (size_t)i0*CC;
    const __nv_bfloat16* Ql = g_qTl + (size_t)b*NV*CC + (size_t)i0*CC;
    const __nv_bfloat16* Kh = g_kTh + (size_t)b*NV*CC;
    const __nv_bfloat16* Kl = g_kTl + (size_t)b*NV*CC;
    const __nv_bfloat16* Vh = g_vh  + (size_t)b*CC*NV;
    const __nv_bfloat16* Vl = g_vl  + (size_t)b*CC*NV;

    // ---- prologue: Q tiles (group 0), chunk 0 (group 1)
    for (int idx = tid; idx < 1024; idx += 256) {
        int row = idx >> 4, c = idx & 15;
        uint32_t so = sb + row*FA_QSTR + c*16;
        size_t go = (size_t)row*CC + c*8;
        CP_ASYNC16(so, Qh + go);
        CP_ASYNC16(so + FA_QL, Ql + go);
    }
    CP_COMMIT();
    {
        uint32_t base = sb + FA_BUF0;
        for (int idx = tid; idx < 1024; idx += 256) {
            int row = idx >> 4, c = idx & 15;
            uint32_t so = base + row*FA_QSTR + c*16;
            size_t go = (size_t)row*CC + c*8;
            CP_ASYNC16(so, Kh + go);
            CP_ASYNC16(so + FA_KL, Kl + go);
        }
        for (int idx = tid; idx < 1024; idx += 256) {
            int row = idx >> 3, c = idx & 7;
            uint32_t so = base + FA_VH + row*FA_VSTR + c*16;
            size_t go = (size_t)row*NV + c*8;
            CP_ASYNC16(so, Vh + go);
            CP_ASYNC16(so + (FA_VL - FA_VH), Vl + go);
        }
        CP_COMMIT();
    }

    int ig = (wid & 3) * 16;
    int jh = (wid >> 2) * 32;
    int half = jh >> 5;
    int arow = lane & 15, acol = (lane >> 4) << 3;
    int bm = lane >> 3;
    int brow = ((bm >> 1) << 3) + (lane & 7);
    int bcol = (bm & 1) << 3;
    int qgrp = lane & 3;
    int lr = ig + (lane >> 2);

    // ---- wait for Q (group 1 may still be in flight), hoist Q frags
    CP_WAIT1();
    __syncthreads();
    uint32_t qh[8][4], ql[8][4];
    #pragma unroll
    for (int k = 0; k < 8; k++) {
        uint32_t ad = sb + (ig + arow)*FA_QSTR + (k*16 + acol)*2;
        LDMX4(qh[k][0], qh[k][1], qh[k][2], qh[k][3], ad);
        LDMX4(ql[k][0], ql[k][1], ql[k][2], ql[k][3], ad + FA_QL);
    }

    float acc[16][4];
    #pragma unroll
    for (int nt = 0; nt < 16; nt++)
        #pragma unroll
        for (int e = 0; e < 4; e++) acc[nt][e] = 0.f;
    float l0 = 0.f, l1 = 0.f, m0 = -1e30f, m1 = -1e30f;

    float* hm = (float*)(smem + FA_HM);
    float* ls = (float*)(smem + FA_LS);

    for (int t = 0; t < 64; t++) {
        uint32_t base = sb + FA_BUF0 + (uint32_t)(t & 1)*FA_BUFSZ;
        if (t + 1 < 64) {
            uint32_t nb = sb + FA_BUF0 + (uint32_t)((t + 1) & 1)*FA_BUFSZ;
            int j0 = (t + 1) * 64;
            for (int idx = tid; idx < 1024; idx += 256) {
                int row = idx >> 4, c = idx & 15;
                uint32_t so = nb + row*FA_QSTR + c*16;
                size_t go = (size_t)(j0 + row)*CC + c*8;
                CP_ASYNC16(so, Kh + go);
                CP_ASYNC16(so + FA_KL, Kl + go);
            }
            for (int idx = tid; idx < 1024; idx += 256) {
                int row = idx >> 3, c = idx & 7;
                uint32_t so = nb + FA_VH + row*FA_VSTR + c*16;
                size_t go = (size_t)row*NV + j0 + c*8;
                CP_ASYNC16(so, Vh + go);
                CP_ASYNC16(so + (FA_VL - FA_VH), Vl + go);
            }
            CP_COMMIT();
            CP_WAIT1();
        } else {
            CP_WAIT0();
        }
        __syncthreads();

        // ---- QK: S (16 x 32); K_hi frags reused by Qh and Ql passes
        float s[4][4];
        #pragma unroll
        for (int nt = 0; nt < 4; nt++)
            #pragma unroll
            for (int e = 0; e < 4; e++) s[nt][e] = 0.f;
        #pragma unroll
        for (int k = 0; k < 8; k++) {
            uint32_t bh[4][2], bl[4][2];
            #pragma unroll
            for (int ntp = 0; ntp < 2; ntp++) {
                uint32_t ad = base + (jh + ntp*16 + brow)*FA_QSTR + (k*16 + bcol)*2;
                uint32_t q0, q1, q2, q3;
                LDMX4(q0, q1, q2, q3, ad);
                bh[2*ntp][0] = q0;   bh[2*ntp][1] = q1;
                bh[2*ntp+1][0] = q2; bh[2*ntp+1][1] = q3;
                LDMX4(q0, q1, q2, q3, ad + FA_KL);
                bl[2*ntp][0] = q0;   bl[2*ntp][1] = q1;
                bl[2*ntp+1][0] = q2; bl[2*ntp+1][1] = q3;
            }
            #pragma unroll
            for (int nt = 0; nt < 4; nt++) {
                MMA_BF16(s[nt], qh[k], bh[nt]);   // hi*hi
                MMA_BF16(s[nt], ql[k], bh[nt]);   // lo*hi
                MMA_BF16(s[nt], qh[k], bl[nt]);   // hi*lo
            }
        }

        // ---- online softmax (pair-shared max via smem)
        float mx0 = -1e30f, mx1 = -1e30f;
        #pragma unroll
        for (int nt = 0; nt < 4; nt++) {
            mx0 = fmaxf(mx0, fmaxf(s[nt][0], s[nt][1]));
            mx1 = fmaxf(mx1, fmaxf(s[nt][2], s[nt][3]));
        }
        mx0 = fmaxf(mx0, __shfl_xor_sync(0xffffffffu, mx0, 1));
        mx0 = fmaxf(mx0, __shfl_xor_sync(0xffffffffu, mx0, 2));
        mx1 = fmaxf(mx1, __shfl_xor_sync(0xffffffffu, mx1, 1));
        mx1 = fmaxf(mx1, __shfl_xor_sync(0xffffffffu, mx1, 2));
        if (qgrp == 0) {
            hm[lr*2 + half]     = mx0;
            hm[(lr+8)*2 + half] = mx1;
        }
        __syncthreads();
        float mn0 = fmaxf(m0, fmaxf(hm[lr*2],     hm[lr*2 + 1]));
        float mn1 = fmaxf(m1, fmaxf(hm[(lr+8)*2], hm[(lr+8)*2 + 1]));
        float al0 = exp2f(m0 - mn0), al1 = exp2f(m1 - mn1);
        m0 = mn0; m1 = mn1;
        float rs0 = 0.f, rs1 = 0.f;
        #pragma unroll
        for (int nt = 0; nt < 4; nt++) {
            s[nt][0] = exp2f(s[nt][0] - m0);
            s[nt][1] = exp2f(s[nt][1] - m0);
            s[nt][2] = exp2f(s[nt][2] - m1);
            s[nt][3] = exp2f(s[nt][3] - m1);
            rs0 += s[nt][0] + s[nt][1];
            rs1 += s[nt][2] + s[nt][3];
        }
        rs0 += __shfl_xor_sync(0xffffffffu, rs0, 1);
        rs0 += __shfl_xor_sync(0xffffffffu, rs0, 2);
        rs1 += __shfl_xor_sync(0xffffffffu, rs1, 1);
        rs1 += __shfl_xor_sync(0xffffffffu, rs1, 2);
        l0 = l0*al0 + rs0;
        l1 = l1*al1 + rs1;
        #pragma unroll
        for (int nt = 0; nt < 16; nt++) {
            acc[nt][0] *= al0; acc[nt][1] *= al0;
            acc[nt][2] *= al1; acc[nt][3] *= al1;
        }

        // ---- P -> bf16 hi/lo A-fragments in registers
        uint32_t ah[2][4], av[2][4];
        #pragma unroll
        for (int kb = 0; kb < 2; kb++) {
            int tA = 2*kb, tB = 2*kb + 1;
            split_pack(s[tA][0], s[tA][1], ah[kb][0], av[kb][0]);
            split_pack(s[tA][2], s[tA][3], ah[kb][1], av[kb][1]);
            split_pack(s[tB][0], s[tB][1], ah[kb][2], av[kb][2]);
            split_pack(s[tB][2], s[tB][3], ah[kb][3], av[kb][3]);
        }

        // ---- PV: acc += P @ V^T; V_hi frags reused by Ph and Pl
        #pragma unroll
        for (int kb = 0; kb < 2; kb++) {
            int kc = jh + kb*16;
            uint32_t bf2[16][2];
            #pragma unroll
            for (int ntp = 0; ntp < 8; ntp++) {
                uint32_t q0, q1, q2, q3;
                LDMX4(q0, q1, q2, q3,
                      base + FA_VH + (ntp*16 + brow)*FA_VSTR + (kc + bcol)*2);
                bf2[2*ntp][0] = q0;   bf2[2*ntp][1] = q1;
                bf2[2*ntp+1][0] = q2; bf2[2*ntp+1][1] = q3;
            }
            #pragma unroll
            for (int nt = 0; nt < 16; nt++) {
                MMA_BF16(acc[nt], ah[kb], bf2[nt]);   // hi*hi
                MMA_BF16(acc[nt], av[kb], bf2[nt]);   // lo*hi
            }
            #pragma unroll
            for (int ntp = 0; ntp < 8; ntp++) {
                uint32_t q0, q1, q2, q3;
                LDMX4(q0, q1, q2, q3,
                      base + FA_VL + (ntp*16 + brow)*FA_VSTR + (kc + bcol)*2);
                bf2[2*ntp][0] = q0;   bf2[2*ntp][1] = q1;
                bf2[2*ntp+1][0] = q2; bf2[2*ntp+1][1] = q3;
            }
            #pragma unroll
            for (int nt = 0; nt < 16; nt++)
                MMA_BF16(acc[nt], ah[kb], bf2[nt]);   // hi*lo
        }
        __syncthreads();
    }

    // ---- epilogue: merge j-half partials, normalize, store
    if (qgrp == 0) {
        ls[lr*2 + half]     = l0;
        ls[(lr+8)*2 + half] = l1;
    }
    float* Hred = (float*)(smem + FA_BUF0);
    if (half) {
        #pragma unroll
        for (int nt = 0; nt < 16; nt++) {
            Hred[lr*128 + nt*8 + qgrp*2]         = acc[nt][0];
            Hred[lr*128 + nt*8 + qgrp*2 + 1]     = acc[nt][1];
            Hred[(lr+8)*128 + nt*8 + qgrp*2]     = acc[nt][2];
            Hred[(lr+8)*128 + nt*8 + qgrp*2 + 1] = acc[nt][3];
        }
    }
    __syncthreads();
    if (!half) {
        float inv0 = 1.f / (ls[lr*2]     + ls[lr*2 + 1]);
        float inv1 = 1.f / (ls[(lr+8)*2] + ls[(lr+8)*2 + 1]);
        float* H = g_hT + (size_t)b*NV*CC;
        #pragma unroll
        for (int nt = 0; nt < 16; nt++) {
            float h0 = (acc[nt][0] + Hred[lr*128 + nt*8 + qgrp*2])         * inv0;
            float h1 = (acc[nt][1] + Hred[lr*128 + nt*8 + qgrp*2 + 1])     * inv0;
            float h2 = (acc[nt][2] + Hred[(lr+8)*128 + nt*8 + qgrp*2])     * inv1;
            float h3 = (acc[nt][3] + Hred[(lr+8)*128 + nt*8 + qgrp*2 + 1]) * inv1;
            *(float2*)(H + (size_t)(i0 + lr)*CC + nt*8 + qgrp*2)     = make_float2(h0, h1);
            *(float2*)(H + (size_t)(i0 + lr + 8)*CC + nt*8 + qgrp*2) = make_float2(h2, h3);
        }
    }
}

// ---------------- 5) output projection + residual ---------------
__global__ void proj_kernel(const float* __restrict__ inp,
                            const float* __restrict__ Wo,
                            const float* __restrict__ bo,
                            float* __restrict__ outp)
{
    extern __shared__ float sm[];
    float* Ws = sm;
    float* xs = sm + CC*CC;
    int b = blockIdx.y;
    int n0 = blockIdx.x * 64;
    int tid = threadIdx.x;

    for (int i = tid; i < CC*CC/4; i += 256) {
        int o  = i >> 5;
        int c4 = (i & 31) << 2;
        float4 w = *(const float4*)(Wo + o*CC + c4);
        Ws[(c4+0)*CC + o] = w.x;
        Ws[(c4+1)*CC + o] = w.y;
        Ws[(c4+2)*CC + o] = w.z;
        Ws[(c4+3)*CC + o] = w.w;
    }
    const float* hsrc = g_hT + (size_t)b*NV*CC;
    for (int i = tid; i < 64*32; i += 256) {
        int j  = i >> 5;
        int c4 = (i & 31) << 2;
        float4 h4 = *(const float4*)(hsrc + (size_t)(n0 + j)*CC + c4);
        xs[(c4+0)*64 + j] = h4.x;
        xs[(c4+1)*64 + j] = h4.y;
        xs[(c4+2)*64 + j] = h4.z;
        xs[(c4+3)*64 + j] = h4.w;
    }
    __syncthreads();

    int oy = tid >> 4;
    int nx = tid & 15;
    float acc[8][4];
    #pragma unroll
    for (int u = 0; u < 8; u++)
        #pragma unroll
        for (int v = 0; v < 4; v++) acc[u][v] = 0.f;

    #pragma unroll 4
    for (int c = 0; c < CC; c++) {
        float4 w0 = *(float4*)(Ws + c*CC + oy*8);
        float4 w1 = *(float4*)(Ws + c*CC + oy*8 + 4);
        float4 x4 = *(float4*)(xs + c*64 + nx*4);
        float wv[8] = {w0.x, w0.y, w0.z, w0.w, w1.x, w1.y, w1.z, w1.w};
        float xv[4] = {x4.x, x4.y, x4.z, x4.w};
        #pragma unroll
        for (int u = 0; u < 8; u++)
            #pragma unroll
            for (int v = 0; v < 4; v++) acc[u][v] += wv[u] * xv[v];
    }

    #pragma unroll
    for (int u = 0; u < 8; u++) {
        int o = oy*8 + u;
        float bias = bo[o];
        float4 r0 = *(const float4*)(inp + ((size_t)b*CC + o)*NV + n0 + nx*4);
        float4 r = make_float4(acc[u][0] + bias + r0.x,
                               acc[u][1] + bias + r0.y,
                               acc[u][2] + bias + r0.z,
                               acc[u][3] + bias + r0.w);
        *(float4*)(outp + ((size_t)b*CC + o)*NV + n0 + nx*4) = r;
    }
}

// ---------------- launch ----------------------------------------
extern "C" void kernel_launch(void* const* d_in, const int* in_sizes, int n_in,
                              void* d_out, int out_size)
{
    const float* inp   = (const float*)d_in[0];
    const float* gamma = (const float*)d_in[1];
    const float* beta  = (const float*)d_in[2];
    const float* Wq    = (const float*)d_in[3];
    const float* bq    = (const float*)d_in[4];
    const float* Wk    = (const float*)d_in[5];
    const float* bk    = (const float*)d_in[6];
    const float* Wv    = (const float*)d_in[7];
    const float* bv    = (const float*)d_in[8];
    const float* Wo    = (const float*)d_in[9];
    const float* bo    = (const float*)d_in[10];
    float* outp = (float*)d_out;

    int gemm_smem = (CC*CC + CC*64) * (int)sizeof(float);   // 96 KB
    cudaFuncSetAttribute(qkv_kernel,   cudaFuncAttributeMaxDynamicSharedMemorySize, gemm_smem);
    cudaFuncSetAttribute(proj_kernel,  cudaFuncAttributeMaxDynamicSharedMemorySize, gemm_smem);
    cudaFuncSetAttribute(fattn_kernel, cudaFuncAttributeMaxDynamicSharedMemorySize, FA_SMEM);

    stats_kernel<<<CC, 256>>>(inp, gamma, beta);
    fold_kernel<<<3*CC, CC>>>(Wq, bq, Wk, bk, Wv, bv);
    qkv_kernel<<<dim3(NV/64, 3, NB), 256, gemm_smem>>>(inp);
    fattn_kernel<<<dim3(NV/64, NB), 256, FA_SMEM>>>();
    proj_kernel<<<dim3(NV/64, NB), 256, gemm_smem>>>(inp, Wo, bo, outp);
}

// round 11
// speedup vs baseline: 6.8196x; 1.3521x over previous
#include <cuda_runtime.h>
#include <cuda_fp16.h>
#include <math.h>
#include <stdint.h>

#define CC   128
#define NV   4096
#define NB   2
#define EPSF 1e-5f

// ---------------- scratch (no allocation allowed) ----------------
__device__ float g_a[CC];
__device__ float g_dd[CC];
__device__ float g_Wq[CC*CC];
__device__ float g_Wk[CC*CC];
__device__ float g_Wv[CC*CC];
__device__ float g_bq[CC];
__device__ float g_bk[CC];
__device__ float g_bv[CC];
__device__ float g_hT[NB*NV*CC];     // attention out, [b][i][c]
__device__ __half g_qTh[NB*NV*CC];   // q^T split hi/lo (fp16), [b][i][c]
__device__ __half g_qTl[NB*NV*CC];
__device__ __half g_kTh[NB*NV*CC];   // k^T fp16 (single), [b][i][c]
__device__ __half g_vh[NB*CC*NV];    // v fp16 (single), natural [b][c][n]

// ---------------- PTX helpers (compute_80-era only!) -------------
__device__ __forceinline__ uint32_t smem_u32(const void* p) {
    uint32_t a;
    asm("{ .reg .u64 t; cvta.to.shared.u64 t, %1; cvt.u32.u64 %0, t; }"
        : "=r"(a) : "l"(p));
    return a;
}
#define LDMX4(r0,r1,r2,r3,addr) \
    asm volatile("ldmatrix.sync.aligned.m8n8.x4.shared.b16 {%0,%1,%2,%3}, [%4];" \
                 : "=r"(r0),"=r"(r1),"=r"(r2),"=r"(r3) : "r"(addr))
#define MMA_F16(c,a,b) \
    asm volatile("mma.sync.aligned.m16n8k16.row.col.f32.f16.f16.f32 " \
                 "{%0,%1,%2,%3}, {%4,%5,%6,%7}, {%8,%9}, {%0,%1,%2,%3};" \
                 : "+f"((c)[0]),"+f"((c)[1]),"+f"((c)[2]),"+f"((c)[3]) \
                 : "r"((a)[0]),"r"((a)[1]),"r"((a)[2]),"r"((a)[3]), \
                   "r"((b)[0]),"r"((b)[1]))
#define CP_ASYNC16(s,g) \
    asm volatile("cp.async.cg.shared.global [%0], [%1], 16;" :: "r"(s), "l"(g) : "memory")
#define CP_COMMIT()  asm volatile("cp.async.commit_group;" ::: "memory")
#define CP_WAIT1()   asm volatile("cp.async.wait_group 1;" ::: "memory")
#define CP_WAIT0()   asm volatile("cp.async.wait_group 0;" ::: "memory")

__device__ __forceinline__ uint32_t pack_h2(float a, float b) {
    __half2 t = __floats2half2_rn(a, b);
    return *reinterpret_cast<uint32_t*>(&t);
}
__device__ __forceinline__ void split_pack_h(float a, float b, uint32_t& hi, uint32_t& lo) {
    __half ha = __float2half_rn(a), hb = __float2half_rn(b);
    __half2 H; H.x = ha; H.y = hb;
    hi = *reinterpret_cast<uint32_t*>(&H);
    lo = pack_h2(a - __half2float(ha), b - __half2float(hb));
}

// ---------------- 1) per-channel batch stats --------------------
__global__ void stats_kernel(const float* __restrict__ inp,
                             const float* __restrict__ gamma,
                             const float* __restrict__ beta)
{
    int c = blockIdx.x;
    int tid = threadIdx.x;
    const float* p0 = inp + c * NV;
    const float* p1 = inp + (CC + c) * NV;
    float s = 0.f, ss = 0.f;
    for (int n = tid * 4; n < NV; n += 256 * 4) {
        float4 a = *(const float4*)(p0 + n);
        float4 b = *(const float4*)(p1 + n);
        s  += a.x + a.y + a.z + a.w + b.x + b.y + b.z + b.w;
        ss += a.x*a.x + a.y*a.y + a.z*a.z + a.w*a.w
            + b.x*b.x + b.y*b.y + b.z*b.z + b.w*b.w;
    }
    #pragma unroll
    for (int off = 16; off; off >>= 1) {
        s  += __shfl_xor_sync(0xffffffffu, s, off);
        ss += __shfl_xor_sync(0xffffffffu, ss, off);
    }
    __shared__ float sb[8], ssb[8];
    int w = tid >> 5;
    if ((tid & 31) == 0) { sb[w] = s; ssb[w] = ss; }
    __syncthreads();
    if (tid == 0) {
        float ts = 0.f, tss = 0.f;
        #pragma unroll
        for (int i = 0; i < 8; i++) { ts += sb[i]; tss += ssb[i]; }
        const float inv = 1.f / (float)(NB * NV);
        float mean = ts * inv;
        float var  = tss * inv - mean * mean;
        float a = gamma[c] * rsqrtf(var + EPSF);
        g_a[c]  = a;
        g_dd[c] = beta[c] - mean * a;
    }
}

// ---------------- 2) fold BN (+ q scale + log2e) into weights ---
__global__ void fold_kernel(const float* __restrict__ Wq, const float* __restrict__ bq,
                            const float* __restrict__ Wk, const float* __restrict__ bk,
                            const float* __restrict__ Wv, const float* __restrict__ bv)
{
    int m = blockIdx.x >> 7;
    int o = blockIdx.x & 127;
    int c = threadIdx.x;
    const float QSC = 1.44269504088896341f * 0.0883883476483184406f;
    const float* W; const float* bs; float* Wd; float* bd; float sc;
    if (m == 0)      { W = Wq; bs = bq; Wd = g_Wq; bd = g_bq; sc = QSC; }
    else if (m == 1) { W = Wk; bs = bk; Wd = g_Wk; bd = g_bk; sc = 1.f; }
    else             { W = Wv; bs = bv; Wd = g_Wv; bd = g_bv; sc = 1.f; }
    float w = W[o*CC + c];
    Wd[o*CC + c] = w * g_a[c] * sc;
    float part = w * g_dd[c];
    #pragma unroll
    for (int off = 16; off; off >>= 1)
        part += __shfl_xor_sync(0xffffffffu, part, off);
    __shared__ float pb[4];
    if ((c & 31) == 0) pb[c >> 5] = part;
    __syncthreads();
    if (c == 0) bd[o] = (bs[o] + pb[0] + pb[1] + pb[2] + pb[3]) * sc;
}

// ---------------- 3) QKV GEMM + fp16 split/transpose ------------
__global__ void qkv_kernel(const float* __restrict__ inp)
{
    extern __shared__ float sm[];
    float* Ws = sm;
    float* xs = sm + CC*CC;
    int m = blockIdx.y, b = blockIdx.z;
    int n0 = blockIdx.x * 64;
    const float* W  = (m == 0) ? g_Wq : (m == 1) ? g_Wk : g_Wv;
    const float* bb = (m == 0) ? g_bq : (m == 1) ? g_bk : g_bv;
    int tid = threadIdx.x;

    for (int i = tid; i < CC*CC/4; i += 256) {
        int o  = i >> 5;
        int c4 = (i & 31) << 2;
        float4 w = *(const float4*)(W + o*CC + c4);
        Ws[(c4+0)*CC + o] = w.x;
        Ws[(c4+1)*CC + o] = w.y;
        Ws[(c4+2)*CC + o] = w.z;
        Ws[(c4+3)*CC + o] = w.w;
    }
    for (int i = tid; i < CC*16; i += 256) {
        int c  = i >> 4;
        int j4 = (i & 15) << 2;
        *(float4*)(xs + c*64 + j4) =
            *(const float4*)(inp + ((size_t)b*CC + c)*NV + n0 + j4);
    }
    __syncthreads();

    int oy = tid >> 4;
    int nx = tid & 15;
    float acc[8][4];
    #pragma unroll
    for (int u = 0; u < 8; u++)
        #pragma unroll
        for (int v = 0; v < 4; v++) acc[u][v] = 0.f;

    #pragma unroll 4
    for (int c = 0; c < CC; c++) {
        float4 w0 = *(float4*)(Ws + c*CC + oy*8);
        float4 w1 = *(float4*)(Ws + c*CC + oy*8 + 4);
        float4 x4 = *(float4*)(xs + c*64 + nx*4);
        float wv[8] = {w0.x, w0.y, w0.z, w0.w, w1.x, w1.y, w1.z, w1.w};
        float xv[4] = {x4.x, x4.y, x4.z, x4.w};
        #pragma unroll
        for (int u = 0; u < 8; u++)
            #pragma unroll
            for (int v = 0; v < 4; v++) acc[u][v] += wv[u] * xv[v];
    }

    #pragma unroll
    for (int u = 0; u < 8; u++) {
        float bias = bb[oy*8 + u];
        #pragma unroll
        for (int v = 0; v < 4; v++) acc[u][v] += bias;
    }

    if (m == 0) {
        // q: transposed + hi/lo split
        __half* dh = g_qTh + (size_t)b*NV*CC;
        __half* dl = g_qTl + (size_t)b*NV*CC;
        #pragma unroll
        for (int v = 0; v < 4; v++) {
            int i = n0 + nx*4 + v;
            uint32_t hi[4], lo[4];
            #pragma unroll
            for (int p = 0; p < 4; p++)
                split_pack_h(acc[2*p][v], acc[2*p+1][v], hi[p], lo[p]);
            *(uint4*)(dh + (size_t)i*CC + oy*8) = make_uint4(hi[0], hi[1], hi[2], hi[3]);
            *(uint4*)(dl + (size_t)i*CC + oy*8) = make_uint4(lo[0], lo[1], lo[2], lo[3]);
        }
    } else if (m == 1) {
        // k: transposed, single fp16
        __half* dh = g_kTh + (size_t)b*NV*CC;
        #pragma unroll
        for (int v = 0; v < 4; v++) {
            int i = n0 + nx*4 + v;
            uint32_t hi[4];
            #pragma unroll
            for (int p = 0; p < 4; p++)
                hi[p] = pack_h2(acc[2*p][v], acc[2*p+1][v]);
            *(uint4*)(dh + (size_t)i*CC + oy*8) = make_uint4(hi[0], hi[1], hi[2], hi[3]);
        }
    } else {
        // v: natural, single fp16
        __half* dh = g_vh + (size_t)b*CC*NV;
        #pragma unroll
        for (int u = 0; u < 8; u++) {
            int c = oy*8 + u;
            uint32_t h0 = pack_h2(acc[u][0], acc[u][1]);
            uint32_t h1 = pack_h2(acc[u][2], acc[u][3]);
            *(uint2*)(dh + (size_t)c*NV + n0 + nx*4) = make_uint2(h0, h1);
        }
    }
}

// ---------------- 4) fused flash attention (fp16 HMMA) ----------
// grid (NV/32, NB), 128 thr = 4 warps, 2 CTAs/SM.
// warp w: i-rows (w&1)*16..+16, j-half (w>>1)*32 of each 64-j chunk.
// QK = qh*K + ql*K (2 passes); PV = P*V (1 pass).
// Per-warp independent softmax state; halves merged in epilogue.
// Double buffer, ONE __syncthreads per chunk:
//   WAIT0 -> sync -> prefetch(t+1) -> consume(t)
#define FB_QSTR 272
#define FB_VSTR 144
#define FB_QL   8704          // Ql tile offset (32*272)
#define FB_Q    17408         // Q area total
#define FB_VOFF 17408         // V within buffer (K is 64*272)
#define FB_BUFSZ 35840        // K 17408 + V 18432
#define FB_SMEM (FB_Q + 2*FB_BUFSZ)   // 89088

__global__ void __launch_bounds__(128, 2) fattn_kernel()
{
    extern __shared__ char smem[];
    uint32_t sb = smem_u32(smem);
    int tid = threadIdx.x, wid = tid >> 5, lane = tid & 31;
    int b = blockIdx.y, i0 = blockIdx.x * 32;

    const __half* Qh = g_qTh + (size_t)b*NV*CC + (size_t)i0*CC;
    const __half* Ql = g_qTl + (size_t)b*NV*CC + (size_t)i0*CC;
    const __half* Kh = g_kTh + (size_t)b*NV*CC;
    const __half* Vh = g_vh  + (size_t)b*CC*NV;

    // ---- prologue: Q (group 0), chunk 0 (group 1)
    for (int idx = tid; idx < 512; idx += 128) {
        int row = idx >> 4, c = idx & 15;
        uint32_t so = sb + row*FB_QSTR + c*16;
        size_t go = (size_t)row*CC + c*8;
        CP_ASYNC16(so, Qh + go);
        CP_ASYNC16(so + FB_QL, Ql + go);
    }
    CP_COMMIT();
    {
        uint32_t base = sb + FB_Q;
        for (int idx = tid; idx < 1024; idx += 128) {
            int row = idx >> 4, c = idx & 15;
            CP_ASYNC16(base + row*FB_QSTR + c*16, Kh + (size_t)row*CC + c*8);
        }
        for (int idx = tid; idx < 1024; idx += 128) {
            int row = idx >> 3, c = idx & 7;
            CP_ASYNC16(base + FB_VOFF + row*FB_VSTR + c*16, Vh + (size_t)row*NV + c*8);
        }
        CP_COMMIT();
    }

    int ig = (wid & 1) * 16;
    int half = wid >> 1;
    int jh = half * 32;
    int arow = lane & 15, acol = (lane >> 4) << 3;
    int bm = lane >> 3;
    int brow = ((bm >> 1) << 3) + (lane & 7);
    int bcol = (bm & 1) << 3;
    int qgrp = lane & 3;
    int lr = ig + (lane >> 2);

    // ---- wait for Q (chunk0 may still be in flight), hoist Q frags
    CP_WAIT1();
    __syncthreads();
    uint32_t qh[8][4], ql[8][4];
    #pragma unroll
    for (int k = 0; k < 8; k++) {
        uint32_t ad = sb + (ig + arow)*FB_QSTR + (k*16 + acol)*2;
        LDMX4(qh[k][0], qh[k][1], qh[k][2], qh[k][3], ad);
        LDMX4(ql[k][0], ql[k][1], ql[k][2], ql[k][3], ad + FB_QL);
    }

    float acc[16][4];
    #pragma unroll
    for (int nt = 0; nt < 16; nt++)
        #pragma unroll
        for (int e = 0; e < 4; e++) acc[nt][e] = 0.f;
    float l0 = 0.f, l1 = 0.f, m0 = -1e30f, m1 = -1e30f;

    for (int t = 0; t < 64; t++) {
        uint32_t base = sb + FB_Q + (uint32_t)(t & 1)*FB_BUFSZ;
        CP_WAIT0();
        __syncthreads();
        if (t + 1 < 64) {
            uint32_t nb = sb + FB_Q + (uint32_t)((t + 1) & 1)*FB_BUFSZ;
            int j0 = (t + 1) * 64;
            for (int idx = tid; idx < 1024; idx += 128) {
                int row = idx >> 4, c = idx & 15;
                CP_ASYNC16(nb + row*FB_QSTR + c*16,
                           Kh + (size_t)(j0 + row)*CC + c*8);
            }
            for (int idx = tid; idx < 1024; idx += 128) {
                int row = idx >> 3, c = idx & 7;
                CP_ASYNC16(nb + FB_VOFF + row*FB_VSTR + c*16,
                           Vh + (size_t)row*NV + j0 + c*8);
            }
            CP_COMMIT();
        }

        // ---- QK: S (16 x 32); 2 passes (qh, ql) x K single
        float s[4][4];
        #pragma unroll
        for (int nt = 0; nt < 4; nt++)
            #pragma unroll
            for (int e = 0; e < 4; e++) s[nt][e] = 0.f;
        #pragma unroll
        for (int k = 0; k < 8; k++) {
            uint32_t bh[4][2];
            #pragma unroll
            for (int ntp = 0; ntp < 2; ntp++) {
                uint32_t q0, q1, q2, q3;
                LDMX4(q0, q1, q2, q3,
                      base + (jh + ntp*16 + brow)*FB_QSTR + (k*16 + bcol)*2);
                bh[2*ntp][0] = q0;   bh[2*ntp][1] = q1;
                bh[2*ntp+1][0] = q2; bh[2*ntp+1][1] = q3;
            }
            #pragma unroll
            for (int nt = 0; nt < 4; nt++) {
                MMA_F16(s[nt], qh[k], bh[nt]);
                MMA_F16(s[nt], ql[k], bh[nt]);
            }
        }

        // ---- warp-local online softmax (no cross-warp exchange)
        float mx0 = -1e30f, mx1 = -1e30f;
        #pragma unroll
        for (int nt = 0; nt < 4; nt++) {
            mx0 = fmaxf(mx0, fmaxf(s[nt][0], s[nt][1]));
            mx1 = fmaxf(mx1, fmaxf(s[nt][2], s[nt][3]));
        }
        mx0 = fmaxf(mx0, __shfl_xor_sync(0xffffffffu, mx0, 1));
        mx0 = fmaxf(mx0, __shfl_xor_sync(0xffffffffu, mx0, 2));
        mx1 = fmaxf(mx1, __shfl_xor_sync(0xffffffffu, mx1, 1));
        mx1 = fmaxf(mx1, __shfl_xor_sync(0xffffffffu, mx1, 2));
        float mn0 = fmaxf(m0, mx0), mn1 = fmaxf(m1, mx1);
        float al0 = exp2f(m0 - mn0), al1 = exp2f(m1 - mn1);
        m0 = mn0; m1 = mn1;
        float rs0 = 0.f, rs1 = 0.f;
        #pragma unroll
        for (int nt = 0; nt < 4; nt++) {
            s[nt][0] = exp2f(s[nt][0] - m0);
            s[nt][1] = exp2f(s[nt][1] - m0);
            s[nt][2] = exp2f(s[nt][2] - m1);
            s[nt][3] = exp2f(s[nt][3] - m1);
            rs0 += s[nt][0] + s[nt][1];
            rs1 += s[nt][2] + s[nt][3];
        }
        rs0 += __shfl_xor_sync(0xffffffffu, rs0, 1);
        rs0 += __shfl_xor_sync(0xffffffffu, rs0, 2);
        rs1 += __shfl_xor_sync(0xffffffffu, rs1, 1);
        rs1 += __shfl_xor_sync(0xffffffffu, rs1, 2);
        l0 = l0*al0 + rs0;
        l1 = l1*al1 + rs1;
        #pragma unroll
        for (int nt = 0; nt < 16; nt++) {
            acc[nt][0] *= al0; acc[nt][1] *= al0;
            acc[nt][2] *= al1; acc[nt][3] *= al1;
        }

        // ---- P -> fp16 A-fragments (single term)
        uint32_t ah[2][4];
        #pragma unroll
        for (int kb = 0; kb < 2; kb++) {
            int tA = 2*kb, tB = 2*kb + 1;
            ah[kb][0] = pack_h2(s[tA][0], s[tA][1]);
            ah[kb][1] = pack_h2(s[tA][2], s[tA][3]);
            ah[kb][2] = pack_h2(s[tB][0], s[tB][1]);
            ah[kb][3] = pack_h2(s[tB][2], s[tB][3]);
        }

        // ---- PV: acc += P @ V^T (single pass)
        #pragma unroll
        for (int kb = 0; kb < 2; kb++) {
            int kc = jh + kb*16;
            uint32_t bf2[16][2];
            #pragma unroll
            for (int ntp = 0; ntp < 8; ntp++) {
                uint32_t q0, q1, q2, q3;
                LDMX4(q0, q1, q2, q3,
                      base + FB_VOFF + (ntp*16 + brow)*FB_VSTR + (kc + bcol)*2);
                bf2[2*ntp][0] = q0;   bf2[2*ntp][1] = q1;
                bf2[2*ntp+1][0] = q2; bf2[2*ntp+1][1] = q3;
            }
            #pragma unroll
            for (int nt = 0; nt < 16; nt++)
                MMA_F16(acc[nt], ah[kb], bf2[nt]);
        }
    }

    // ---- epilogue: merge the two j-half partials
    __syncthreads();
    float* ms   = (float*)(smem + FB_Q);
    float* ls   = (float*)(smem + FB_Q + 128);
    float* Hred = (float*)(smem + FB_Q + 256);
    if (half) {
        if (qgrp == 0) {
            ms[lr] = m0;   ls[lr] = l0;
            ms[lr+8] = m1; ls[lr+8] = l1;
        }
        #pragma unroll
        for (int nt = 0; nt < 16; nt++) {
            Hred[lr*128 + nt*8 + qgrp*2]         = acc[nt][0];
            Hred[lr*128 + nt*8 + qgrp*2 + 1]     = acc[nt][1];
            Hred[(lr+8)*128 + nt*8 + qgrp*2]     = acc[nt][2];
            Hred[(lr+8)*128 + nt*8 + qgrp*2 + 1] = acc[nt][3];
        }
    }
    __syncthreads();
    if (!half) {
        float mo0 = ms[lr],   lo0 = ls[lr];
        float mo1 = ms[lr+8], lo1 = ls[lr+8];
        float mt0 = fmaxf(m0, mo0), mt1 = fmaxf(m1, mo1);
        float sA0 = exp2f(m0 - mt0), sB0 = exp2f(mo0 - mt0);
        float sA1 = exp2f(m1 - mt1), sB1 = exp2f(mo1 - mt1);
        float inv0 = 1.f / (l0*sA0 + lo0*sB0);
        float inv1 = 1.f / (l1*sA1 + lo1*sB1);
        float* H = g_hT + (size_t)b*NV*CC;
        #pragma unroll
        for (int nt = 0; nt < 16; nt++) {
            float h0 = (acc[nt][0]*sA0 + Hred[lr*128 + nt*8 + qgrp*2]*sB0)         * inv0;
            float h1 = (acc[nt][1]*sA0 + Hred[lr*128 + nt*8 + qgrp*2 + 1]*sB0)     * inv0;
            float h2 = (acc[nt][2]*sA1 + Hred[(lr+8)*128 + nt*8 + qgrp*2]*sB1)     * inv1;
            float h3 = (acc[nt][3]*sA1 + Hred[(lr+8)*128 + nt*8 + qgrp*2 + 1]*sB1) * inv1;
            *(float2*)(H + (size_t)(i0 + lr)*CC + nt*8 + qgrp*2)     = make_float2(h0, h1);
            *(float2*)(H + (size_t)(i0 + lr + 8)*CC + nt*8 + qgrp*2) = make_float2(h2, h3);
        }
    }
}

// ---------------- 5) output projection + residual ---------------
__global__ void proj_kernel(const float* __restrict__ inp,
                            const float* __restrict__ Wo,
                            const float* __restrict__ bo,
                            float* __restrict__ outp)
{
    extern __shared__ float sm[];
    float* Ws = sm;
    float* xs = sm + CC*CC;
    int b = blockIdx.y;
    int n0 = blockIdx.x * 64;
    int tid = threadIdx.x;

    for (int i = tid; i < CC*CC/4; i += 256) {
        int o  = i >> 5;
        int c4 = (i & 31) << 2;
        float4 w = *(const float4*)(Wo + o*CC + c4);
        Ws[(c4+0)*CC + o] = w.x;
        Ws[(c4+1)*CC + o] = w.y;
        Ws[(c4+2)*CC + o] = w.z;
        Ws[(c4+3)*CC + o] = w.w;
    }
    const float* hsrc = g_hT + (size_t)b*NV*CC;
    for (int i = tid; i < 64*32; i += 256) {
        int j  = i >> 5;
        int c4 = (i & 31) << 2;
        float4 h4 = *(const float4*)(hsrc + (size_t)(n0 + j)*CC + c4);
        xs[(c4+0)*64 + j] = h4.x;
        xs[(c4+1)*64 + j] = h4.y;
        xs[(c4+2)*64 + j] = h4.z;
        xs[(c4+3)*64 + j] = h4.w;
    }
    __syncthreads();

    int oy = tid >> 4;
    int nx = tid & 15;
    float acc[8][4];
    #pragma unroll
    for (int u = 0; u < 8; u++)
        #pragma unroll
        for (int v = 0; v < 4; v++) acc[u][v] = 0.f;

    #pragma unroll 4
    for (int c = 0; c < CC; c++) {
        float4 w0 = *(float4*)(Ws + c*CC + oy*8);
        float4 w1 = *(float4*)(Ws + c*CC + oy*8 + 4);
        float4 x4 = *(float4*)(xs + c*64 + nx*4);
        float wv[8] = {w0.x, w0.y, w0.z, w0.w, w1.x, w1.y, w1.z, w1.w};
        float xv[4] = {x4.x, x4.y, x4.z, x4.w};
        #pragma unroll
        for (int u = 0; u < 8; u++)
            #pragma unroll
            for (int v = 0; v < 4; v++) acc[u][v] += wv[u] * xv[v];
    }

    #pragma unroll
    for (int u = 0; u < 8; u++) {
        int o = oy*8 + u;
        float bias = bo[o];
        float4 r0 = *(const float4*)(inp + ((size_t)b*CC + o)*NV + n0 + nx*4);
        float4 r = make_float4(acc[u][0] + bias + r0.x,
                               acc[u][1] + bias + r0.y,
                               acc[u][2] + bias + r0.z,
                               acc[u][3] + bias + r0.w);
        *(float4*)(outp + ((size_t)b*CC + o)*NV + n0 + nx*4) = r;
    }
}

// ---------------- launch ----------------------------------------
extern "C" void kernel_launch(void* const* d_in, const int* in_sizes, int n_in,
                              void* d_out, int out_size)
{
    const float* inp   = (const float*)d_in[0];
    const float* gamma = (const float*)d_in[1];
    const float* beta  = (const float*)d_in[2];
    const float* Wq    = (const float*)d_in[3];
    const float* bq    = (const float*)d_in[4];
    const float* Wk    = (const float*)d_in[5];
    const float* bk    = (const float*)d_in[6];
    const float* Wv    = (const float*)d_in[7];
    const float* bv    = (const float*)d_in[8];
    const float* Wo    = (const float*)d_in[9];
    const float* bo    = (const float*)d_in[10];
    float* outp = (float*)d_out;

    int gemm_smem = (CC*CC + CC*64) * (int)sizeof(float);   // 96 KB
    cudaFuncSetAttribute(qkv_kernel,   cudaFuncAttributeMaxDynamicSharedMemorySize, gemm_smem);
    cudaFuncSetAttribute(proj_kernel,  cudaFuncAttributeMaxDynamicSharedMemorySize, gemm_smem);
    cudaFuncSetAttribute(fattn_kernel, cudaFuncAttributeMaxDynamicSharedMemorySize, FB_SMEM);

    stats_kernel<<<CC, 256>>>(inp, gamma, beta);
    fold_kernel<<<3*CC, CC>>>(Wq, bq, Wk, bk, Wv, bv);
    qkv_kernel<<<dim3(NV/64, 3, NB), 256, gemm_smem>>>(inp);
    fattn_kernel<<<dim3(NV/32, NB), 128, FB_SMEM>>>();
    proj_kernel<<<dim3(NV/64, NB), 256, gemm_smem>>>(inp, Wo, bo, outp);
}

// round 13
// speedup vs baseline: 7.5388x; 1.1055x over previous
#include <cuda_runtime.h>
#include <cuda_fp16.h>
#include <math.h>
#include <stdint.h>

#define CC   128
#define NV   4096
#define NB   2
#define EPSF 1e-5f

// ---------------- scratch (no allocation allowed) ----------------
__device__ float g_a[CC];
__device__ float g_dd[CC];
__device__ float g_Wq[CC*CC];
__device__ float g_Wk[CC*CC];
__device__ float g_Wv[CC*CC];
__device__ float g_bq[CC];
__device__ float g_bk[CC];
__device__ float g_bv[CC];
__device__ float g_hT[NB*NV*CC];     // attention out, [b][i][c]
__device__ __half g_qT[NB*NV*CC];    // q^T fp16, [b][i][c]
__device__ __half g_kT[NB*NV*CC];    // k^T fp16, [b][i][c]
__device__ __half g_vh[NB*CC*NV];    // v fp16, natural [b][c][n]

// ---------------- PTX helpers (compute_80-era only!) -------------
__device__ __forceinline__ uint32_t smem_u32(const void* p) {
    uint32_t a;
    asm("{ .reg .u64 t; cvta.to.shared.u64 t, %1; cvt.u32.u64 %0, t; }"
        : "=r"(a) : "l"(p));
    return a;
}
#define LDMX4(r0,r1,r2,r3,addr) \
    asm volatile("ldmatrix.sync.aligned.m8n8.x4.shared.b16 {%0,%1,%2,%3}, [%4];" \
                 : "=r"(r0),"=r"(r1),"=r"(r2),"=r"(r3) : "r"(addr))
#define MMA_F16(c,a,b) \
    asm volatile("mma.sync.aligned.m16n8k16.row.col.f32.f16.f16.f32 " \
                 "{%0,%1,%2,%3}, {%4,%5,%6,%7}, {%8,%9}, {%0,%1,%2,%3};" \
                 : "+f"((c)[0]),"+f"((c)[1]),"+f"((c)[2]),"+f"((c)[3]) \
                 : "r"((a)[0]),"r"((a)[1]),"r"((a)[2]),"r"((a)[3]), \
                   "r"((b)[0]),"r"((b)[1]))
#define CP_ASYNC16(s,g) \
    asm volatile("cp.async.cg.shared.global [%0], [%1], 16;" :: "r"(s), "l"(g) : "memory")
#define CP_COMMIT()  asm volatile("cp.async.commit_group;" ::: "memory")
#define CP_WAIT1()   asm volatile("cp.async.wait_group 1;" ::: "memory")
#define CP_WAIT0()   asm volatile("cp.async.wait_group 0;" ::: "memory")

__device__ __forceinline__ uint32_t pack_h2(float a, float b) {
    __half2 t = __floats2half2_rn(a, b);
    return *reinterpret_cast<uint32_t*>(&t);
}

// ---------------- 1) per-channel batch stats --------------------
__global__ void stats_kernel(const float* __restrict__ inp,
                             const float* __restrict__ gamma,
                             const float* __restrict__ beta)
{
    int c = blockIdx.x;
    int tid = threadIdx.x;
    const float* p0 = inp + c * NV;
    const float* p1 = inp + (CC + c) * NV;
    float s = 0.f, ss = 0.f;
    for (int n = tid * 4; n < NV; n += 256 * 4) {
        float4 a = *(const float4*)(p0 + n);
        float4 b = *(const float4*)(p1 + n);
        s  += a.x + a.y + a.z + a.w + b.x + b.y + b.z + b.w;
        ss += a.x*a.x + a.y*a.y + a.z*a.z + a.w*a.w
            + b.x*b.x + b.y*b.y + b.z*b.z + b.w*b.w;
    }
    #pragma unroll
    for (int off = 16; off; off >>= 1) {
        s  += __shfl_xor_sync(0xffffffffu, s, off);
        ss += __shfl_xor_sync(0xffffffffu, ss, off);
    }
    __shared__ float sb[8], ssb[8];
    int w = tid >> 5;
    if ((tid & 31) == 0) { sb[w] = s; ssb[w] = ss; }
    __syncthreads();
    if (tid == 0) {
        float ts = 0.f, tss = 0.f;
        #pragma unroll
        for (int i = 0; i < 8; i++) { ts += sb[i]; tss += ssb[i]; }
        const float inv = 1.f / (float)(NB * NV);
        float mean = ts * inv;
        float var  = tss * inv - mean * mean;
        float a = gamma[c] * rsqrtf(var + EPSF);
        g_a[c]  = a;
        g_dd[c] = beta[c] - mean * a;
    }
}

// ---------------- 2) fold BN (+ q scale + log2e) into weights ---
__global__ void fold_kernel(const float* __restrict__ Wq, const float* __restrict__ bq,
                            const float* __restrict__ Wk, const float* __restrict__ bk,
                            const float* __restrict__ Wv, const float* __restrict__ bv)
{
    int m = blockIdx.x >> 7;
    int o = blockIdx.x & 127;
    int c = threadIdx.x;
    const float QSC = 1.44269504088896341f * 0.0883883476483184406f;
    const float* W; const float* bs; float* Wd; float* bd; float sc;
    if (m == 0)      { W = Wq; bs = bq; Wd = g_Wq; bd = g_bq; sc = QSC; }
    else if (m == 1) { W = Wk; bs = bk; Wd = g_Wk; bd = g_bk; sc = 1.f; }
    else             { W = Wv; bs = bv; Wd = g_Wv; bd = g_bv; sc = 1.f; }
    float w = W[o*CC + c];
    Wd[o*CC + c] = w * g_a[c] * sc;
    float part = w * g_dd[c];
    #pragma unroll
    for (int off = 16; off; off >>= 1)
        part += __shfl_xor_sync(0xffffffffu, part, off);
    __shared__ float pb[4];
    if ((c & 31) == 0) pb[c >> 5] = part;
    __syncthreads();
    if (c == 0) bd[o] = (bs[o] + pb[0] + pb[1] + pb[2] + pb[3]) * sc;
}

// ---------------- 3) QKV GEMM + fp16 pack/transpose -------------
__global__ void qkv_kernel(const float* __restrict__ inp)
{
    extern __shared__ float sm[];
    float* Ws = sm;
    float* xs = sm + CC*CC;
    int m = blockIdx.y, b = blockIdx.z;
    int n0 = blockIdx.x * 64;
    const float* W  = (m == 0) ? g_Wq : (m == 1) ? g_Wk : g_Wv;
    const float* bb = (m == 0) ? g_bq : (m == 1) ? g_bk : g_bv;
    int tid = threadIdx.x;

    for (int i = tid; i < CC*CC/4; i += 256) {
        int o  = i >> 5;
        int c4 = (i & 31) << 2;
        float4 w = *(const float4*)(W + o*CC + c4);
        Ws[(c4+0)*CC + o] = w.x;
        Ws[(c4+1)*CC + o] = w.y;
        Ws[(c4+2)*CC + o] = w.z;
        Ws[(c4+3)*CC + o] = w.w;
    }
    for (int i = tid; i < CC*16; i += 256) {
        int c  = i >> 4;
        int j4 = (i & 15) << 2;
        *(float4*)(xs + c*64 + j4) =
            *(const float4*)(inp + ((size_t)b*CC + c)*NV + n0 + j4);
    }
    __syncthreads();

    int oy = tid >> 4;
    int nx = tid & 15;
    float acc[8][4];
    #pragma unroll
    for (int u = 0; u < 8; u++)
        #pragma unroll
        for (int v = 0; v < 4; v++) acc[u][v] = 0.f;

    #pragma unroll 4
    for (int c = 0; c < CC; c++) {
        float4 w0 = *(float4*)(Ws + c*CC + oy*8);
        float4 w1 = *(float4*)(Ws + c*CC + oy*8 + 4);
        float4 x4 = *(float4*)(xs + c*64 + nx*4);
        float wv[8] = {w0.x, w0.y, w0.z, w0.w, w1.x, w1.y, w1.z, w1.w};
        float xv[4] = {x4.x, x4.y, x4.z, x4.w};
        #pragma unroll
        for (int u = 0; u < 8; u++)
            #pragma unroll
            for (int v = 0; v < 4; v++) acc[u][v] += wv[u] * xv[v];
    }

    #pragma unroll
    for (int u = 0; u < 8; u++) {
        float bias = bb[oy*8 + u];
        #pragma unroll
        for (int v = 0; v < 4; v++) acc[u][v] += bias;
    }

    if (m < 2) {
        // q/k: transposed, single fp16, 16B stores of 8 channels
        __half* dh = (m == 0 ? g_qT : g_kT) + (size_t)b*NV*CC;
        #pragma unroll
        for (int v = 0; v < 4; v++) {
            int i = n0 + nx*4 + v;
            uint32_t hi[4];
            #pragma unroll
            for (int p = 0; p < 4; p++)
                hi[p] = pack_h2(acc[2*p][v], acc[2*p+1][v]);
            *(uint4*)(dh + (size_t)i*CC + oy*8) = make_uint4(hi[0], hi[1], hi[2], hi[3]);
        }
    } else {
        // v: natural, single fp16
        __half* dh = g_vh + (size_t)b*CC*NV;
        #pragma unroll
        for (int u = 0; u < 8; u++) {
            int c = oy*8 + u;
            uint32_t h0 = pack_h2(acc[u][0], acc[u][1]);
            uint32_t h1 = pack_h2(acc[u][2], acc[u][3]);
            *(uint2*)(dh + (size_t)c*NV + n0 + nx*4) = make_uint2(h0, h1);
        }
    }
}

// ---------------- 4) fused flash attention (fp16 HMMA) ----------
// grid (NV/32, NB), 128 thr = 4 warps, 2 CTAs/SM.
// warp w: i-rows (w&1)*16..+16, j-half (w>>1)*32 of each 64-j chunk.
// QK = q*K (1 pass); PV = P*V (1 pass). Warp-local softmax state;
// rescale skipped via warp vote when max unchanged.
// Double buffer, ONE __syncthreads per chunk.
#define FB_QSTR 272
#define FB_VSTR 144
#define FB_Q    8704          // Q area (32*272)
#define FB_VOFF 17408         // V within buffer (K is 64*272)
#define FB_BUFSZ 35840        // K 17408 + V 18432
#define FB_SMEM (FB_Q + 2*FB_BUFSZ)   // 80384

__global__ void __launch_bounds__(128, 2) fattn_kernel()
{
    extern __shared__ char smem[];
    uint32_t sb = smem_u32(smem);
    int tid = threadIdx.x, wid = tid >> 5, lane = tid & 31;
    int b = blockIdx.y, i0 = blockIdx.x * 32;

    const __half* Qp = g_qT + (size_t)b*NV*CC + (size_t)i0*CC;
    const __half* Kh = g_kT + (size_t)b*NV*CC;
    const __half* Vh = g_vh + (size_t)b*CC*NV;

    // ---- prologue: Q (group 0), chunk 0 (group 1)
    for (int idx = tid; idx < 512; idx += 128) {
        int row = idx >> 4, c = idx & 15;
        CP_ASYNC16(sb + row*FB_QSTR + c*16, Qp + (size_t)row*CC + c*8);
    }
    CP_COMMIT();
    {
        uint32_t base = sb + FB_Q;
        for (int idx = tid; idx < 1024; idx += 128) {
            int row = idx >> 4, c = idx & 15;
            CP_ASYNC16(base + row*FB_QSTR + c*16, Kh + (size_t)row*CC + c*8);
        }
        for (int idx = tid; idx < 1024; idx += 128) {
            int row = idx >> 3, c = idx & 7;
            CP_ASYNC16(base + FB_VOFF + row*FB_VSTR + c*16, Vh + (size_t)row*NV + c*8);
        }
        CP_COMMIT();
    }

    int ig = (wid & 1) * 16;
    int half = wid >> 1;
    int jh = half * 32;
    int arow = lane & 15, acol = (lane >> 4) << 3;
    int bm = lane >> 3;
    int brow = ((bm >> 1) << 3) + (lane & 7);
    int bcol = (bm & 1) << 3;
    int qgrp = lane & 3;
    int lr = ig + (lane >> 2);

    // ---- wait for Q, hoist Q fragments
    CP_WAIT1();
    __syncthreads();
    uint32_t qf[8][4];
    #pragma unroll
    for (int k = 0; k < 8; k++) {
        uint32_t ad = sb + (ig + arow)*FB_QSTR + (k*16 + acol)*2;
        LDMX4(qf[k][0], qf[k][1], qf[k][2], qf[k][3], ad);
    }

    float acc[16][4];
    #pragma unroll
    for (int nt = 0; nt < 16; nt++)
        #pragma unroll
        for (int e = 0; e < 4; e++) acc[nt][e] = 0.f;
    float l0 = 0.f, l1 = 0.f, m0 = -1e30f, m1 = -1e30f;

    for (int t = 0; t < 64; t++) {
        uint32_t base = sb + FB_Q + (uint32_t)(t & 1)*FB_BUFSZ;
        CP_WAIT0();
        __syncthreads();
        if (t + 1 < 64) {
            uint32_t nb = sb + FB_Q + (uint32_t)((t + 1) & 1)*FB_BUFSZ;
            int j0 = (t + 1) * 64;
            for (int idx = tid; idx < 1024; idx += 128) {
                int row = idx >> 4, c = idx & 15;
                CP_ASYNC16(nb + row*FB_QSTR + c*16,
                           Kh + (size_t)(j0 + row)*CC + c*8);
            }
            for (int idx = tid; idx < 1024; idx += 128) {
                int row = idx >> 3, c = idx & 7;
                CP_ASYNC16(nb + FB_VOFF + row*FB_VSTR + c*16,
                           Vh + (size_t)row*NV + j0 + c*8);
            }
            CP_COMMIT();
        }

        // ---- QK: S (16 x 32), single fp16 pass
        float s[4][4];
        #pragma unroll
        for (int nt = 0; nt < 4; nt++)
            #pragma unroll
            for (int e = 0; e < 4; e++) s[nt][e] = 0.f;
        #pragma unroll
        for (int k = 0; k < 8; k++) {
            uint32_t bh[4][2];
            #pragma unroll
            for (int ntp = 0; ntp < 2; ntp++) {
                uint32_t q0, q1, q2, q3;
                LDMX4(q0, q1, q2, q3,
                      base + (jh + ntp*16 + brow)*FB_QSTR + (k*16 + bcol)*2);
                bh[2*ntp][0] = q0;   bh[2*ntp][1] = q1;
                bh[2*ntp+1][0] = q2; bh[2*ntp+1][1] = q3;
            }
            #pragma unroll
            for (int nt = 0; nt < 4; nt++)
                MMA_F16(s[nt], qf[k], bh[nt]);
        }

        // ---- warp-local online softmax
        float mx0 = -1e30f, mx1 = -1e30f;
        #pragma unroll
        for (int nt = 0; nt < 4; nt++) {
            mx0 = fmaxf(mx0, fmaxf(s[nt][0], s[nt][1]));
            mx1 = fmaxf(mx1, fmaxf(s[nt][2], s[nt][3]));
        }
        mx0 = fmaxf(mx0, __shfl_xor_sync(0xffffffffu, mx0, 1));
        mx0 = fmaxf(mx0, __shfl_xor_sync(0xffffffffu, mx0, 2));
        mx1 = fmaxf(mx1, __shfl_xor_sync(0xffffffffu, mx1, 1));
        mx1 = fmaxf(mx1, __shfl_xor_sync(0xffffffffu, mx1, 2));
        bool upd = (mx0 > m0) || (mx1 > m1);
        if (__any_sync(0xffffffffu, upd)) {
            float mn0 = fmaxf(m0, mx0), mn1 = fmaxf(m1, mx1);
            float al0 = exp2f(m0 - mn0), al1 = exp2f(m1 - mn1);
            m0 = mn0; m1 = mn1;
            l0 *= al0; l1 *= al1;
            #pragma unroll
            for (int nt = 0; nt < 16; nt++) {
                acc[nt][0] *= al0; acc[nt][1] *= al0;
                acc[nt][2] *= al1; acc[nt][3] *= al1;
            }
        }
        float rs0 = 0.f, rs1 = 0.f;
        #pragma unroll
        for (int nt = 0; nt < 4; nt++) {
            s[nt][0] = exp2f(s[nt][0] - m0);
            s[nt][1] = exp2f(s[nt][1] - m0);
            s[nt][2] = exp2f(s[nt][2] - m1);
            s[nt][3] = exp2f(s[nt][3] - m1);
            rs0 += s[nt][0] + s[nt][1];
            rs1 += s[nt][2] + s[nt][3];
        }
        rs0 += __shfl_xor_sync(0xffffffffu, rs0, 1);
        rs0 += __shfl_xor_sync(0xffffffffu, rs0, 2);
        rs1 += __shfl_xor_sync(0xffffffffu, rs1, 1);
        rs1 += __shfl_xor_sync(0xffffffffu, rs1, 2);
        l0 += rs0;
        l1 += rs1;

        // ---- P -> fp16 A-fragments
        uint32_t ah[2][4];
        #pragma unroll
        for (int kb = 0; kb < 2; kb++) {
            int tA = 2*kb, tB = 2*kb + 1;
            ah[kb][0] = pack_h2(s[tA][0], s[tA][1]);
            ah[kb][1] = pack_h2(s[tA][2], s[tA][3]);
            ah[kb][2] = pack_h2(s[tB][0], s[tB][1]);
            ah[kb][3] = pack_h2(s[tB][2], s[tB][3]);
        }

        // ---- PV: acc += P @ V^T (single pass)
        #pragma unroll
        for (int kb = 0; kb < 2; kb++) {
            int kc = jh + kb*16;
            uint32_t bf2[16][2];
            #pragma unroll
            for (int ntp = 0; ntp < 8; ntp++) {
                uint32_t q0, q1, q2, q3;
                LDMX4(q0, q1, q2, q3,
                      base + FB_VOFF + (ntp*16 + brow)*FB_VSTR + (kc + bcol)*2);
                bf2[2*ntp][0] = q0;   bf2[2*ntp][1] = q1;
                bf2[2*ntp+1][0] = q2; bf2[2*ntp+1][1] = q3;
            }
            #pragma unroll
            for (int nt = 0; nt < 16; nt++)
                MMA_F16(acc[nt], ah[kb], bf2[nt]);
        }
    }

    // ---- epilogue: merge the two j-half partials
    __syncthreads();
    float* ms   = (float*)(smem + FB_Q);
    float* ls   = (float*)(smem + FB_Q + 128);
    float* Hred = (float*)(smem + FB_Q + 256);
    if (half) {
        if (qgrp == 0) {
            ms[lr] = m0;   ls[lr] = l0;
            ms[lr+8] = m1; ls[lr+8] = l1;
        }
        #pragma unroll
        for (int nt = 0; nt < 16; nt++) {
            Hred[lr*128 + nt*8 + qgrp*2]         = acc[nt][0];
            Hred[lr*128 + nt*8 + qgrp*2 + 1]     = acc[nt][1];
            Hred[(lr+8)*128 + nt*8 + qgrp*2]     = acc[nt][2];
            Hred[(lr+8)*128 + nt*8 + qgrp*2 + 1] = acc[nt][3];
        }
    }
    __syncthreads();
    if (!half) {
        float mo0 = ms[lr],   lo0 = ls[lr];
        float mo1 = ms[lr+8], lo1 = ls[lr+8];
        float mt0 = fmaxf(m0, mo0), mt1 = fmaxf(m1, mo1);
        float sA0 = exp2f(m0 - mt0), sB0 = exp2f(mo0 - mt0);
        float sA1 = exp2f(m1 - mt1), sB1 = exp2f(mo1 - mt1);
        float inv0 = 1.f / (l0*sA0 + lo0*sB0);
        float inv1 = 1.f / (l1*sA1 + lo1*sB1);
        float* H = g_hT + (size_t)b*NV*CC;
        #pragma unroll
        for (int nt = 0; nt < 16; nt++) {
            float h0 = (acc[nt][0]*sA0 + Hred[lr*128 + nt*8 + qgrp*2]*sB0)         * inv0;
            float h1 = (acc[nt][1]*sA0 + Hred[lr*128 + nt*8 + qgrp*2 + 1]*sB0)     * inv0;
            float h2 = (acc[nt][2]*sA1 + Hred[(lr+8)*128 + nt*8 + qgrp*2]*sB1)     * inv1;
            float h3 = (acc[nt][3]*sA1 + Hred[(lr+8)*128 + nt*8 + qgrp*2 + 1]*sB1) * inv1;
            *(float2*)(H + (size_t)(i0 + lr)*CC + nt*8 + qgrp*2)     = make_float2(h0, h1);
            *(float2*)(H + (size_t)(i0 + lr + 8)*CC + nt*8 + qgrp*2) = make_float2(h2, h3);
        }
    }
}

// ---------------- 5) output projection + residual ---------------
__global__ void proj_kernel(const float* __restrict__ inp,
                            const float* __restrict__ Wo,
                            const float* __restrict__ bo,
                            float* __restrict__ outp)
{
    extern __shared__ float sm[];
    float* Ws = sm;
    float* xs = sm + CC*CC;
    int b = blockIdx.y;
    int n0 = blockIdx.x * 64;
    int tid = threadIdx.x;

    for (int i = tid; i < CC*CC/4; i += 256) {
        int o  = i >> 5;
        int c4 = (i & 31) << 2;
        float4 w = *(const float4*)(Wo + o*CC + c4);
        Ws[(c4+0)*CC + o] = w.x;
        Ws[(c4+1)*CC + o] = w.y;
        Ws[(c4+2)*CC + o] = w.z;
        Ws[(c4+3)*CC + o] = w.w;
    }
    const float* hsrc = g_hT + (size_t)b*NV*CC;
    for (int i = tid; i < 64*32; i += 256) {
        int j  = i >> 5;
        int c4 = (i & 31) << 2;
        float4 h4 = *(const float4*)(hsrc + (size_t)(n0 + j)*CC + c4);
        xs[(c4+0)*64 + j] = h4.x;
        xs[(c4+1)*64 + j] = h4.y;
        xs[(c4+2)*64 + j] = h4.z;
        xs[(c4+3)*64 + j] = h4.w;
    }
    __syncthreads();

    int oy = tid >> 4;
    int nx = tid & 15;
    float acc[8][4];
    #pragma unroll
    for (int u = 0; u < 8; u++)
        #pragma unroll
        for (int v = 0; v < 4; v++) acc[u][v] = 0.f;

    #pragma unroll 4
    for (int c = 0; c < CC; c++) {
        float4 w0 = *(float4*)(Ws + c*CC + oy*8);
        float4 w1 = *(float4*)(Ws + c*CC + oy*8 + 4);
        float4 x4 = *(float4*)(xs + c*64 + nx*4);
        float wv[8] = {w0.x, w0.y, w0.z, w0.w, w1.x, w1.y, w1.z, w1.w};
        float xv[4] = {x4.x, x4.y, x4.z, x4.w};
        #pragma unroll
        for (int u = 0; u < 8; u++)
            #pragma unroll
            for (int v = 0; v < 4; v++) acc[u][v] += wv[u] * xv[v];
    }

    #pragma unroll
    for (int u = 0; u < 8; u++) {
        int o = oy*8 + u;
        float bias = bo[o];
        float4 r0 = *(const float4*)(inp + ((size_t)b*CC + o)*NV + n0 + nx*4);
        float4 r = make_float4(acc[u][0] + bias + r0.x,
                               acc[u][1] + bias + r0.y,
                               acc[u][2] + bias + r0.z,
                               acc[u][3] + bias + r0.w);
        *(float4*)(outp + ((size_t)b*CC + o)*NV + n0 + nx*4) = r;
    }
}

// ---------------- launch ----------------------------------------
extern "C" void kernel_launch(void* const* d_in, const int* in_sizes, int n_in,
                              void* d_out, int out_size)
{
    const float* inp   = (const float*)d_in[0];
    const float* gamma = (const float*)d_in[1];
    const float* beta  = (const float*)d_in[2];
    const float* Wq    = (const float*)d_in[3];
    const float* bq    = (const float*)d_in[4];
    const float* Wk    = (const float*)d_in[5];
    const float* bk    = (const float*)d_in[6];
    const float* Wv    = (const float*)d_in[7];
    const float* bv    = (const float*)d_in[8];
    const float* Wo    = (const float*)d_in[9];
    const float* bo    = (const float*)d_in[10];
    float* outp = (float*)d_out;

    int gemm_smem = (CC*CC + CC*64) * (int)sizeof(float);   // 96 KB
    cudaFuncSetAttribute(qkv_kernel,   cudaFuncAttributeMaxDynamicSharedMemorySize, gemm_smem);
    cudaFuncSetAttribute(proj_kernel,  cudaFuncAttributeMaxDynamicSharedMemorySize, gemm_smem);
    cudaFuncSetAttribute(fattn_kernel, cudaFuncAttributeMaxDynamicSharedMemorySize, FB_SMEM);

    stats_kernel<<<CC, 256>>>(inp, gamma, beta);
    fold_kernel<<<3*CC, CC>>>(Wq, bq, Wk, bk, Wv, bv);
    qkv_kernel<<<dim3(NV/64, 3, NB), 256, gemm_smem>>>(inp);
    fattn_kernel<<<dim3(NV/32, NB), 128, FB_SMEM>>>();
    proj_kernel<<<dim3(NV/64, NB), 256, gemm_smem>>>(inp, Wo, bo, outp);
}

// round 15
// speedup vs baseline: 9.4578x; 1.2546x over previous
#include <cuda_runtime.h>
#include <cuda_fp16.h>
#include <math.h>
#include <stdint.h>

#define CC   128
#define NV   4096
#define NB   2
#define EPSF 1e-5f

// ---------------- scratch (no allocation allowed) ----------------
__device__ float g_a[CC];
__device__ float g_dd[CC];
__device__ __half g_W16h[3*CC*CC];   // folded W' fp16 hi, [m][o][c]
__device__ __half g_W16l[3*CC*CC];   // folded W' fp16 lo
__device__ float g_bq[CC];
__device__ float g_bk[CC];
__device__ float g_bv[CC];
__device__ float g_hT[NB*NV*CC];     // attention out, [b][i][c]
__device__ __half g_qT[NB*NV*CC];    // q^T fp16, [b][i][c]
__device__ __half g_kT[NB*NV*CC];    // k^T fp16, [b][i][c]
__device__ __half g_vh[NB*CC*NV];    // v fp16, natural [b][c][n]

// ---------------- PTX helpers (compute_80-era only!) -------------
__device__ __forceinline__ uint32_t smem_u32(const void* p) {
    uint32_t a;
    asm("{ .reg .u64 t; cvta.to.shared.u64 t, %1; cvt.u32.u64 %0, t; }"
        : "=r"(a) : "l"(p));
    return a;
}
#define LDMX4(r0,r1,r2,r3,addr) \
    asm volatile("ldmatrix.sync.aligned.m8n8.x4.shared.b16 {%0,%1,%2,%3}, [%4];" \
                 : "=r"(r0),"=r"(r1),"=r"(r2),"=r"(r3) : "r"(addr))
#define LDMX4T(r0,r1,r2,r3,addr) \
    asm volatile("ldmatrix.sync.aligned.m8n8.x4.trans.shared.b16 {%0,%1,%2,%3}, [%4];" \
                 : "=r"(r0),"=r"(r1),"=r"(r2),"=r"(r3) : "r"(addr))
#define MMA_F16(c,a,b) \
    asm volatile("mma.sync.aligned.m16n8k16.row.col.f32.f16.f16.f32 " \
                 "{%0,%1,%2,%3}, {%4,%5,%6,%7}, {%8,%9}, {%0,%1,%2,%3};" \
                 : "+f"((c)[0]),"+f"((c)[1]),"+f"((c)[2]),"+f"((c)[3]) \
                 : "r"((a)[0]),"r"((a)[1]),"r"((a)[2]),"r"((a)[3]), \
                   "r"((b)[0]),"r"((b)[1]))
#define CP_ASYNC16(s,g) \
    asm volatile("cp.async.cg.shared.global [%0], [%1], 16;" :: "r"(s), "l"(g) : "memory")
#define CP_COMMIT()  asm volatile("cp.async.commit_group;" ::: "memory")
#define CP_WAIT1()   asm volatile("cp.async.wait_group 1;" ::: "memory")
#define CP_WAIT0()   asm volatile("cp.async.wait_group 0;" ::: "memory")

__device__ __forceinline__ uint32_t pack_h2(float a, float b) {
    __half2 t = __floats2half2_rn(a, b);
    return *reinterpret_cast<uint32_t*>(&t);
}
__device__ __forceinline__ void split_pack_h(float a, float b, uint32_t& hi, uint32_t& lo) {
    __half ha = __float2half_rn(a), hb = __float2half_rn(b);
    __half2 H; H.x = ha; H.y = hb;
    hi = *reinterpret_cast<uint32_t*>(&H);
    lo = pack_h2(a - __half2float(ha), b - __half2float(hb));
}

// ---------------- 1) per-channel batch stats --------------------
__global__ void stats_kernel(const float* __restrict__ inp,
                             const float* __restrict__ gamma,
                             const float* __restrict__ beta)
{
    int c = blockIdx.x;
    int tid = threadIdx.x;
    const float* p0 = inp + c * NV;
    const float* p1 = inp + (CC + c) * NV;
    float s = 0.f, ss = 0.f;
    for (int n = tid * 4; n < NV; n += 256 * 4) {
        float4 a = *(const float4*)(p0 + n);
        float4 b = *(const float4*)(p1 + n);
        s  += a.x + a.y + a.z + a.w + b.x + b.y + b.z + b.w;
        ss += a.x*a.x + a.y*a.y + a.z*a.z + a.w*a.w
            + b.x*b.x + b.y*b.y + b.z*b.z + b.w*b.w;
    }
    #pragma unroll
    for (int off = 16; off; off >>= 1) {
        s  += __shfl_xor_sync(0xffffffffu, s, off);
        ss += __shfl_xor_sync(0xffffffffu, ss, off);
    }
    __shared__ float sb[8], ssb[8];
    int w = tid >> 5;
    if ((tid & 31) == 0) { sb[w] = s; ssb[w] = ss; }
    __syncthreads();
    if (tid == 0) {
        float ts = 0.f, tss = 0.f;
        #pragma unroll
        for (int i = 0; i < 8; i++) { ts += sb[i]; tss += ssb[i]; }
        const float inv = 1.f / (float)(NB * NV);
        float mean = ts * inv;
        float var  = tss * inv - mean * mean;
        float a = gamma[c] * rsqrtf(var + EPSF);
        g_a[c]  = a;
        g_dd[c] = beta[c] - mean * a;
    }
}

// ---------------- 2) fold BN into weights + fp16 split ----------
__global__ void fold_kernel(const float* __restrict__ Wq, const float* __restrict__ bq,
                            const float* __restrict__ Wk, const float* __restrict__ bk,
                            const float* __restrict__ Wv, const float* __restrict__ bv)
{
    int m = blockIdx.x >> 7;
    int o = blockIdx.x & 127;
    int c = threadIdx.x;
    const float QSC = 1.44269504088896341f * 0.0883883476483184406f;
    const float* W; const float* bs; float* bd; float sc;
    if (m == 0)      { W = Wq; bs = bq; bd = g_bq; sc = QSC; }
    else if (m == 1) { W = Wk; bs = bk; bd = g_bk; sc = 1.f; }
    else             { W = Wv; bs = bv; bd = g_bv; sc = 1.f; }
    float w = W[o*CC + c];
    float wp = w * g_a[c] * sc;
    __half h = __float2half_rn(wp);
    g_W16h[m*CC*CC + o*CC + c] = h;
    g_W16l[m*CC*CC + o*CC + c] = __float2half_rn(wp - __half2float(h));
    float part = w * g_dd[c];
    #pragma unroll
    for (int off = 16; off; off >>= 1)
        part += __shfl_xor_sync(0xffffffffu, part, off);
    __shared__ float pb[4];
    if ((c & 31) == 0) pb[c >> 5] = part;
    __syncthreads();
    if (c == 0) bd[o] = (bs[o] + pb[0] + pb[1] + pb[2] + pb[3]) * sc;
}

// ---------------- 3) QKV GEMM via HMMA (fp16 split x3) ----------
// grid (NV/64, 3, NB), 256 thr = 8 warps (4 o-groups x 2 n-halves).
// A = W' [o][c] (non-trans frags), B = x [c][n] via ldmatrix.trans.
// q/k outputs transposed through fp32 smem staging; v direct.
#define QG_XH   0
#define QG_XL   18432
#define QG_WH   36864
#define QG_WL   71680
#define QG_SMEM 106496
#define QG_XSTR 144
#define QG_WSTR 272

__global__ void __launch_bounds__(256, 2) qkv_kernel(const float* __restrict__ inp)
{
    extern __shared__ char smem[];
    uint32_t sb = smem_u32(smem);
    int m = blockIdx.y, b = blockIdx.z;
    int n0g = blockIdx.x * 64;
    int tid = threadIdx.x, wid = tid >> 5, lane = tid & 31;
    const __half* Wh = g_W16h + (size_t)m*CC*CC;
    const __half* Wl = g_W16l + (size_t)m*CC*CC;
    const float* bb = (m == 0) ? g_bq : (m == 1) ? g_bk : g_bv;

    // W hi/lo via cp.async (fp16, 128 rows x 256 B each)
    for (int idx = tid; idx < 2048; idx += 256) {
        int r = idx >> 4, c16 = idx & 15;
        CP_ASYNC16(sb + QG_WH + r*QG_WSTR + c16*16, Wh + (size_t)r*CC + c16*8);
        CP_ASYNC16(sb + QG_WL + r*QG_WSTR + c16*16, Wl + (size_t)r*CC + c16*8);
    }
    CP_COMMIT();

    // x: LDG fp32 [c][n] -> split fp16 hi/lo -> STS same layout
    {
        const float* xg = inp + (size_t)b*CC*NV + n0g;
        int c = tid >> 1, nh2 = (tid & 1) * 32;
        #pragma unroll
        for (int i = 0; i < 8; i++) {
            float4 v = *(const float4*)(xg + (size_t)c*NV + nh2 + i*4);
            uint32_t h0, l0, h1, l1;
            split_pack_h(v.x, v.y, h0, l0);
            split_pack_h(v.z, v.w, h1, l1);
            *(uint2*)(smem + QG_XH + c*QG_XSTR + (nh2 + i*4)*2) = make_uint2(h0, h1);
            *(uint2*)(smem + QG_XL + c*QG_XSTR + (nh2 + i*4)*2) = make_uint2(l0, l1);
        }
    }
    CP_WAIT0();
    __syncthreads();

    int og = wid >> 1, nh = wid & 1;
    int o0 = og * 32, n0 = nh * 32;
    int arow = lane & 15, acol = (lane >> 4) << 3;
    int btrow = ((lane >> 3) & 1)*8 + (lane & 7);   // + kc
    int btcolb = (lane >> 4) * 16;                   // byte offset

    float acc[2][4][4];
    #pragma unroll
    for (int mt = 0; mt < 2; mt++)
        #pragma unroll
        for (int nt = 0; nt < 4; nt++)
            #pragma unroll
            for (int e = 0; e < 4; e++) acc[mt][nt][e] = 0.f;

    #pragma unroll
    for (int pass = 0; pass < 3; pass++) {
        uint32_t Ab = sb + (pass == 1 ? QG_WL : QG_WH);
        uint32_t Bb = sb + (pass == 2 ? QG_XL : QG_XH);
        #pragma unroll
        for (int k = 0; k < 8; k++) {
            int kc = k * 16;
            uint32_t a[2][4];
            #pragma unroll
            for (int mt = 0; mt < 2; mt++)
                LDMX4(a[mt][0], a[mt][1], a[mt][2], a[mt][3],
                      Ab + (o0 + mt*16 + arow)*QG_WSTR + (kc + acol)*2);
            uint32_t bf[4][2];
            #pragma unroll
            for (int nt2 = 0; nt2 < 2; nt2++) {
                uint32_t q0, q1, q2, q3;
                LDMX4T(q0, q1, q2, q3,
                       Bb + (kc + btrow)*QG_XSTR + (n0 + nt2*16)*2 + btcolb);
                bf[2*nt2][0] = q0;   bf[2*nt2][1] = q1;
                bf[2*nt2+1][0] = q2; bf[2*nt2+1][1] = q3;
            }
            #pragma unroll
            for (int mt = 0; mt < 2; mt++)
                #pragma unroll
                for (int nt = 0; nt < 4; nt++)
                    MMA_F16(acc[mt][nt], a[mt], bf[nt]);
        }
    }

    __syncthreads();
    if (m < 2) {
        // transpose via fp32 staging [o][n] stride 68 (reuses XH/XL area)
        float* Hst = (float*)smem;
        #pragma unroll
        for (int mt = 0; mt < 2; mt++) {
            int ob = o0 + mt*16 + (lane >> 2);
            float b0 = bb[ob], b1 = bb[ob + 8];
            #pragma unroll
            for (int nt = 0; nt < 4; nt++) {
                int n = n0 + nt*8 + (lane & 3)*2;
                *(float2*)(Hst + ob*68 + n)     = make_float2(acc[mt][nt][0] + b0, acc[mt][nt][1] + b0);
                *(float2*)(Hst + (ob+8)*68 + n) = make_float2(acc[mt][nt][2] + b1, acc[mt][nt][3] + b1);
            }
        }
        __syncthreads();
        __half* dq = (m == 0 ? g_qT : g_kT) + (size_t)b*NV*CC;
        int i = tid & 63, ch = (tid >> 6) * 32;
        uint32_t pk[16];
        #pragma unroll
        for (int u = 0; u < 16; u++) {
            float v0 = Hst[(ch + 2*u)*68 + i];
            float v1 = Hst[(ch + 2*u + 1)*68 + i];
            pk[u] = pack_h2(v0, v1);
        }
        #pragma unroll
        for (int u = 0; u < 4; u++)
            *(uint4*)(dq + (size_t)(n0g + i)*CC + ch + u*8) =
                make_uint4(pk[4*u], pk[4*u+1], pk[4*u+2], pk[4*u+3]);
    } else {
        __half* dv = g_vh + (size_t)b*CC*NV;
        #pragma unroll
        for (int mt = 0; mt < 2; mt++) {
            int ob = o0 + mt*16 + (lane >> 2);
            float b0 = bb[ob], b1 = bb[ob + 8];
            #pragma unroll
            for (int nt = 0; nt < 4; nt++) {
                int n = n0g + n0 + nt*8 + (lane & 3)*2;
                *(uint32_t*)(dv + (size_t)ob*NV + n)     = pack_h2(acc[mt][nt][0] + b0, acc[mt][nt][1] + b0);
                *(uint32_t*)(dv + (size_t)(ob+8)*NV + n) = pack_h2(acc[mt][nt][2] + b1, acc[mt][nt][3] + b1);
            }
        }
    }
}

// ---------------- 4) fused flash attention (fp16 HMMA) ----------
// grid (NV/32, NB), 128 thr = 4 warps, 2 CTAs/SM.
// V tile carries a ones-channel (row 128) so PV computes row sums of
// P (the softmax normalizer l) as acc[16] -- no shfl reduction.
#define FB_QSTR 272
#define FB_VSTR 144
#define FB_Q    8704          // Q area (32*272)
#define FB_VOFF 17408         // V within buffer (K is 64*272)
#define FB_BUFSZ 38144        // K 17408 + V 144rows*144 = 20736
#define FB_SMEM (FB_Q + 2*FB_BUFSZ)   // 85  KB -> 2 CTAs/SM

__global__ void __launch_bounds__(128, 2) fattn_kernel()
{
    extern __shared__ char smem[];
    uint32_t sb = smem_u32(smem);
    int tid = threadIdx.x, wid = tid >> 5, lane = tid & 31;
    int b = blockIdx.y, i0 = blockIdx.x * 32;

    const __half* Qp = g_qT + (size_t)b*NV*CC + (size_t)i0*CC;
    const __half* Kh = g_kT + (size_t)b*NV*CC;
    const __half* Vh = g_vh + (size_t)b*CC*NV;

    // ---- prologue: Q (group 0), chunk 0 (group 1)
    for (int idx = tid; idx < 512; idx += 128) {
        int row = idx >> 4, c = idx & 15;
        CP_ASYNC16(sb + row*FB_QSTR + c*16, Qp + (size_t)row*CC + c*8);
    }
    CP_COMMIT();
    {
        uint32_t base = sb + FB_Q;
        for (int idx = tid; idx < 1024; idx += 128) {
            int row = idx >> 4, c = idx & 15;
            CP_ASYNC16(base + row*FB_QSTR + c*16, Kh + (size_t)row*CC + c*8);
        }
        for (int idx = tid; idx < 1024; idx += 128) {
            int row = idx >> 3, c = idx & 7;
            CP_ASYNC16(base + FB_VOFF + row*FB_VSTR + c*16, Vh + (size_t)row*NV + c*8);
        }
        CP_COMMIT();
    }
    // ---- init V pad rows 128..143 (row 128 = ones) in both buffers
    for (int idx = tid; idx < 1152; idx += 128) {
        int bufi = (idx >= 576) ? 1 : 0;
        int rem  = idx - bufi*576;
        int r    = 128 + rem/36;
        int w4   = rem % 36;
        uint32_t val = (r == 128 && w4 < 32) ? 0x3C003C00u : 0u;
        *(uint32_t*)(smem + FB_Q + bufi*FB_BUFSZ + FB_VOFF + r*FB_VSTR + w4*4) = val;
    }

    int ig = (wid & 1) * 16;
    int half = wid >> 1;
    int jh = half * 32;
    int arow = lane & 15, acol = (lane >> 4) << 3;
    int bm = lane >> 3;
    int brow = ((bm >> 1) << 3) + (lane & 7);
    int bcol = (bm & 1) << 3;
    int qgrp = lane & 3;
    int lr = ig + (lane >> 2);

    // ---- wait for Q, hoist Q fragments
    CP_WAIT1();
    __syncthreads();
    uint32_t qf[8][4];
    #pragma unroll
    for (int k = 0; k < 8; k++) {
        uint32_t ad = sb + (ig + arow)*FB_QSTR + (k*16 + acol)*2;
        LDMX4(qf[k][0], qf[k][1], qf[k][2], qf[k][3], ad);
    }

    float acc[17][4];
    #pragma unroll
    for (int nt = 0; nt < 17; nt++)
        #pragma unroll
        for (int e = 0; e < 4; e++) acc[nt][e] = 0.f;
    float m0 = -1e30f, m1 = -1e30f;

    for (int t = 0; t < 64; t++) {
        uint32_t base = sb + FB_Q + (uint32_t)(t & 1)*FB_BUFSZ;
        CP_WAIT0();
        __syncthreads();
        if (t + 1 < 64) {
            uint32_t nb = sb + FB_Q + (uint32_t)((t + 1) & 1)*FB_BUFSZ;
            int j0 = (t + 1) * 64;
            for (int idx = tid; idx < 1024; idx += 128) {
                int row = idx >> 4, c = idx & 15;
                CP_ASYNC16(nb + row*FB_QSTR + c*16,
                           Kh + (size_t)(j0 + row)*CC + c*8);
            }
            for (int idx = tid; idx < 1024; idx += 128) {
                int row = idx >> 3, c = idx & 7;
                CP_ASYNC16(nb + FB_VOFF + row*FB_VSTR + c*16,
                           Vh + (size_t)row*NV + j0 + c*8);
            }
            CP_COMMIT();
        }

        // ---- QK: S (16 x 32), single fp16 pass
        float s[4][4];
        #pragma unroll
        for (int nt = 0; nt < 4; nt++)
            #pragma unroll
            for (int e = 0; e < 4; e++) s[nt][e] = 0.f;
        #pragma unroll
        for (int k = 0; k < 8; k++) {
            uint32_t bh[4][2];
            #pragma unroll
            for (int ntp = 0; ntp < 2; ntp++) {
                uint32_t q0, q1, q2, q3;
                LDMX4(q0, q1, q2, q3,
                      base + (jh + ntp*16 + brow)*FB_QSTR + (k*16 + bcol)*2);
                bh[2*ntp][0] = q0;   bh[2*ntp][1] = q1;
                bh[2*ntp+1][0] = q2; bh[2*ntp+1][1] = q3;
            }
            #pragma unroll
            for (int nt = 0; nt < 4; nt++)
                MMA_F16(s[nt], qf[k], bh[nt]);
        }

        // ---- warp-local online softmax (no l reduction needed)
        float mx0 = -1e30f, mx1 = -1e30f;
        #pragma unroll
        for (int nt = 0; nt < 4; nt++) {
            mx0 = fmaxf(mx0, fmaxf(s[nt][0], s[nt][1]));
            mx1 = fmaxf(mx1, fmaxf(s[nt][2], s[nt][3]));
        }
        mx0 = fmaxf(mx0, __shfl_xor_sync(0xffffffffu, mx0, 1));
        mx0 = fmaxf(mx0, __shfl_xor_sync(0xffffffffu, mx0, 2));
        mx1 = fmaxf(mx1, __shfl_xor_sync(0xffffffffu, mx1, 1));
        mx1 = fmaxf(mx1, __shfl_xor_sync(0xffffffffu, mx1, 2));
        bool upd = (mx0 > m0) || (mx1 > m1);
        if (__any_sync(0xffffffffu, upd)) {
            float mn0 = fmaxf(m0, mx0), mn1 = fmaxf(m1, mx1);
            float al0 = exp2f(m0 - mn0), al1 = exp2f(m1 - mn1);
            m0 = mn0; m1 = mn1;
            #pragma unroll
            for (int nt = 0; nt < 17; nt++) {
                acc[nt][0] *= al0; acc[nt][1] *= al0;
                acc[nt][2] *= al1; acc[nt][3] *= al1;
            }
        }
        #pragma unroll
        for (int nt = 0; nt < 4; nt++) {
            s[nt][0] = exp2f(s[nt][0] - m0);
            s[nt][1] = exp2f(s[nt][1] - m0);
            s[nt][2] = exp2f(s[nt][2] - m1);
            s[nt][3] = exp2f(s[nt][3] - m1);
        }

        // ---- P -> fp16 A-fragments
        uint32_t ah[2][4];
        #pragma unroll
        for (int kb = 0; kb < 2; kb++) {
            int tA = 2*kb, tB = 2*kb + 1;
            ah[kb][0] = pack_h2(s[tA][0], s[tA][1]);
            ah[kb][1] = pack_h2(s[tA][2], s[tA][3]);
            ah[kb][2] = pack_h2(s[tB][0], s[tB][1]);
            ah[kb][3] = pack_h2(s[tB][2], s[tB][3]);
        }

        // ---- PV: acc += P @ V^T incl. ones-channel (nt 16 = l)
        #pragma unroll
        for (int kb = 0; kb < 2; kb++) {
            int kc = jh + kb*16;
            uint32_t bf2[18][2];
            #pragma unroll
            for (int ntp = 0; ntp < 9; ntp++) {
                uint32_t q0, q1, q2, q3;
                LDMX4(q0, q1, q2, q3,
                      base + FB_VOFF + (ntp*16 + brow)*FB_VSTR + (kc + bcol)*2);
                bf2[2*ntp][0] = q0;   bf2[2*ntp][1] = q1;
                bf2[2*ntp+1][0] = q2; bf2[2*ntp+1][1] = q3;
            }
            #pragma unroll
            for (int nt = 0; nt < 17; nt++)
                MMA_F16(acc[nt], ah[kb], bf2[nt]);
        }
    }

    // ---- recover l from the ones-channel, merge j-half partials
    int lsrc = lane & ~3;
    float l0 = __shfl_sync(0xffffffffu, acc[16][0], lsrc);
    float l1 = __shfl_sync(0xffffffffu, acc[16][2], lsrc);

    __syncthreads();
    float* ms   = (float*)(smem + FB_Q);
    float* ls   = (float*)(smem + FB_Q + 128);
    float* Hred = (float*)(smem + FB_Q + 256);
    if (half) {
        if (qgrp == 0) {
            ms[lr] = m0;   ls[lr] = l0;
            ms[lr+8] = m1; ls[lr+8] = l1;
        }
        #pragma unroll
        for (int nt = 0; nt < 16; nt++) {
            Hred[lr*128 + nt*8 + qgrp*2]         = acc[nt][0];
            Hred[lr*128 + nt*8 + qgrp*2 + 1]     = acc[nt][1];
            Hred[(lr+8)*128 + nt*8 + qgrp*2]     = acc[nt][2];
            Hred[(lr+8)*128 + nt*8 + qgrp*2 + 1] = acc[nt][3];
        }
    }
    __syncthreads();
    if (!half) {
        float mo0 = ms[lr],   lo0 = ls[lr];
        float mo1 = ms[lr+8], lo1 = ls[lr+8];
        float mt0 = fmaxf(m0, mo0), mt1 = fmaxf(m1, mo1);
        float sA0 = exp2f(m0 - mt0), sB0 = exp2f(mo0 - mt0);
        float sA1 = exp2f(m1 - mt1), sB1 = exp2f(mo1 - mt1);
        float inv0 = 1.f / (l0*sA0 + lo0*sB0);
        float inv1 = 1.f / (l1*sA1 + lo1*sB1);
        float* H = g_hT + (size_t)b*NV*CC;
        #pragma unroll
        for (int nt = 0; nt < 16; nt++) {
            float h0 = (acc[nt][0]*sA0 + Hred[lr*128 + nt*8 + qgrp*2]*sB0)         * inv0;
            float h1 = (acc[nt][1]*sA0 + Hred[lr*128 + nt*8 + qgrp*2 + 1]*sB0)     * inv0;
            float h2 = (acc[nt][2]*sA1 + Hred[(lr+8)*128 + nt*8 + qgrp*2]*sB1)     * inv1;
            float h3 = (acc[nt][3]*sA1 + Hred[(lr+8)*128 + nt*8 + qgrp*2 + 1]*sB1) * inv1;
            *(float2*)(H + (size_t)(i0 + lr)*CC + nt*8 + qgrp*2)     = make_float2(h0, h1);
            *(float2*)(H + (size_t)(i0 + lr + 8)*CC + nt*8 + qgrp*2) = make_float2(h2, h3);
        }
    }
}

// ---------------- 5) output projection + residual ---------------
__global__ void proj_kernel(const float* __restrict__ inp,
                            const float* __restrict__ Wo,
                            const float* __restrict__ bo,
                            float* __restrict__ outp)
{
    extern __shared__ float sm[];
    float* Ws = sm;
    float* xs = sm + CC*CC;
    int b = blockIdx.y;
    int n0 = blockIdx.x * 64;
    int tid = threadIdx.x;

    for (int i = tid; i < CC*CC/4; i += 256) {
        int o  = i >> 5;
        int c4 = (i & 31) << 2;
        float4 w = *(const float4*)(Wo + o*CC + c4);
        Ws[(c4+0)*CC + o] = w.x;
        Ws[(c4+1)*CC + o] = w.y;
        Ws[(c4+2)*CC + o] = w.z;
        Ws[(c4+3)*CC + o] = w.w;
    }
    const float* hsrc = g_hT + (size_t)b*NV*CC;
    for (int i = tid; i < 64*32; i += 256) {
        int j  = i >> 5;
        int c4 = (i & 31) << 2;
        float4 h4 = *(const float4*)(hsrc + (size_t)(n0 + j)*CC + c4);
        xs[(c4+0)*64 + j] = h4.x;
        xs[(c4+1)*64 + j] = h4.y;
        xs[(c4+2)*64 + j] = h4.z;
        xs[(c4+3)*64 + j] = h4.w;
    }
    __syncthreads();

    int oy = tid >> 4;
    int nx = tid & 15;
    float acc[8][4];
    #pragma unroll
    for (int u = 0; u < 8; u++)
        #pragma unroll
        for (int v = 0; v < 4; v++) acc[u][v] = 0.f;

    #pragma unroll 4
    for (int c = 0; c < CC; c++) {
        float4 w0 = *(float4*)(Ws + c*CC + oy*8);
        float4 w1 = *(float4*)(Ws + c*CC + oy*8 + 4);
        float4 x4 = *(float4*)(xs + c*64 + nx*4);
        float wv[8] = {w0.x, w0.y, w0.z, w0.w, w1.x, w1.y, w1.z, w1.w};
        float xv[4] = {x4.x, x4.y, x4.z, x4.w};
        #pragma unroll
        for (int u = 0; u < 8; u++)
            #pragma unroll
            for (int v = 0; v < 4; v++) acc[u][v] += wv[u] * xv[v];
    }

    #pragma unroll
    for (int u = 0; u < 8; u++) {
        int o = oy*8 + u;
        float bias = bo[o];
        float4 r0 = *(const float4*)(inp + ((size_t)b*CC + o)*NV + n0 + nx*4);
        float4 r = make_float4(acc[u][0] + bias + r0.x,
                               acc[u][1] + bias + r0.y,
                               acc[u][2] + bias + r0.z,
                               acc[u][3] + bias + r0.w);
        *(float4*)(outp + ((size_t)b*CC + o)*NV + n0 + nx*4) = r;
    }
}

// ---------------- launch ----------------------------------------
extern "C" void kernel_launch(void* const* d_in, const int* in_sizes, int n_in,
                              void* d_out, int out_size)
{
    const float* inp   = (const float*)d_in[0];
    const float* gamma = (const float*)d_in[1];
    const float* beta  = (const float*)d_in[2];
    const float* Wq    = (const float*)d_in[3];
    const float* bq    = (const float*)d_in[4];
    const float* Wk    = (const float*)d_in[5];
    const float* bk    = (const float*)d_in[6];
    const float* Wv    = (const float*)d_in[7];
    const float* bv    = (const float*)d_in[8];
    const float* Wo    = (const float*)d_in[9];
    const float* bo    = (const float*)d_in[10];
    float* outp = (float*)d_out;

    int gemm_smem = (CC*CC + CC*64) * (int)sizeof(float);   // 96 KB
    cudaFuncSetAttribute(qkv_kernel,   cudaFuncAttributeMaxDynamicSharedMemorySize, QG_SMEM);
    cudaFuncSetAttribute(proj_kernel,  cudaFuncAttributeMaxDynamicSharedMemorySize, gemm_smem);
    cudaFuncSetAttribute(fattn_kernel, cudaFuncAttributeMaxDynamicSharedMemorySize, FB_SMEM);

    stats_kernel<<<CC, 256>>>(inp, gamma, beta);
    fold_kernel<<<3*CC, CC>>>(Wq, bq, Wk, bk, Wv, bv);
    qkv_kernel<<<dim3(NV/64, 3, NB), 256, QG_SMEM>>>(inp);
    fattn_kernel<<<dim3(NV/32, NB), 128, FB_SMEM>>>();
    proj_kernel<<<dim3(NV/64, NB), 256, gemm_smem>>>(inp, Wo, bo, outp);
}

// round 16
// speedup vs baseline: 10.9423x; 1.1570x over previous
#include <cuda_runtime.h>
#include <cuda_fp16.h>
#include <math.h>
#include <stdint.h>

#define CC   128
#define NV   4096
#define NB   2
#define EPSF 1e-5f

// ---------------- scratch (no allocation allowed) ----------------
__device__ float2 g_part[NB*CC];      // per (b,c) partial (sum, sumsq)
__device__ __half g_W16h[4*CC*CC];    // folded W' fp16 hi, [m][o][c] (m=3: Wo)
__device__ __half g_W16l[4*CC*CC];    // folded W' fp16 lo
__device__ float g_bq[CC];
__device__ float g_bk[CC];
__device__ float g_bv[CC];
__device__ __half g_hTh[NB*NV*CC];    // attention out hi/lo fp16, [b][i][c]
__device__ __half g_hTl[NB*NV*CC];
__device__ __half g_qT[NB*NV*CC];     // q^T fp16, [b][i][c]
__device__ __half g_kT[NB*NV*CC];     // k^T fp16, [b][i][c]
__device__ __half g_vh[NB*CC*NV];     // v fp16, natural [b][c][n]

// ---------------- PTX helpers (compute_80-era only!) -------------
__device__ __forceinline__ uint32_t smem_u32(const void* p) {
    uint32_t a;
    asm("{ .reg .u64 t; cvta.to.shared.u64 t, %1; cvt.u32.u64 %0, t; }"
        : "=r"(a) : "l"(p));
    return a;
}
#define LDMX4(r0,r1,r2,r3,addr) \
    asm volatile("ldmatrix.sync.aligned.m8n8.x4.shared.b16 {%0,%1,%2,%3}, [%4];" \
                 : "=r"(r0),"=r"(r1),"=r"(r2),"=r"(r3) : "r"(addr))
#define LDMX4T(r0,r1,r2,r3,addr) \
    asm volatile("ldmatrix.sync.aligned.m8n8.x4.trans.shared.b16 {%0,%1,%2,%3}, [%4];" \
                 : "=r"(r0),"=r"(r1),"=r"(r2),"=r"(r3) : "r"(addr))
#define MMA_F16(c,a,b) \
    asm volatile("mma.sync.aligned.m16n8k16.row.col.f32.f16.f16.f32 " \
                 "{%0,%1,%2,%3}, {%4,%5,%6,%7}, {%8,%9}, {%0,%1,%2,%3};" \
                 : "+f"((c)[0]),"+f"((c)[1]),"+f"((c)[2]),"+f"((c)[3]) \
                 : "r"((a)[0]),"r"((a)[1]),"r"((a)[2]),"r"((a)[3]), \
                   "r"((b)[0]),"r"((b)[1]))
#define CP_ASYNC16(s,g) \
    asm volatile("cp.async.cg.shared.global [%0], [%1], 16;" :: "r"(s), "l"(g) : "memory")
#define CP_COMMIT()  asm volatile("cp.async.commit_group;" ::: "memory")
#define CP_WAIT1()   asm volatile("cp.async.wait_group 1;" ::: "memory")
#define CP_WAIT0()   asm volatile("cp.async.wait_group 0;" ::: "memory")

__device__ __forceinline__ uint32_t pack_h2(float a, float b) {
    __half2 t = __floats2half2_rn(a, b);
    return *reinterpret_cast<uint32_t*>(&t);
}
__device__ __forceinline__ void split_pack_h(float a, float b, uint32_t& hi, uint32_t& lo) {
    __half ha = __float2half_rn(a), hb = __float2half_rn(b);
    __half2 H; H.x = ha; H.y = hb;
    hi = *reinterpret_cast<uint32_t*>(&H);
    lo = pack_h2(a - __half2float(ha), b - __half2float(hb));
}

// ---------------- 1) partial batch stats (contiguous rows) ------
__global__ void stats_kernel(const float* __restrict__ inp)
{
    int c = blockIdx.x, b = blockIdx.y;
    int tid = threadIdx.x;
    const float* p = inp + ((size_t)b*CC + c)*NV;
    float s = 0.f, ss = 0.f;
    #pragma unroll
    for (int r = 0; r < 4; r++) {
        float4 a = *(const float4*)(p + (tid + 256*r)*4);
        s  += a.x + a.y + a.z + a.w;
        ss += a.x*a.x + a.y*a.y + a.z*a.z + a.w*a.w;
    }
    #pragma unroll
    for (int off = 16; off; off >>= 1) {
        s  += __shfl_xor_sync(0xffffffffu, s, off);
        ss += __shfl_xor_sync(0xffffffffu, ss, off);
    }
    __shared__ float sb[8], ssb[8];
    int w = tid >> 5;
    if ((tid & 31) == 0) { sb[w] = s; ssb[w] = ss; }
    __syncthreads();
    if (tid == 0) {
        float ts = 0.f, tss = 0.f;
        #pragma unroll
        for (int i = 0; i < 8; i++) { ts += sb[i]; tss += ssb[i]; }
        g_part[b*CC + c] = make_float2(ts, tss);
    }
}

// ---------------- 2) fold BN into weights + fp16 split ----------
// m=0 q (BN+scale+log2e), m=1 k (BN), m=2 v (BN), m=3 o (no fold)
__global__ void fold_kernel(const float* __restrict__ gamma, const float* __restrict__ beta,
                            const float* __restrict__ Wq, const float* __restrict__ bq,
                            const float* __restrict__ Wk, const float* __restrict__ bk,
                            const float* __restrict__ Wv, const float* __restrict__ bv,
                            const float* __restrict__ Wo)
{
    int m = blockIdx.x >> 7;
    int o = blockIdx.x & 127;
    int c = threadIdx.x;
    float2 p0 = g_part[c], p1 = g_part[CC + c];
    const float inv = 1.f / (float)(NB * NV);
    float mean = (p0.x + p1.x) * inv;
    float var  = (p0.y + p1.y) * inv - mean * mean;
    float a  = gamma[c] * rsqrtf(var + EPSF);
    float dd = beta[c] - mean * a;

    if (m == 3) {
        float wp = Wo[o*CC + c];
        __half h = __float2half_rn(wp);
        g_W16h[3*CC*CC + o*CC + c] = h;
        g_W16l[3*CC*CC + o*CC + c] = __float2half_rn(wp - __half2float(h));
        return;
    }
    const float QSC = 1.44269504088896341f * 0.0883883476483184406f;
    const float* W; const float* bs; float* bd; float sc;
    if (m == 0)      { W = Wq; bs = bq; bd = g_bq; sc = QSC; }
    else if (m == 1) { W = Wk; bs = bk; bd = g_bk; sc = 1.f; }
    else             { W = Wv; bs = bv; bd = g_bv; sc = 1.f; }
    float w = W[o*CC + c];
    float wp = w * a * sc;
    __half h = __float2half_rn(wp);
    g_W16h[m*CC*CC + o*CC + c] = h;
    g_W16l[m*CC*CC + o*CC + c] = __float2half_rn(wp - __half2float(h));
    float part = w * dd;
    #pragma unroll
    for (int off = 16; off; off >>= 1)
        part += __shfl_xor_sync(0xffffffffu, part, off);
    __shared__ float pb[4];
    if ((c & 31) == 0) pb[c >> 5] = part;
    __syncthreads();
    if (c == 0) bd[o] = (bs[o] + pb[0] + pb[1] + pb[2] + pb[3]) * sc;
}

// ---------------- 3) QKV GEMM via HMMA (fp16 split x3) ----------
#define QG_XH   0
#define QG_XL   18432
#define QG_WH   36864
#define QG_WL   71680
#define QG_SMEM 106496
#define QG_XSTR 144
#define QG_WSTR 272

__global__ void __launch_bounds__(256, 2) qkv_kernel(const float* __restrict__ inp)
{
    extern __shared__ char smem[];
    uint32_t sb = smem_u32(smem);
    int m = blockIdx.y, b = blockIdx.z;
    int n0g = blockIdx.x * 64;
    int tid = threadIdx.x, wid = tid >> 5, lane = tid & 31;
    const __half* Wh = g_W16h + (size_t)m*CC*CC;
    const __half* Wl = g_W16l + (size_t)m*CC*CC;
    const float* bb = (m == 0) ? g_bq : (m == 1) ? g_bk : g_bv;

    for (int idx = tid; idx < 2048; idx += 256) {
        int r = idx >> 4, c16 = idx & 15;
        CP_ASYNC16(sb + QG_WH + r*QG_WSTR + c16*16, Wh + (size_t)r*CC + c16*8);
        CP_ASYNC16(sb + QG_WL + r*QG_WSTR + c16*16, Wl + (size_t)r*CC + c16*8);
    }
    CP_COMMIT();

    {
        const float* xg = inp + (size_t)b*CC*NV + n0g;
        int c = tid >> 1, nh2 = (tid & 1) * 32;
        #pragma unroll
        for (int i = 0; i < 8; i++) {
            float4 v = *(const float4*)(xg + (size_t)c*NV + nh2 + i*4);
            uint32_t h0, l0, h1, l1;
            split_pack_h(v.x, v.y, h0, l0);
            split_pack_h(v.z, v.w, h1, l1);
            *(uint2*)(smem + QG_XH + c*QG_XSTR + (nh2 + i*4)*2) = make_uint2(h0, h1);
            *(uint2*)(smem + QG_XL + c*QG_XSTR + (nh2 + i*4)*2) = make_uint2(l0, l1);
        }
    }
    CP_WAIT0();
    __syncthreads();

    int og = wid >> 1, nh = wid & 1;
    int o0 = og * 32, n0 = nh * 32;
    int arow = lane & 15, acol = (lane >> 4) << 3;
    int btrow = ((lane >> 3) & 1)*8 + (lane & 7);
    int btcolb = (lane >> 4) * 16;

    float acc[2][4][4];
    #pragma unroll
    for (int mt = 0; mt < 2; mt++)
        #pragma unroll
        for (int nt = 0; nt < 4; nt++)
            #pragma unroll
            for (int e = 0; e < 4; e++) acc[mt][nt][e] = 0.f;

    #pragma unroll
    for (int pass = 0; pass < 3; pass++) {
        uint32_t Ab = sb + (pass == 1 ? QG_WL : QG_WH);
        uint32_t Bb = sb + (pass == 2 ? QG_XL : QG_XH);
        #pragma unroll
        for (int k = 0; k < 8; k++) {
            int kc = k * 16;
            uint32_t a[2][4];
            #pragma unroll
            for (int mt = 0; mt < 2; mt++)
                LDMX4(a[mt][0], a[mt][1], a[mt][2], a[mt][3],
                      Ab + (o0 + mt*16 + arow)*QG_WSTR + (kc + acol)*2);
            uint32_t bf[4][2];
            #pragma unroll
            for (int nt2 = 0; nt2 < 2; nt2++) {
                uint32_t q0, q1, q2, q3;
                LDMX4T(q0, q1, q2, q3,
                       Bb + (kc + btrow)*QG_XSTR + (n0 + nt2*16)*2 + btcolb);
                bf[2*nt2][0] = q0;   bf[2*nt2][1] = q1;
                bf[2*nt2+1][0] = q2; bf[2*nt2+1][1] = q3;
            }
            #pragma unroll
            for (int mt = 0; mt < 2; mt++)
                #pragma unroll
                for (int nt = 0; nt < 4; nt++)
                    MMA_F16(acc[mt][nt], a[mt], bf[nt]);
        }
    }

    __syncthreads();
    if (m < 2) {
        float* Hst = (float*)smem;
        #pragma unroll
        for (int mt = 0; mt < 2; mt++) {
            int ob = o0 + mt*16 + (lane >> 2);
            float b0 = bb[ob], b1 = bb[ob + 8];
            #pragma unroll
            for (int nt = 0; nt < 4; nt++) {
                int n = n0 + nt*8 + (lane & 3)*2;
                *(float2*)(Hst + ob*68 + n)     = make_float2(acc[mt][nt][0] + b0, acc[mt][nt][1] + b0);
                *(float2*)(Hst + (ob+8)*68 + n) = make_float2(acc[mt][nt][2] + b1, acc[mt][nt][3] + b1);
            }
        }
        __syncthreads();
        __half* dq = (m == 0 ? g_qT : g_kT) + (size_t)b*NV*CC;
        int i = tid & 63, ch = (tid >> 6) * 32;
        uint32_t pk[16];
        #pragma unroll
        for (int u = 0; u < 16; u++) {
            float v0 = Hst[(ch + 2*u)*68 + i];
            float v1 = Hst[(ch + 2*u + 1)*68 + i];
            pk[u] = pack_h2(v0, v1);
        }
        #pragma unroll
        for (int u = 0; u < 4; u++)
            *(uint4*)(dq + (size_t)(n0g + i)*CC + ch + u*8) =
                make_uint4(pk[4*u], pk[4*u+1], pk[4*u+2], pk[4*u+3]);
    } else {
        __half* dv = g_vh + (size_t)b*CC*NV;
        #pragma unroll
        for (int mt = 0; mt < 2; mt++) {
            int ob = o0 + mt*16 + (lane >> 2);
            float b0 = bb[ob], b1 = bb[ob + 8];
            #pragma unroll
            for (int nt = 0; nt < 4; nt++) {
                int n = n0g + n0 + nt*8 + (lane & 3)*2;
                *(uint32_t*)(dv + (size_t)ob*NV + n)     = pack_h2(acc[mt][nt][0] + b0, acc[mt][nt][1] + b0);
                *(uint32_t*)(dv + (size_t)(ob+8)*NV + n) = pack_h2(acc[mt][nt][2] + b1, acc[mt][nt][3] + b1);
            }
        }
    }
}

// ---------------- 4) fused flash attention (fp16 HMMA) ----------
#define FB_QSTR 272
#define FB_VSTR 144
#define FB_Q    8704
#define FB_VOFF 17408
#define FB_BUFSZ 38144
#define FB_SMEM (FB_Q + 2*FB_BUFSZ)

__global__ void __launch_bounds__(128, 2) fattn_kernel()
{
    extern __shared__ char smem[];
    uint32_t sb = smem_u32(smem);
    int tid = threadIdx.x, wid = tid >> 5, lane = tid & 31;
    int b = blockIdx.y, i0 = blockIdx.x * 32;

    const __half* Qp = g_qT + (size_t)b*NV*CC + (size_t)i0*CC;
    const __half* Kh = g_kT + (size_t)b*NV*CC;
    const __half* Vh = g_vh + (size_t)b*CC*NV;

    for (int idx = tid; idx < 512; idx += 128) {
        int row = idx >> 4, c = idx & 15;
        CP_ASYNC16(sb + row*FB_QSTR + c*16, Qp + (size_t)row*CC + c*8);
    }
    CP_COMMIT();
    {
        uint32_t base = sb + FB_Q;
        for (int idx = tid; idx < 1024; idx += 128) {
            int row = idx >> 4, c = idx & 15;
            CP_ASYNC16(base + row*FB_QSTR + c*16, Kh + (size_t)row*CC + c*8);
        }
        for (int idx = tid; idx < 1024; idx += 128) {
            int row = idx >> 3, c = idx & 7;
            CP_ASYNC16(base + FB_VOFF + row*FB_VSTR + c*16, Vh + (size_t)row*NV + c*8);
        }
        CP_COMMIT();
    }
    // V pad rows 128..143 (row 128 = ones)
    for (int idx = tid; idx < 1152; idx += 128) {
        int bufi = (idx >= 576) ? 1 : 0;
        int rem  = idx - bufi*576;
        int r    = 128 + rem/36;
        int w4   = rem % 36;
        uint32_t val = (r == 128 && w4 < 32) ? 0x3C003C00u : 0u;
        *(uint32_t*)(smem + FB_Q + bufi*FB_BUFSZ + FB_VOFF + r*FB_VSTR + w4*4) = val;
    }

    int ig = (wid & 1) * 16;
    int half = wid >> 1;
    int jh = half * 32;
    int arow = lane & 15, acol = (lane >> 4) << 3;
    int bm = lane >> 3;
    int brow = ((bm >> 1) << 3) + (lane & 7);
    int bcol = (bm & 1) << 3;
    int qgrp = lane & 3;
    int lr = ig + (lane >> 2);

    CP_WAIT1();
    __syncthreads();
    uint32_t qf[8][4];
    #pragma unroll
    for (int k = 0; k < 8; k++) {
        uint32_t ad = sb + (ig + arow)*FB_QSTR + (k*16 + acol)*2;
        LDMX4(qf[k][0], qf[k][1], qf[k][2], qf[k][3], ad);
    }

    float acc[17][4];
    #pragma unroll
    for (int nt = 0; nt < 17; nt++)
        #pragma unroll
        for (int e = 0; e < 4; e++) acc[nt][e] = 0.f;
    float m0 = -1e30f, m1 = -1e30f;

    #pragma unroll 2
    for (int t = 0; t < 64; t++) {
        uint32_t base = sb + FB_Q + (uint32_t)(t & 1)*FB_BUFSZ;
        CP_WAIT0();
        __syncthreads();
        if (t + 1 < 64) {
            uint32_t nb = sb + FB_Q + (uint32_t)((t + 1) & 1)*FB_BUFSZ;
            int j0 = (t + 1) * 64;
            for (int idx = tid; idx < 1024; idx += 128) {
                int row = idx >> 4, c = idx & 15;
                CP_ASYNC16(nb + row*FB_QSTR + c*16,
                           Kh + (size_t)(j0 + row)*CC + c*8);
            }
            for (int idx = tid; idx < 1024; idx += 128) {
                int row = idx >> 3, c = idx & 7;
                CP_ASYNC16(nb + FB_VOFF + row*FB_VSTR + c*16,
                           Vh + (size_t)row*NV + j0 + c*8);
            }
            CP_COMMIT();
        }

        float s[4][4];
        #pragma unroll
        for (int nt = 0; nt < 4; nt++)
            #pragma unroll
            for (int e = 0; e < 4; e++) s[nt][e] = 0.f;
        #pragma unroll
        for (int k = 0; k < 8; k++) {
            uint32_t bh[4][2];
            #pragma unroll
            for (int ntp = 0; ntp < 2; ntp++) {
                uint32_t q0, q1, q2, q3;
                LDMX4(q0, q1, q2, q3,
                      base + (jh + ntp*16 + brow)*FB_QSTR + (k*16 + bcol)*2);
                bh[2*ntp][0] = q0;   bh[2*ntp][1] = q1;
                bh[2*ntp+1][0] = q2; bh[2*ntp+1][1] = q3;
            }
            #pragma unroll
            for (int nt = 0; nt < 4; nt++)
                MMA_F16(s[nt], qf[k], bh[nt]);
        }

        float mx0 = -1e30f, mx1 = -1e30f;
        #pragma unroll
        for (int nt = 0; nt < 4; nt++) {
            mx0 = fmaxf(mx0, fmaxf(s[nt][0], s[nt][1]));
            mx1 = fmaxf(mx1, fmaxf(s[nt][2], s[nt][3]));
        }
        mx0 = fmaxf(mx0, __shfl_xor_sync(0xffffffffu, mx0, 1));
        mx0 = fmaxf(mx0, __shfl_xor_sync(0xffffffffu, mx0, 2));
        mx1 = fmaxf(mx1, __shfl_xor_sync(0xffffffffu, mx1, 1));
        mx1 = fmaxf(mx1, __shfl_xor_sync(0xffffffffu, mx1, 2));
        bool upd = (mx0 > m0) || (mx1 > m1);
        if (__any_sync(0xffffffffu, upd)) {
            float mn0 = fmaxf(m0, mx0), mn1 = fmaxf(m1, mx1);
            float al0 = exp2f(m0 - mn0), al1 = exp2f(m1 - mn1);
            m0 = mn0; m1 = mn1;
            #pragma unroll
            for (int nt = 0; nt < 17; nt++) {
                acc[nt][0] *= al0; acc[nt][1] *= al0;
                acc[nt][2] *= al1; acc[nt][3] *= al1;
            }
        }
        #pragma unroll
        for (int nt = 0; nt < 4; nt++) {
            s[nt][0] = exp2f(s[nt][0] - m0);
            s[nt][1] = exp2f(s[nt][1] - m0);
            s[nt][2] = exp2f(s[nt][2] - m1);
            s[nt][3] = exp2f(s[nt][3] - m1);
        }

        uint32_t ah[2][4];
        #pragma unroll
        for (int kb = 0; kb < 2; kb++) {
            int tA = 2*kb, tB = 2*kb + 1;
            ah[kb][0] = pack_h2(s[tA][0], s[tA][1]);
            ah[kb][1] = pack_h2(s[tA][2], s[tA][3]);
            ah[kb][2] = pack_h2(s[tB][0], s[tB][1]);
            ah[kb][3] = pack_h2(s[tB][2], s[tB][3]);
        }

        #pragma unroll
        for (int kb = 0; kb < 2; kb++) {
            int kc = jh + kb*16;
            uint32_t bf2[18][2];
            #pragma unroll
            for (int ntp = 0; ntp < 9; ntp++) {
                uint32_t q0, q1, q2, q3;
                LDMX4(q0, q1, q2, q3,
                      base + FB_VOFF + (ntp*16 + brow)*FB_VSTR + (kc + bcol)*2);
                bf2[2*ntp][0] = q0;   bf2[2*ntp][1] = q1;
                bf2[2*ntp+1][0] = q2; bf2[2*ntp+1][1] = q3;
            }
            #pragma unroll
            for (int nt = 0; nt < 17; nt++)
                MMA_F16(acc[nt], ah[kb], bf2[nt]);
        }
    }

    int lsrc = lane & ~3;
    float l0 = __shfl_sync(0xffffffffu, acc[16][0], lsrc);
    float l1 = __shfl_sync(0xffffffffu, acc[16][2], lsrc);

    __syncthreads();
    float* ms   = (float*)(smem + FB_Q);
    float* ls   = (float*)(smem + FB_Q + 128);
    float* Hred = (float*)(smem + FB_Q + 256);
    if (half) {
        if (qgrp == 0) {
            ms[lr] = m0;   ls[lr] = l0;
            ms[lr+8] = m1; ls[lr+8] = l1;
        }
        #pragma unroll
        for (int nt = 0; nt < 16; nt++) {
            Hred[lr*128 + nt*8 + qgrp*2]         = acc[nt][0];
            Hred[lr*128 + nt*8 + qgrp*2 + 1]     = acc[nt][1];
            Hred[(lr+8)*128 + nt*8 + qgrp*2]     = acc[nt][2];
            Hred[(lr+8)*128 + nt*8 + qgrp*2 + 1] = acc[nt][3];
        }
    }
    __syncthreads();
    if (!half) {
        float mo0 = ms[lr],   lo0 = ls[lr];
        float mo1 = ms[lr+8], lo1 = ls[lr+8];
        float mt0 = fmaxf(m0, mo0), mt1 = fmaxf(m1, mo1);
        float sA0 = exp2f(m0 - mt0), sB0 = exp2f(mo0 - mt0);
        float sA1 = exp2f(m1 - mt1), sB1 = exp2f(mo1 - mt1);
        float inv0 = 1.f / (l0*sA0 + lo0*sB0);
        float inv1 = 1.f / (l1*sA1 + lo1*sB1);
        __half* Hh = g_hTh + (size_t)b*NV*CC;
        __half* Hl = g_hTl + (size_t)b*NV*CC;
        #pragma unroll
        for (int nt = 0; nt < 16; nt++) {
            float h0 = (acc[nt][0]*sA0 + Hred[lr*128 + nt*8 + qgrp*2]*sB0)         * inv0;
            float h1 = (acc[nt][1]*sA0 + Hred[lr*128 + nt*8 + qgrp*2 + 1]*sB0)     * inv0;
            float h2 = (acc[nt][2]*sA1 + Hred[(lr+8)*128 + nt*8 + qgrp*2]*sB1)     * inv1;
            float h3 = (acc[nt][3]*sA1 + Hred[(lr+8)*128 + nt*8 + qgrp*2 + 1]*sB1) * inv1;
            uint32_t hh, hl;
            split_pack_h(h0, h1, hh, hl);
            *(uint32_t*)(Hh + (size_t)(i0 + lr)*CC + nt*8 + qgrp*2) = hh;
            *(uint32_t*)(Hl + (size_t)(i0 + lr)*CC + nt*8 + qgrp*2) = hl;
            split_pack_h(h2, h3, hh, hl);
            *(uint32_t*)(Hh + (size_t)(i0 + lr + 8)*CC + nt*8 + qgrp*2) = hh;
            *(uint32_t*)(Hl + (size_t)(i0 + lr + 8)*CC + nt*8 + qgrp*2) = hl;
        }
    }
}

// ---------------- 5) output projection via HMMA + residual ------
// out[o][n] = sum_c Wo[o][c] * hT[n][c]  + bo + inp   (S-form GEMM)
#define PJ_HH   0
#define PJ_HL   17408
#define PJ_WH   34816
#define PJ_WL   69632
#define PJ_SMEM 104448
#define PJ_STR  272

__global__ void __launch_bounds__(256, 1) proj_kernel(const float* __restrict__ inp,
                                                      const float* __restrict__ bo,
                                                      float* __restrict__ outp)
{
    extern __shared__ char smem[];
    uint32_t sb = smem_u32(smem);
    int b = blockIdx.y;
    int n0g = blockIdx.x * 64;
    int tid = threadIdx.x, wid = tid >> 5, lane = tid & 31;
    const __half* Wh = g_W16h + (size_t)3*CC*CC;
    const __half* Wl = g_W16l + (size_t)3*CC*CC;
    const __half* Hh = g_hTh + (size_t)b*NV*CC;
    const __half* Hl = g_hTl + (size_t)b*NV*CC;

    for (int idx = tid; idx < 2048; idx += 256) {
        int r = idx >> 4, c16 = idx & 15;
        CP_ASYNC16(sb + PJ_WH + r*PJ_STR + c16*16, Wh + (size_t)r*CC + c16*8);
        CP_ASYNC16(sb + PJ_WL + r*PJ_STR + c16*16, Wl + (size_t)r*CC + c16*8);
    }
    for (int idx = tid; idx < 1024; idx += 256) {
        int r = idx >> 4, c16 = idx & 15;
        CP_ASYNC16(sb + PJ_HH + r*PJ_STR + c16*16, Hh + (size_t)(n0g + r)*CC + c16*8);
        CP_ASYNC16(sb + PJ_HL + r*PJ_STR + c16*16, Hl + (size_t)(n0g + r)*CC + c16*8);
    }
    CP_COMMIT();
    CP_WAIT0();
    __syncthreads();

    int og = wid >> 1, nh = wid & 1;
    int o0 = og * 32, n0 = nh * 32;
    int arow = lane & 15, acol = (lane >> 4) << 3;
    int bm = lane >> 3;
    int brow = ((bm >> 1) << 3) + (lane & 7);
    int bcol = (bm & 1) << 3;

    float acc[2][4][4];
    #pragma unroll
    for (int mt = 0; mt < 2; mt++)
        #pragma unroll
        for (int nt = 0; nt < 4; nt++)
            #pragma unroll
            for (int e = 0; e < 4; e++) acc[mt][nt][e] = 0.f;

    #pragma unroll
    for (int pass = 0; pass < 3; pass++) {
        uint32_t Ab = sb + (pass == 1 ? PJ_WL : PJ_WH);
        uint32_t Bb = sb + (pass == 2 ? PJ_HL : PJ_HH);
        #pragma unroll
        for (int k = 0; k < 8; k++) {
            int kc = k * 16;
            uint32_t a[2][4];
            #pragma unroll
            for (int mt = 0; mt < 2; mt++)
                LDMX4(a[mt][0], a[mt][1], a[mt][2], a[mt][3],
                      Ab + (o0 + mt*16 + arow)*PJ_STR + (kc + acol)*2);
            uint32_t bf[4][2];
            #pragma unroll
            for (int ntp = 0; ntp < 2; ntp++) {
                uint32_t q0, q1, q2, q3;
                LDMX4(q0, q1, q2, q3,
                      Bb + (n0 + ntp*16 + brow)*PJ_STR + (kc + bcol)*2);
                bf[2*ntp][0] = q0;   bf[2*ntp][1] = q1;
                bf[2*ntp+1][0] = q2; bf[2*ntp+1][1] = q3;
            }
            #pragma unroll
            for (int mt = 0; mt < 2; mt++)
                #pragma unroll
                for (int nt = 0; nt < 4; nt++)
                    MMA_F16(acc[mt][nt], a[mt], bf[nt]);
        }
    }

    #pragma unroll
    for (int mt = 0; mt < 2; mt++) {
        int ob = o0 + mt*16 + (lane >> 2);
        float b0 = bo[ob], b1 = bo[ob + 8];
        #pragma unroll
        for (int nt = 0; nt < 4; nt++) {
            int n = n0g + n0 + nt*8 + (lane & 3)*2;
            float2 r0 = *(const float2*)(inp + ((size_t)b*CC + ob)*NV + n);
            float2 r1 = *(const float2*)(inp + ((size_t)b*CC + ob + 8)*NV + n);
            *(float2*)(outp + ((size_t)b*CC + ob)*NV + n) =
                make_float2(acc[mt][nt][0] + b0 + r0.x, acc[mt][nt][1] + b0 + r0.y);
            *(float2*)(outp + ((size_t)b*CC + ob + 8)*NV + n) =
                make_float2(acc[mt][nt][2] + b1 + r1.x, acc[mt][nt][3] + b1 + r1.y);
        }
    }
}

// ---------------- launch ----------------------------------------
extern "C" void kernel_launch(void* const* d_in, const int* in_sizes, int n_in,
                              void* d_out, int out_size)
{
    const float* inp   = (const float*)d_in[0];
    const float* gamma = (const float*)d_in[1];
    const float* beta  = (const float*)d_in[2];
    const float* Wq    = (const float*)d_in[3];
    const float* bq    = (const float*)d_in[4];
    const float* Wk    = (const float*)d_in[5];
    const float* bk    = (const float*)d_in[6];
    const float* Wv    = (const float*)d_in[7];
    const float* bv    = (const float*)d_in[8];
    const float* Wo    = (const float*)d_in[9];
    const float* bo    = (const float*)d_in[10];
    float* outp = (float*)d_out;

    cudaFuncSetAttribute(qkv_kernel,   cudaFuncAttributeMaxDynamicSharedMemorySize, QG_SMEM);
    cudaFuncSetAttribute(proj_kernel,  cudaFuncAttributeMaxDynamicSharedMemorySize, PJ_SMEM);
    cudaFuncSetAttribute(fattn_kernel, cudaFuncAttributeMaxDynamicSharedMemorySize, FB_SMEM);

    stats_kernel<<<dim3(CC, NB), 256>>>(inp);
    fold_kernel<<<4*CC, CC>>>(gamma, beta, Wq, bq, Wk, bk, Wv, bv, Wo);
    qkv_kernel<<<dim3(NV/64, 3, NB), 256, QG_SMEM>>>(inp);
    fattn_kernel<<<dim3(NV/32, NB), 128, FB_SMEM>>>();
    proj_kernel<<<dim3(NV/64, NB), 256, PJ_SMEM>>>(inp, bo, outp);
}

// round 17
// speedup vs baseline: 11.8032x; 1.0787x over previous
#include <cuda_runtime.h>
#include <cuda_fp16.h>
#include <math.h>
#include <stdint.h>

#define CC   128
#define NV   4096
#define NB   2
#define EPSF 1e-5f

// ---------------- scratch (no allocation allowed) ----------------
__device__ float2 g_part[NB*CC];      // per (b,c) partial (sum, sumsq)
__device__ __half g_W16h[4*CC*CC];    // folded W' fp16 hi, [m][o][c] (m=3: Wo)
__device__ __half g_W16l[4*CC*CC];    // folded W' fp16 lo
__device__ float g_bq[CC];
__device__ float g_bk[CC];
__device__ float g_bv[CC];
__device__ __half g_hTh[NB*NV*CC];    // attention out hi/lo fp16, [b][i][c]
__device__ __half g_hTl[NB*NV*CC];
__device__ __half g_qT[NB*NV*CC];     // q^T fp16, [b][i][c]
__device__ __half g_kT[NB*NV*CC];     // k^T fp16, [b][i][c]
__device__ __half g_vh[NB*CC*NV];     // v fp16, natural [b][c][n]

// ---------------- PTX helpers (compute_80-era only!) -------------
__device__ __forceinline__ uint32_t smem_u32(const void* p) {
    uint32_t a;
    asm("{ .reg .u64 t; cvta.to.shared.u64 t, %1; cvt.u32.u64 %0, t; }"
        : "=r"(a) : "l"(p));
    return a;
}
#define LDMX4(r0,r1,r2,r3,addr) \
    asm volatile("ldmatrix.sync.aligned.m8n8.x4.shared.b16 {%0,%1,%2,%3}, [%4];" \
                 : "=r"(r0),"=r"(r1),"=r"(r2),"=r"(r3) : "r"(addr))
#define LDMX4T(r0,r1,r2,r3,addr) \
    asm volatile("ldmatrix.sync.aligned.m8n8.x4.trans.shared.b16 {%0,%1,%2,%3}, [%4];" \
                 : "=r"(r0),"=r"(r1),"=r"(r2),"=r"(r3) : "r"(addr))
#define MMA_F16(c,a,b) \
    asm volatile("mma.sync.aligned.m16n8k16.row.col.f32.f16.f16.f32 " \
                 "{%0,%1,%2,%3}, {%4,%5,%6,%7}, {%8,%9}, {%0,%1,%2,%3};" \
                 : "+f"((c)[0]),"+f"((c)[1]),"+f"((c)[2]),"+f"((c)[3]) \
                 : "r"((a)[0]),"r"((a)[1]),"r"((a)[2]),"r"((a)[3]), \
                   "r"((b)[0]),"r"((b)[1]))
#define CP_ASYNC16(s,g) \
    asm volatile("cp.async.cg.shared.global [%0], [%1], 16;" :: "r"(s), "l"(g) : "memory")
#define CP_COMMIT()  asm volatile("cp.async.commit_group;" ::: "memory")
#define CP_WAIT1()   asm volatile("cp.async.wait_group 1;" ::: "memory")
#define CP_WAIT0()   asm volatile("cp.async.wait_group 0;" ::: "memory")

__device__ __forceinline__ uint32_t pack_h2(float a, float b) {
    __half2 t = __floats2half2_rn(a, b);
    return *reinterpret_cast<uint32_t*>(&t);
}
__device__ __forceinline__ void split_pack_h(float a, float b, uint32_t& hi, uint32_t& lo) {
    __half ha = __float2half_rn(a), hb = __float2half_rn(b);
    __half2 H; H.x = ha; H.y = hb;
    hi = *reinterpret_cast<uint32_t*>(&H);
    lo = pack_h2(a - __half2float(ha), b - __half2float(hb));
}

// ---------------- 1) partial batch stats (contiguous rows) ------
__global__ void stats_kernel(const float* __restrict__ inp)
{
    int c = blockIdx.x, b = blockIdx.y;
    int tid = threadIdx.x;
    const float* p = inp + ((size_t)b*CC + c)*NV;
    float s = 0.f, ss = 0.f;
    #pragma unroll
    for (int r = 0; r < 4; r++) {
        float4 a = *(const float4*)(p + (tid + 256*r)*4);
        s  += a.x + a.y + a.z + a.w;
        ss += a.x*a.x + a.y*a.y + a.z*a.z + a.w*a.w;
    }
    #pragma unroll
    for (int off = 16; off; off >>= 1) {
        s  += __shfl_xor_sync(0xffffffffu, s, off);
        ss += __shfl_xor_sync(0xffffffffu, ss, off);
    }
    __shared__ float sb[8], ssb[8];
    int w = tid >> 5;
    if ((tid & 31) == 0) { sb[w] = s; ssb[w] = ss; }
    __syncthreads();
    if (tid == 0) {
        float ts = 0.f, tss = 0.f;
        #pragma unroll
        for (int i = 0; i < 8; i++) { ts += sb[i]; tss += ssb[i]; }
        g_part[b*CC + c] = make_float2(ts, tss);
    }
}

// ---------------- 2) fold BN into weights + fp16 split ----------
__global__ void fold_kernel(const float* __restrict__ gamma, const float* __restrict__ beta,
                            const float* __restrict__ Wq, const float* __restrict__ bq,
                            const float* __restrict__ Wk, const float* __restrict__ bk,
                            const float* __restrict__ Wv, const float* __restrict__ bv,
                            const float* __restrict__ Wo)
{
    int m = blockIdx.x >> 7;
    int o = blockIdx.x & 127;
    int c = threadIdx.x;
    float2 p0 = g_part[c], p1 = g_part[CC + c];
    const float inv = 1.f / (float)(NB * NV);
    float mean = (p0.x + p1.x) * inv;
    float var  = (p0.y + p1.y) * inv - mean * mean;
    float a  = gamma[c] * rsqrtf(var + EPSF);
    float dd = beta[c] - mean * a;

    if (m == 3) {
        float wp = Wo[o*CC + c];
        __half h = __float2half_rn(wp);
        g_W16h[3*CC*CC + o*CC + c] = h;
        g_W16l[3*CC*CC + o*CC + c] = __float2half_rn(wp - __half2float(h));
        return;
    }
    const float QSC = 1.44269504088896341f * 0.0883883476483184406f;
    const float* W; const float* bs; float* bd; float sc;
    if (m == 0)      { W = Wq; bs = bq; bd = g_bq; sc = QSC; }
    else if (m == 1) { W = Wk; bs = bk; bd = g_bk; sc = 1.f; }
    else             { W = Wv; bs = bv; bd = g_bv; sc = 1.f; }
    float w = W[o*CC + c];
    float wp = w * a * sc;
    __half h = __float2half_rn(wp);
    g_W16h[m*CC*CC + o*CC + c] = h;
    g_W16l[m*CC*CC + o*CC + c] = __float2half_rn(wp - __half2float(h));
    float part = w * dd;
    #pragma unroll
    for (int off = 16; off; off >>= 1)
        part += __shfl_xor_sync(0xffffffffu, part, off);
    __shared__ float pb[4];
    if ((c & 31) == 0) pb[c >> 5] = part;
    __syncthreads();
    if (c == 0) bd[o] = (bs[o] + pb[0] + pb[1] + pb[2] + pb[3]) * sc;
}

// ---------------- 3) QKV GEMM via HMMA (fp16 split x3) ----------
#define QG_XH   0
#define QG_XL   18432
#define QG_WH   36864
#define QG_WL   71680
#define QG_SMEM 106496
#define QG_XSTR 144
#define QG_WSTR 272

__global__ void __launch_bounds__(256, 2) qkv_kernel(const float* __restrict__ inp)
{
    extern __shared__ char smem[];
    uint32_t sb = smem_u32(smem);
    int m = blockIdx.y, b = blockIdx.z;
    int n0g = blockIdx.x * 64;
    int tid = threadIdx.x, wid = tid >> 5, lane = tid & 31;
    const __half* Wh = g_W16h + (size_t)m*CC*CC;
    const __half* Wl = g_W16l + (size_t)m*CC*CC;
    const float* bb = (m == 0) ? g_bq : (m == 1) ? g_bk : g_bv;

    for (int idx = tid; idx < 2048; idx += 256) {
        int r = idx >> 4, c16 = idx & 15;
        CP_ASYNC16(sb + QG_WH + r*QG_WSTR + c16*16, Wh + (size_t)r*CC + c16*8);
        CP_ASYNC16(sb + QG_WL + r*QG_WSTR + c16*16, Wl + (size_t)r*CC + c16*8);
    }
    CP_COMMIT();

    {
        const float* xg = inp + (size_t)b*CC*NV + n0g;
        int c = tid >> 1, nh2 = (tid & 1) * 32;
        #pragma unroll
        for (int i = 0; i < 8; i++) {
            float4 v = *(const float4*)(xg + (size_t)c*NV + nh2 + i*4);
            uint32_t h0, l0, h1, l1;
            split_pack_h(v.x, v.y, h0, l0);
            split_pack_h(v.z, v.w, h1, l1);
            *(uint2*)(smem + QG_XH + c*QG_XSTR + (nh2 + i*4)*2) = make_uint2(h0, h1);
            *(uint2*)(smem + QG_XL + c*QG_XSTR + (nh2 + i*4)*2) = make_uint2(l0, l1);
        }
    }
    CP_WAIT0();
    __syncthreads();

    int og = wid >> 1, nh = wid & 1;
    int o0 = og * 32, n0 = nh * 32;
    int arow = lane & 15, acol = (lane >> 4) << 3;
    int btrow = ((lane >> 3) & 1)*8 + (lane & 7);
    int btcolb = (lane >> 4) * 16;

    float acc[2][4][4];
    #pragma unroll
    for (int mt = 0; mt < 2; mt++)
        #pragma unroll
        for (int nt = 0; nt < 4; nt++)
            #pragma unroll
            for (int e = 0; e < 4; e++) acc[mt][nt][e] = 0.f;

    #pragma unroll
    for (int pass = 0; pass < 3; pass++) {
        uint32_t Ab = sb + (pass == 1 ? QG_WL : QG_WH);
        uint32_t Bb = sb + (pass == 2 ? QG_XL : QG_XH);
        #pragma unroll
        for (int k = 0; k < 8; k++) {
            int kc = k * 16;
            uint32_t a[2][4];
            #pragma unroll
            for (int mt = 0; mt < 2; mt++)
                LDMX4(a[mt][0], a[mt][1], a[mt][2], a[mt][3],
                      Ab + (o0 + mt*16 + arow)*QG_WSTR + (kc + acol)*2);
            uint32_t bf[4][2];
            #pragma unroll
            for (int nt2 = 0; nt2 < 2; nt2++) {
                uint32_t q0, q1, q2, q3;
                LDMX4T(q0, q1, q2, q3,
                       Bb + (kc + btrow)*QG_XSTR + (n0 + nt2*16)*2 + btcolb);
                bf[2*nt2][0] = q0;   bf[2*nt2][1] = q1;
                bf[2*nt2+1][0] = q2; bf[2*nt2+1][1] = q3;
            }
            #pragma unroll
            for (int mt = 0; mt < 2; mt++)
                #pragma unroll
                for (int nt = 0; nt < 4; nt++)
                    MMA_F16(acc[mt][nt], a[mt], bf[nt]);
        }
    }

    __syncthreads();
    if (m < 2) {
        float* Hst = (float*)smem;
        #pragma unroll
        for (int mt = 0; mt < 2; mt++) {
            int ob = o0 + mt*16 + (lane >> 2);
            float b0 = bb[ob], b1 = bb[ob + 8];
            #pragma unroll
            for (int nt = 0; nt < 4; nt++) {
                int n = n0 + nt*8 + (lane & 3)*2;
                *(float2*)(Hst + ob*68 + n)     = make_float2(acc[mt][nt][0] + b0, acc[mt][nt][1] + b0);
                *(float2*)(Hst + (ob+8)*68 + n) = make_float2(acc[mt][nt][2] + b1, acc[mt][nt][3] + b1);
            }
        }
        __syncthreads();
        __half* dq = (m == 0 ? g_qT : g_kT) + (size_t)b*NV*CC;
        int i = tid & 63, ch = (tid >> 6) * 32;
        uint32_t pk[16];
        #pragma unroll
        for (int u = 0; u < 16; u++) {
            float v0 = Hst[(ch + 2*u)*68 + i];
            float v1 = Hst[(ch + 2*u + 1)*68 + i];
            pk[u] = pack_h2(v0, v1);
        }
        #pragma unroll
        for (int u = 0; u < 4; u++)
            *(uint4*)(dq + (size_t)(n0g + i)*CC + ch + u*8) =
                make_uint4(pk[4*u], pk[4*u+1], pk[4*u+2], pk[4*u+3]);
    } else {
        __half* dv = g_vh + (size_t)b*CC*NV;
        #pragma unroll
        for (int mt = 0; mt < 2; mt++) {
            int ob = o0 + mt*16 + (lane >> 2);
            float b0 = bb[ob], b1 = bb[ob + 8];
            #pragma unroll
            for (int nt = 0; nt < 4; nt++) {
                int n = n0g + n0 + nt*8 + (lane & 3)*2;
                *(uint32_t*)(dv + (size_t)ob*NV + n)     = pack_h2(acc[mt][nt][0] + b0, acc[mt][nt][1] + b0);
                *(uint32_t*)(dv + (size_t)(ob+8)*NV + n) = pack_h2(acc[mt][nt][2] + b1, acc[mt][nt][3] + b1);
            }
        }
    }
}

// ---------------- 4) fused flash attention (fp16 HMMA) ----------
// grid (NV/64, NB) = 128 CTAs, 256 thr = 8 warps (4 i-groups x 2
// j-halves), 1 CTA/SM. i-tile 64, j-chunk 128, double-buffered.
// Per-warp 16i x 64j. Ones-channel in V row 128 gives l via MMA.
#define FC_STR  272
#define FC_Q    17408                 // Q area (64*272)
#define FC_VOFF 34816                 // V within buffer (K is 128*272)
#define FC_BUFSZ (34816 + 144*272)    // 73984
#define FC_SMEM (FC_Q + 2*FC_BUFSZ)   // 165376

__global__ void __launch_bounds__(256, 1) fattn_kernel()
{
    extern __shared__ char smem[];
    uint32_t sb = smem_u32(smem);
    int tid = threadIdx.x, wid = tid >> 5, lane = tid & 31;
    int b = blockIdx.y, i0 = blockIdx.x * 64;

    const __half* Qp = g_qT + (size_t)b*NV*CC + (size_t)i0*CC;
    const __half* Kh = g_kT + (size_t)b*NV*CC;
    const __half* Vh = g_vh + (size_t)b*CC*NV;

    // ---- prologue: Q (group 0), chunk 0 (group 1)
    for (int idx = tid; idx < 1024; idx += 256) {
        int row = idx >> 4, c = idx & 15;
        CP_ASYNC16(sb + row*FC_STR + c*16, Qp + (size_t)row*CC + c*8);
    }
    CP_COMMIT();
    {
        uint32_t base = sb + FC_Q;
        for (int idx = tid; idx < 2048; idx += 256) {
            int row = idx >> 4, c = idx & 15;
            CP_ASYNC16(base + row*FC_STR + c*16, Kh + (size_t)row*CC + c*8);
        }
        for (int idx = tid; idx < 2048; idx += 256) {
            int row = idx >> 4, c = idx & 15;
            CP_ASYNC16(base + FC_VOFF + row*FC_STR + c*16, Vh + (size_t)row*NV + c*8);
        }
        CP_COMMIT();
    }
    // V pad rows 128..143 in both buffers (row 128 = ones, 128 j wide)
    for (int idx = tid; idx < 2048; idx += 256) {
        int bufi = idx >> 10;
        int rem  = idx & 1023;
        int r    = 128 + (rem >> 6);
        int w4   = rem & 63;
        uint32_t val = (r == 128) ? 0x3C003C00u : 0u;
        *(uint32_t*)(smem + FC_Q + bufi*FC_BUFSZ + FC_VOFF + r*FC_STR + w4*4) = val;
    }

    int ig = (wid & 3) * 16;
    int half = wid >> 2;
    int jh = half * 64;
    int arow = lane & 15, acol = (lane >> 4) << 3;
    int bm = lane >> 3;
    int brow = ((bm >> 1) << 3) + (lane & 7);
    int bcol = (bm & 1) << 3;
    int qgrp = lane & 3;
    int lr = ig + (lane >> 2);

    CP_WAIT1();
    __syncthreads();
    uint32_t qf[8][4];
    #pragma unroll
    for (int k = 0; k < 8; k++) {
        uint32_t ad = sb + (ig + arow)*FC_STR + (k*16 + acol)*2;
        LDMX4(qf[k][0], qf[k][1], qf[k][2], qf[k][3], ad);
    }

    float acc[17][4];
    #pragma unroll
    for (int nt = 0; nt < 17; nt++)
        #pragma unroll
        for (int e = 0; e < 4; e++) acc[nt][e] = 0.f;
    float m0 = -1e30f, m1 = -1e30f;

    #pragma unroll 1
    for (int t = 0; t < 32; t++) {
        uint32_t base = sb + FC_Q + (uint32_t)(t & 1)*FC_BUFSZ;
        CP_WAIT0();
        __syncthreads();
        if (t + 1 < 32) {
            uint32_t nb = sb + FC_Q + (uint32_t)((t + 1) & 1)*FC_BUFSZ;
            int j0 = (t + 1) * 128;
            for (int idx = tid; idx < 2048; idx += 256) {
                int row = idx >> 4, c = idx & 15;
                CP_ASYNC16(nb + row*FC_STR + c*16,
                           Kh + (size_t)(j0 + row)*CC + c*8);
            }
            for (int idx = tid; idx < 2048; idx += 256) {
                int row = idx >> 4, c = idx & 15;
                CP_ASYNC16(nb + FC_VOFF + row*FC_STR + c*16,
                           Vh + (size_t)row*NV + j0 + c*8);
            }
            CP_COMMIT();
        }

        // ---- QK: S (16 x 64) per warp, single fp16 pass
        float s[8][4];
        #pragma unroll
        for (int nt = 0; nt < 8; nt++)
            #pragma unroll
            for (int e = 0; e < 4; e++) s[nt][e] = 0.f;
        #pragma unroll
        for (int k = 0; k < 8; k++) {
            uint32_t bh[8][2];
            #pragma unroll
            for (int ntp = 0; ntp < 4; ntp++) {
                uint32_t q0, q1, q2, q3;
                LDMX4(q0, q1, q2, q3,
                      base + (jh + ntp*16 + brow)*FC_STR + (k*16 + bcol)*2);
                bh[2*ntp][0] = q0;   bh[2*ntp][1] = q1;
                bh[2*ntp+1][0] = q2; bh[2*ntp+1][1] = q3;
            }
            #pragma unroll
            for (int nt = 0; nt < 8; nt++)
                MMA_F16(s[nt], qf[k], bh[nt]);
        }

        // ---- warp-local online softmax
        float mx0 = -1e30f, mx1 = -1e30f;
        #pragma unroll
        for (int nt = 0; nt < 8; nt++) {
            mx0 = fmaxf(mx0, fmaxf(s[nt][0], s[nt][1]));
            mx1 = fmaxf(mx1, fmaxf(s[nt][2], s[nt][3]));
        }
        mx0 = fmaxf(mx0, __shfl_xor_sync(0xffffffffu, mx0, 1));
        mx0 = fmaxf(mx0, __shfl_xor_sync(0xffffffffu, mx0, 2));
        mx1 = fmaxf(mx1, __shfl_xor_sync(0xffffffffu, mx1, 1));
        mx1 = fmaxf(mx1, __shfl_xor_sync(0xffffffffu, mx1, 2));
        bool upd = (mx0 > m0) || (mx1 > m1);
        if (__any_sync(0xffffffffu, upd)) {
            float mn0 = fmaxf(m0, mx0), mn1 = fmaxf(m1, mx1);
            float al0 = exp2f(m0 - mn0), al1 = exp2f(m1 - mn1);
            m0 = mn0; m1 = mn1;
            #pragma unroll
            for (int nt = 0; nt < 17; nt++) {
                acc[nt][0] *= al0; acc[nt][1] *= al0;
                acc[nt][2] *= al1; acc[nt][3] *= al1;
            }
        }
        #pragma unroll
        for (int nt = 0; nt < 8; nt++) {
            s[nt][0] = exp2f(s[nt][0] - m0);
            s[nt][1] = exp2f(s[nt][1] - m0);
            s[nt][2] = exp2f(s[nt][2] - m1);
            s[nt][3] = exp2f(s[nt][3] - m1);
        }

        // ---- P -> fp16 A-fragments (4 k-blocks of 16 j)
        uint32_t ah[4][4];
        #pragma unroll
        for (int kb = 0; kb < 4; kb++) {
            int tA = 2*kb, tB = 2*kb + 1;
            ah[kb][0] = pack_h2(s[tA][0], s[tA][1]);
            ah[kb][1] = pack_h2(s[tA][2], s[tA][3]);
            ah[kb][2] = pack_h2(s[tB][0], s[tB][1]);
            ah[kb][3] = pack_h2(s[tB][2], s[tB][3]);
        }

        // ---- PV: acc += P @ V^T incl. ones-channel (nt 16 = l)
        #pragma unroll
        for (int kb = 0; kb < 4; kb++) {
            int kc = jh + kb*16;
            uint32_t bf2[18][2];
            #pragma unroll
            for (int ntp = 0; ntp < 9; ntp++) {
                uint32_t q0, q1, q2, q3;
                LDMX4(q0, q1, q2, q3,
                      base + FC_VOFF + (ntp*16 + brow)*FC_STR + (kc + bcol)*2);
                bf2[2*ntp][0] = q0;   bf2[2*ntp][1] = q1;
                bf2[2*ntp+1][0] = q2; bf2[2*ntp+1][1] = q3;
            }
            #pragma unroll
            for (int nt = 0; nt < 17; nt++)
                MMA_F16(acc[nt], ah[kb], bf2[nt]);
        }
    }

    int lsrc = lane & ~3;
    float l0 = __shfl_sync(0xffffffffu, acc[16][0], lsrc);
    float l1 = __shfl_sync(0xffffffffu, acc[16][2], lsrc);

    __syncthreads();
    float* ms   = (float*)(smem);
    float* ls   = (float*)(smem + 256);
    float* Hred = (float*)(smem + 512);
    if (half) {
        if (qgrp == 0) {
            ms[lr] = m0;   ls[lr] = l0;
            ms[lr+8] = m1; ls[lr+8] = l1;
        }
        #pragma unroll
        for (int nt = 0; nt < 16; nt++) {
            Hred[lr*128 + nt*8 + qgrp*2]         = acc[nt][0];
            Hred[lr*128 + nt*8 + qgrp*2 + 1]     = acc[nt][1];
            Hred[(lr+8)*128 + nt*8 + qgrp*2]     = acc[nt][2];
            Hred[(lr+8)*128 + nt*8 + qgrp*2 + 1] = acc[nt][3];
        }
    }
    __syncthreads();
    if (!half) {
        float mo0 = ms[lr],   lo0 = ls[lr];
        float mo1 = ms[lr+8], lo1 = ls[lr+8];
        float mt0 = fmaxf(m0, mo0), mt1 = fmaxf(m1, mo1);
        float sA0 = exp2f(m0 - mt0), sB0 = exp2f(mo0 - mt0);
        float sA1 = exp2f(m1 - mt1), sB1 = exp2f(mo1 - mt1);
        float inv0 = 1.f / (l0*sA0 + lo0*sB0);
        float inv1 = 1.f / (l1*sA1 + lo1*sB1);
        __half* Hh = g_hTh + (size_t)b*NV*CC;
        __half* Hl = g_hTl + (size_t)b*NV*CC;
        #pragma unroll
        for (int nt = 0; nt < 16; nt++) {
            float h0 = (acc[nt][0]*sA0 + Hred[lr*128 + nt*8 + qgrp*2]*sB0)         * inv0;
            float h1 = (acc[nt][1]*sA0 + Hred[lr*128 + nt*8 + qgrp*2 + 1]*sB0)     * inv0;
            float h2 = (acc[nt][2]*sA1 + Hred[(lr+8)*128 + nt*8 + qgrp*2]*sB1)     * inv1;
            float h3 = (acc[nt][3]*sA1 + Hred[(lr+8)*128 + nt*8 + qgrp*2 + 1]*sB1) * inv1;
            uint32_t hh, hl;
            split_pack_h(h0, h1, hh, hl);
            *(uint32_t*)(Hh + (size_t)(i0 + lr)*CC + nt*8 + qgrp*2) = hh;
            *(uint32_t*)(Hl + (size_t)(i0 + lr)*CC + nt*8 + qgrp*2) = hl;
            split_pack_h(h2, h3, hh, hl);
            *(uint32_t*)(Hh + (size_t)(i0 + lr + 8)*CC + nt*8 + qgrp*2) = hh;
            *(uint32_t*)(Hl + (size_t)(i0 + lr + 8)*CC + nt*8 + qgrp*2) = hl;
        }
    }
}

// ---------------- 5) output projection via HMMA + residual ------
#define PJ_HH   0
#define PJ_HL   17408
#define PJ_WH   34816
#define PJ_WL   69632
#define PJ_SMEM 104448
#define PJ_STR  272

__global__ void __launch_bounds__(256, 1) proj_kernel(const float* __restrict__ inp,
                                                      const float* __restrict__ bo,
                                                      float* __restrict__ outp)
{
    extern __shared__ char smem[];
    uint32_t sb = smem_u32(smem);
    int b = blockIdx.y;
    int n0g = blockIdx.x * 64;
    int tid = threadIdx.x, wid = tid >> 5, lane = tid & 31;
    const __half* Wh = g_W16h + (size_t)3*CC*CC;
    const __half* Wl = g_W16l + (size_t)3*CC*CC;
    const __half* Hh = g_hTh + (size_t)b*NV*CC;
    const __half* Hl = g_hTl + (size_t)b*NV*CC;

    for (int idx = tid; idx < 2048; idx += 256) {
        int r = idx >> 4, c16 = idx & 15;
        CP_ASYNC16(sb + PJ_WH + r*PJ_STR + c16*16, Wh + (size_t)r*CC + c16*8);
        CP_ASYNC16(sb + PJ_WL + r*PJ_STR + c16*16, Wl + (size_t)r*CC + c16*8);
    }
    for (int idx = tid; idx < 1024; idx += 256) {
        int r = idx >> 4, c16 = idx & 15;
        CP_ASYNC16(sb + PJ_HH + r*PJ_STR + c16*16, Hh + (size_t)(n0g + r)*CC + c16*8);
        CP_ASYNC16(sb + PJ_HL + r*PJ_STR + c16*16, Hl + (size_t)(n0g + r)*CC + c16*8);
    }
    CP_COMMIT();
    CP_WAIT0();
    __syncthreads();

    int og = wid >> 1, nh = wid & 1;
    int o0 = og * 32, n0 = nh * 32;
    int arow = lane & 15, acol = (lane >> 4) << 3;
    int bm = lane >> 3;
    int brow = ((bm >> 1) << 3) + (lane & 7);
    int bcol = (bm & 1) << 3;

    float acc[2][4][4];
    #pragma unroll
    for (int mt = 0; mt < 2; mt++)
        #pragma unroll
        for (int nt = 0; nt < 4; nt++)
            #pragma unroll
            for (int e = 0; e < 4; e++) acc[mt][nt][e] = 0.f;

    #pragma unroll
    for (int pass = 0; pass < 3; pass++) {
        uint32_t Ab = sb + (pass == 1 ? PJ_WL : PJ_WH);
        uint32_t Bb = sb + (pass == 2 ? PJ_HL : PJ_HH);
        #pragma unroll
        for (int k = 0; k < 8; k++) {
            int kc = k * 16;
            uint32_t a[2][4];
            #pragma unroll
            for (int mt = 0; mt < 2; mt++)
                LDMX4(a[mt][0], a[mt][1], a[mt][2], a[mt][3],
                      Ab + (o0 + mt*16 + arow)*PJ_STR + (kc + acol)*2);
            uint32_t bf[4][2];
            #pragma unroll
            for (int ntp = 0; ntp < 2; ntp++) {
                uint32_t q0, q1, q2, q3;
                LDMX4(q0, q1, q2, q3,
                      Bb + (n0 + ntp*16 + brow)*PJ_STR + (kc + bcol)*2);
                bf[2*ntp][0] = q0;   bf[2*ntp][1] = q1;
                bf[2*ntp+1][0] = q2; bf[2*ntp+1][1] = q3;
            }
            #pragma unroll
            for (int mt = 0; mt < 2; mt++)
                #pragma unroll
                for (int nt = 0; nt < 4; nt++)
                    MMA_F16(acc[mt][nt], a[mt], bf[nt]);
        }
    }

    #pragma unroll
    for (int mt = 0; mt < 2; mt++) {
        int ob = o0 + mt*16 + (lane >> 2);
        float b0 = bo[ob], b1 = bo[ob + 8];
        #pragma unroll
        for (int nt = 0; nt < 4; nt++) {
            int n = n0g + n0 + nt*8 + (lane & 3)*2;
            float2 r0 = *(const float2*)(inp + ((size_t)b*CC + ob)*NV + n);
            float2 r1 = *(const float2*)(inp + ((size_t)b*CC + ob + 8)*NV + n);
            *(float2*)(outp + ((size_t)b*CC + ob)*NV + n) =
                make_float2(acc[mt][nt][0] + b0 + r0.x, acc[mt][nt][1] + b0 + r0.y);
            *(float2*)(outp + ((size_t)b*CC + ob + 8)*NV + n) =
                make_float2(acc[mt][nt][2] + b1 + r1.x, acc[mt][nt][3] + b1 + r1.y);
        }
    }
}

// ---------------- launch ----------------------------------------
extern "C" void kernel_launch(void* const* d_in, const int* in_sizes, int n_in,
                              void* d_out, int out_size)
{
    const float* inp   = (const float*)d_in[0];
    const float* gamma = (const float*)d_in[1];
    const float* beta  = (const float*)d_in[2];
    const float* Wq    = (const float*)d_in[3];
    const float* bq    = (const float*)d_in[4];
    const float* Wk    = (const float*)d_in[5];
    const float* bk    = (const float*)d_in[6];
    const float* Wv    = (const float*)d_in[7];
    const float* bv    = (const float*)d_in[8];
    const float* Wo    = (const float*)d_in[9];
    const float* bo    = (const float*)d_in[10];
    float* outp = (float*)d_out;

    cudaFuncSetAttribute(qkv_kernel,   cudaFuncAttributeMaxDynamicSharedMemorySize, QG_SMEM);
    cudaFuncSetAttribute(proj_kernel,  cudaFuncAttributeMaxDynamicSharedMemorySize, PJ_SMEM);
    cudaFuncSetAttribute(fattn_kernel, cudaFuncAttributeMaxDynamicSharedMemorySize, FC_SMEM);

    stats_kernel<<<dim3(CC, NB), 256>>>(inp);
    fold_kernel<<<4*CC, CC>>>(gamma, beta, Wq, bq, Wk, bk, Wv, bv, Wo);
    qkv_kernel<<<dim3(NV/64, 3, NB), 256, QG_SMEM>>>(inp);
    fattn_kernel<<<dim3(NV/64, NB), 256, FC_SMEM>>>();
    proj_kernel<<<dim3(NV/64, NB), 256, PJ_SMEM>>>(inp, bo, outp);
}